// round 2
// baseline (speedup 1.0000x reference)
#include <cuda_runtime.h>
#include <math.h>

#define SEQ 2048
#define DIMD 2048
#define FDM 512

// ------------------------- scratch (device globals) -------------------------
__device__ float g_qkv [(size_t)4096 * 6144];
__device__ float g_lrpre[(size_t)4096 * 12];
__device__ float g_lr  [(size_t)4096 * 12];
__device__ float g_aq  [(size_t)4096 * 2048];
__device__ float g_ak  [(size_t)4096 * 2048];
__device__ float g_fq  [(size_t)8 * SEQ * FDM];
__device__ float g_fk  [(size_t)8 * SEQ * FDM];
__device__ float g_fv  [(size_t)8 * SEQ * FDM];
__device__ float g_w0  [(size_t)8 * FDM * FDM];
__device__ float g_w1  [(size_t)8 * FDM * FDM];
__device__ float g_w2  [(size_t)8 * FDM * FDM];
__device__ float g_gate[(size_t)8 * 1024 * FDM];
__device__ float g_hpre[(size_t)8 * 1024 * FDM];
__device__ float g_dh  [(size_t)8 * 1024 * FDM];
__device__ float g_hid [(size_t)8 * 1024 * FDM];
__device__ float g_ttt [(size_t)8 * SEQ * FDM];
__device__ float g_sum [(size_t)4096 * 2048];

// ---------------- generic batched SGEMM: C = op(A)*op(B) (+C) ---------------
// TA=0: Aop[m,k]=A[m*lda+k], TA=1: Aop[m,k]=A[k*lda+m]
// TB=0: Bop[k,n]=B[k*ldb+n], TB=1: Bop[k,n]=B[n*ldb+k]
template<int TA, int TB, bool ACC>
__global__ void gemm_k(const float* __restrict__ Ag, const float* __restrict__ Bg,
                       float* __restrict__ Cg, int M, int N, int K,
                       int lda, int ldb, int ldc, long sA, long sB, long sC)
{
    __shared__ float As[16][64];
    __shared__ float Bs[16][64];
    const float* A = Ag + (long)blockIdx.z * sA;
    const float* B = Bg + (long)blockIdx.z * sB;
    float*       C = Cg + (long)blockIdx.z * sC;
    int tid = threadIdx.x;
    int tx = tid & 15, ty = tid >> 4;
    int m0 = blockIdx.y * 64, n0 = blockIdx.x * 64;
    float acc[4][4] = {};
    for (int k0 = 0; k0 < K; k0 += 16) {
        if (TA == 0) {
            int m = tid >> 2, k = (tid & 3) * 4;
            float4 v = make_float4(0.f, 0.f, 0.f, 0.f);
            if (m0 + m < M) v = *(const float4*)&A[(long)(m0 + m) * lda + k0 + k];
            As[k][m] = v.x; As[k + 1][m] = v.y; As[k + 2][m] = v.z; As[k + 3][m] = v.w;
        } else {
            #pragma unroll
            for (int p = 0; p < 4; ++p) {
                int m = tid & 63, k = (tid >> 6) + p * 4;
                As[k][m] = (m0 + m < M) ? A[(long)(k0 + k) * lda + m0 + m] : 0.f;
            }
        }
        if (TB == 0) {
            #pragma unroll
            for (int p = 0; p < 4; ++p) {
                int n = tid & 63, k = (tid >> 6) + p * 4;
                Bs[k][n] = (n0 + n < N) ? B[(long)(k0 + k) * ldb + n0 + n] : 0.f;
            }
        } else {
            int n = tid >> 2, k = (tid & 3) * 4;
            float4 v = make_float4(0.f, 0.f, 0.f, 0.f);
            if (n0 + n < N) v = *(const float4*)&B[(long)(n0 + n) * ldb + k0 + k];
            Bs[k][n] = v.x; Bs[k + 1][n] = v.y; Bs[k + 2][n] = v.z; Bs[k + 3][n] = v.w;
        }
        __syncthreads();
        #pragma unroll
        for (int kk = 0; kk < 16; ++kk) {
            float4 av = *(const float4*)&As[kk][ty * 4];
            float4 bv = *(const float4*)&Bs[kk][tx * 4];
            float a0[4] = {av.x, av.y, av.z, av.w};
            float b0[4] = {bv.x, bv.y, bv.z, bv.w};
            #pragma unroll
            for (int i = 0; i < 4; ++i)
                #pragma unroll
                for (int j = 0; j < 4; ++j)
                    acc[i][j] = fmaf(a0[i], b0[j], acc[i][j]);
        }
        __syncthreads();
    }
    #pragma unroll
    for (int i = 0; i < 4; ++i) {
        int gm = m0 + ty * 4 + i;
        if (gm >= M) continue;
        #pragma unroll
        for (int j = 0; j < 4; ++j) {
            int gn = n0 + tx * 4 + j;
            if (gn >= N) continue;
            long off = (long)gm * ldc + gn;
            if (ACC) C[off] += acc[i][j]; else C[off] = acc[i][j];
        }
    }
}

// ------------------------- block reduce (256 thr) ---------------------------
__device__ __forceinline__ float blockReduceSum(float v, float* sred)
{
    int lane = threadIdx.x & 31;
    #pragma unroll
    for (int o = 16; o > 0; o >>= 1) v += __shfl_down_sync(0xffffffffu, v, o);
    if (lane == 0) sred[threadIdx.x >> 5] = v;
    __syncthreads();
    if (threadIdx.x < 8) {
        float r = sred[threadIdx.x];
        #pragma unroll
        for (int o = 4; o > 0; o >>= 1) r += __shfl_down_sync(0xffu, r, o);
        if (threadIdx.x == 0) sred[0] = r;
    }
    __syncthreads();
    float out = sred[0];
    __syncthreads();
    return out;
}

// --------- prep: rmsnorm+rope (attn path) + silu/L2 (fast path) + lr --------
__global__ void prep_kernel(const float* __restrict__ qkv, const float* __restrict__ lrpre,
                            const float* __restrict__ qnw, const float* __restrict__ knw,
                            const float* __restrict__ qksc, const float* __restrict__ qkof,
                            const float* __restrict__ lrb, float base_lr_inv,
                            float* __restrict__ aq, float* __restrict__ ak,
                            float* __restrict__ fq, float* __restrict__ fk,
                            float* __restrict__ fv, float* __restrict__ lrout)
{
    __shared__ float s_q[2048];
    __shared__ float s_k[2048];
    __shared__ float sred[8];
    int row = blockIdx.x;
    int b = row >> 11, t = row & 2047;
    int tid = threadIdx.x;
    const float* qr = qkv + (long)row * 6144;
    const float* kr = qr + 2048;
    const float* vr = qr + 4096;

    float qv[8], kv[8], fqv[8], fkv[8], fvv[8];
    float sq = 0.f, sk = 0.f;
    float p2q[4] = {0, 0, 0, 0}, p2k[4] = {0, 0, 0, 0};
    #pragma unroll
    for (int j = 0; j < 8; ++j) {
        int i = j * 256 + tid;
        float q = qr[i], k = kr[i], v = vr[i];
        qv[j] = q; kv[j] = k;
        sq += q * q; sk += k * k;
        float fqe = (q / (1.f + expf(-q))) * qksc[i * 2 + 0] + qkof[i * 2 + 0];
        float fke = (k / (1.f + expf(-k))) * qksc[i * 2 + 1] + qkof[i * 2 + 1];
        fqv[j] = fqe; fkv[j] = fke; fvv[j] = v / (1.f + expf(-v));
        p2q[j >> 1] += fqe * fqe;
        p2k[j >> 1] += fke * fke;
    }
    float SQ = blockReduceSum(sq, sred);
    float SK = blockReduceSum(sk, sred);
    float G2Q[4], G2K[4];
    #pragma unroll
    for (int g = 0; g < 4; ++g) G2Q[g] = blockReduceSum(p2q[g], sred);
    #pragma unroll
    for (int g = 0; g < 4; ++g) G2K[g] = blockReduceSum(p2k[g], sred);
    float rq = rsqrtf(SQ * (1.f / 2048.f) + 1e-6f);
    float rk = rsqrtf(SK * (1.f / 2048.f) + 1e-6f);
    #pragma unroll
    for (int j = 0; j < 8; ++j) {
        int i = j * 256 + tid;
        s_q[i] = qv[j] * rq * qnw[i];
        s_k[i] = kv[j] * rk * knw[i];
        int g = j >> 1;
        long fb = (((long)(b * 4 + g)) * SEQ + t) * FDM + (i & 511);
        fq[fb] = fqv[j] / (sqrtf(G2Q[g]) + 1e-12f);
        fk[fb] = fkv[j] / (sqrtf(G2K[g]) + 1e-12f);
        fv[fb] = fvv[j];
    }
    __syncthreads();
    #pragma unroll
    for (int j = 0; j < 8; ++j) {
        int i = j * 256 + tid;
        int pos = i & 127;
        int fi = pos & 63;
        float invf = expf(-(float)fi * (logf(500000.f) / 64.f));
        float sn, cs;
        sincosf((float)t * invf, &sn, &cs);
        float oq, ok_;
        if (pos < 64) {
            oq  = s_q[i] * cs - s_q[i + 64] * sn;
            ok_ = s_k[i] * cs - s_k[i + 64] * sn;
        } else {
            oq  = s_q[i] * cs + s_q[i - 64] * sn;
            ok_ = s_k[i] * cs + s_k[i - 64] * sn;
        }
        aq[(long)row * DIMD + i] = oq;
        ak[(long)row * DIMD + i] = ok_;
    }
    if (tid < 12) {
        float x = lrpre[(long)row * 12 + tid] + lrb[tid] + base_lr_inv;
        lrout[(long)row * 12 + tid] = (x > 20.f) ? x : log1pf(expf(x));
    }
}

// ------------------- windowed flash attention (64q x 64k) -------------------
__global__ void attn_kernel(const float* __restrict__ Q, const float* __restrict__ K,
                            const float* __restrict__ QKV, float* __restrict__ O)
{
    extern __shared__ float sm[];
    float* Qs  = sm;               // 64 x 132
    float* KVs = sm + 64 * 132;    // 64 x 132
    float* Ss  = sm + 2 * 64 * 132; // 64 x 66
    int q0 = blockIdx.x << 6;
    int h = blockIdx.y, b = blockIdx.z;
    int tid = threadIdx.x;              // 256
    int tq = tid >> 2, td = tid & 3;
    const float qscale = 0.088388347648318447f * 1.4426950408889634f;

    for (int e = tid; e < 8192; e += 256) {
        int r = e >> 7, c = e & 127;
        Qs[r * 132 + c] = Q[((long)(b * SEQ + q0 + r)) * DIMD + h * 128 + c] * qscale;
    }
    float acc[32];
    #pragma unroll
    for (int d = 0; d < 32; ++d) acc[d] = 0.f;
    float m = -INFINITY, l = 0.f;

    int kt_hi = q0 >> 6;
    int kt_lo = (q0 >= 1024) ? ((q0 - 1023) >> 6) : 0;
    for (int kt = kt_lo; kt <= kt_hi; ++kt) {
        int j0 = kt << 6;
        __syncthreads();
        for (int e = tid; e < 8192; e += 256) {
            int r = e >> 7, c = e & 127;
            KVs[r * 132 + c] = K[((long)(b * SEQ + j0 + r)) * DIMD + h * 128 + c];
        }
        __syncthreads();

        float sacc[16];
        #pragma unroll
        for (int jj = 0; jj < 16; ++jj) sacc[jj] = 0.f;
        #pragma unroll 4
        for (int k4 = 0; k4 < 32; ++k4) {
            float4 qv = *(const float4*)&Qs[tq * 132 + k4 * 4];
            #pragma unroll
            for (int jj = 0; jj < 16; ++jj) {
                float4 kv = *(const float4*)&KVs[(td * 16 + jj) * 132 + k4 * 4];
                sacc[jj] += qv.x * kv.x + qv.y * kv.y + qv.z * kv.z + qv.w * kv.w;
            }
        }
        int ig = q0 + tq;
        float tmax = -INFINITY;
        #pragma unroll
        for (int jj = 0; jj < 16; ++jj) {
            int jg = j0 + td * 16 + jj;
            bool ok = (jg <= ig) && (ig - jg < 1024);
            float sv = ok ? sacc[jj] : -INFINITY;
            Ss[tq * 66 + td * 16 + jj] = sv;
            tmax = fmaxf(tmax, sv);
        }
        tmax = fmaxf(tmax, __shfl_xor_sync(0xffffffffu, tmax, 1));
        tmax = fmaxf(tmax, __shfl_xor_sync(0xffffffffu, tmax, 2));

        __syncthreads();  // everyone done with K in KVs
        for (int e = tid; e < 8192; e += 256) {
            int r = e >> 7, c = e & 127;
            KVs[r * 132 + c] = QKV[((long)(b * SEQ + j0 + r)) * 6144 + 4096 + h * 128 + c];
        }
        __syncthreads();

        float mt  = fmaxf(m, tmax);
        float mte = (mt > -INFINITY) ? mt : 0.f;
        float corr = exp2f(m - mte);
        l *= corr;
        #pragma unroll
        for (int d = 0; d < 32; ++d) acc[d] *= corr;
        float lpart = 0.f;
        #pragma unroll
        for (int jj = 0; jj < 16; ++jj) {
            float p = exp2f(Ss[tq * 66 + td * 16 + jj] - mte);
            Ss[tq * 66 + td * 16 + jj] = p;
            lpart += p;
        }
        lpart += __shfl_xor_sync(0xffffffffu, lpart, 1);
        lpart += __shfl_xor_sync(0xffffffffu, lpart, 2);
        l += lpart;
        __syncwarp();
        #pragma unroll 2
        for (int jj = 0; jj < 64; ++jj) {
            float pj = Ss[tq * 66 + jj];
            const float* vr = &KVs[jj * 132 + td * 32];
            #pragma unroll
            for (int d4 = 0; d4 < 8; ++d4) {
                float4 vv = *(const float4*)&vr[d4 * 4];
                acc[d4 * 4 + 0] = fmaf(pj, vv.x, acc[d4 * 4 + 0]);
                acc[d4 * 4 + 1] = fmaf(pj, vv.y, acc[d4 * 4 + 1]);
                acc[d4 * 4 + 2] = fmaf(pj, vv.z, acc[d4 * 4 + 2]);
                acc[d4 * 4 + 3] = fmaf(pj, vv.w, acc[d4 * 4 + 3]);
            }
        }
        m = mt;
        __syncwarp();
    }
    float rl = 1.f / l;
    float* orow = &O[((long)(b * SEQ + q0 + tq)) * DIMD + h * 128 + td * 32];
    #pragma unroll
    for (int d4 = 0; d4 < 8; ++d4) {
        float4 o;
        o.x = acc[d4 * 4 + 0] * rl; o.y = acc[d4 * 4 + 1] * rl;
        o.z = acc[d4 * 4 + 2] * rl; o.w = acc[d4 * 4 + 3] * rl;
        *(float4*)&orow[d4 * 4] = o;
    }
}

// --------------------------- TTT helper kernels -----------------------------
__global__ void copyw(const float* __restrict__ w0, const float* __restrict__ w1,
                      const float* __restrict__ w2, float* __restrict__ o0,
                      float* __restrict__ o1, float* __restrict__ o2)
{
    long idx = (long)blockIdx.x * 256 + threadIdx.x;   // total 8*512*512
    long src = idx & ((long)4 * 512 * 512 - 1);
    o0[idx] = w0[src]; o1[idx] = w1[src]; o2[idx] = w2[src];
}

__global__ void elem2(const float* __restrict__ fv, const float* __restrict__ lr,
                      float* __restrict__ gate, float* __restrict__ hpre,
                      float* __restrict__ dh, float* __restrict__ hid, int ck0)
{
    long idx = (long)blockIdx.x * 256 + threadIdx.x;   // 8*1024*512
    int col = idx & 511;
    long tt = idx >> 9;
    int c = tt & 1023, bh = tt >> 10;
    int b = bh >> 2, h = bh & 3;
    long row = (long)b * SEQ + ck0 + c;
    float l0 = lr[row * 12 + h], l1 = lr[row * 12 + 4 + h], l2 = lr[row * 12 + 8 + h];
    float g = gate[idx], hp = hpre[idx], d = dh[idx];
    float sig = 1.f / (1.f + expf(-g));
    float sg = g * sig;
    hid[idx] = sg * hp;
    float v = fv[((long)bh * SEQ + ck0 + c) * FDM + col];
    gate[idx] = d * hp * (sig * (1.f + g * (1.f - sig))) * l0;
    hpre[idx] = d * sg * l2;
    dh[idx]   = v * l1;
}

__global__ void elem3(const float* __restrict__ gate, const float* __restrict__ hpre,
                      float* __restrict__ hid)
{
    long idx = (long)blockIdx.x * 256 + threadIdx.x;
    float g = gate[idx];
    hid[idx] = (g / (1.f + expf(-g))) * hpre[idx];
}

// -------------------- ttt rmsnorm + add attention result --------------------
__global__ void post_kernel(const float* __restrict__ ttt, const float* __restrict__ tw,
                            float* __restrict__ sum)
{
    __shared__ float sr[4];
    int fh = blockIdx.x, row = blockIdx.y;
    int b = row >> 11, t = row & 2047;
    int bh = b * 4 + fh;
    const float* src = ttt + ((long)bh * SEQ + t) * FDM;
    int tid = threadIdx.x;   // 128
    float v[4], ss = 0.f;
    #pragma unroll
    for (int j = 0; j < 4; ++j) { v[j] = src[tid + 128 * j]; ss += v[j] * v[j]; }
    #pragma unroll
    for (int o = 16; o > 0; o >>= 1) ss += __shfl_down_sync(0xffffffffu, ss, o);
    if ((tid & 31) == 0) sr[tid >> 5] = ss;
    __syncthreads();
    float tot = sr[0] + sr[1] + sr[2] + sr[3];
    float r = rsqrtf(tot * (1.f / 512.f) + 1e-6f);
    #pragma unroll
    for (int j = 0; j < 4; ++j) {
        int i = tid + 128 * j;
        sum[(long)row * 2048 + fh * 512 + i] += v[j] * r * tw[i];
    }
}

// --------------------------------- launch -----------------------------------
extern "C" void kernel_launch(void* const* d_in, const int* in_sizes, int n_in,
                              void* d_out, int out_size)
{
    const float* hidden = (const float*)d_in[0];
    const float* Wqkv   = (const float*)d_in[1];
    const float* Wo     = (const float*)d_in[2];
    const float* qnw    = (const float*)d_in[3];
    const float* knw    = (const float*)d_in[4];
    const float* w0     = (const float*)d_in[5];
    const float* w1     = (const float*)d_in[6];
    const float* w2     = (const float*)d_in[7];
    const float* lrw    = (const float*)d_in[8];
    const float* lrb    = (const float*)d_in[9];
    const float* qksc   = (const float*)d_in[10];
    const float* qkof   = (const float*)d_in[11];
    const float* tttw   = (const float*)d_in[12];
    float* out = (float*)d_out;

    float *qkv, *lrpre, *lr, *aq, *ak, *fq, *fk, *fv, *pw0, *pw1, *pw2;
    float *gate, *hpre, *dh, *hid, *ttt, *sum;
    cudaGetSymbolAddress((void**)&qkv,   g_qkv);
    cudaGetSymbolAddress((void**)&lrpre, g_lrpre);
    cudaGetSymbolAddress((void**)&lr,    g_lr);
    cudaGetSymbolAddress((void**)&aq,    g_aq);
    cudaGetSymbolAddress((void**)&ak,    g_ak);
    cudaGetSymbolAddress((void**)&fq,    g_fq);
    cudaGetSymbolAddress((void**)&fk,    g_fk);
    cudaGetSymbolAddress((void**)&fv,    g_fv);
    cudaGetSymbolAddress((void**)&pw0,   g_w0);
    cudaGetSymbolAddress((void**)&pw1,   g_w1);
    cudaGetSymbolAddress((void**)&pw2,   g_w2);
    cudaGetSymbolAddress((void**)&gate,  g_gate);
    cudaGetSymbolAddress((void**)&hpre,  g_hpre);
    cudaGetSymbolAddress((void**)&dh,    g_dh);
    cudaGetSymbolAddress((void**)&hid,   g_hid);
    cudaGetSymbolAddress((void**)&ttt,   g_ttt);
    cudaGetSymbolAddress((void**)&sum,   g_sum);

    dim3 blk(256);
    // qkv = hidden @ Wqkv^T ; lrpre = hidden @ lr_w^T
    gemm_k<0,1,false><<<dim3(96,64,1), blk>>>(hidden, Wqkv, qkv, 4096, 6144, 2048,
                                              2048, 2048, 6144, 0, 0, 0);
    gemm_k<0,1,false><<<dim3(1,64,1), blk>>>(hidden, lrw, lrpre, 4096, 12, 2048,
                                             2048, 2048, 12, 0, 0, 0);
    float base = (float)(0.001 + log(-expm1(-0.001)));
    prep_kernel<<<4096, 256>>>(qkv, lrpre, qnw, knw, qksc, qkof, lrb, base,
                               aq, ak, fq, fk, fv, lr);

    cudaFuncSetAttribute(attn_kernel, cudaFuncAttributeMaxDynamicSharedMemorySize, 84480);
    attn_kernel<<<dim3(32,16,2), 256, 84480>>>(aq, ak, qkv, sum);

    copyw<<<8192, 256>>>(w0, w1, w2, pw0, pw1, pw2);

    long sSeq = (long)SEQ * FDM;
    long sChk = (long)1024 * FDM;
    long sW   = (long)FDM * FDM;
    for (int ck = 0; ck < 2; ++ck) {
        int ck0 = ck * 1024;
        const float* Kc = fk + (long)ck0 * FDM;
        const float* Qc = fq + (long)ck0 * FDM;
        const float* Vc = fv + (long)ck0 * FDM;
        // gate = K@W0^T, hpre = K@W2^T, dh = V@W1
        gemm_k<0,1,false><<<dim3(8,16,8), blk>>>(Kc, pw0, gate, 1024, 512, 512,
                                                 512, 512, 512, sSeq, sW, sChk);
        gemm_k<0,1,false><<<dim3(8,16,8), blk>>>(Kc, pw2, hpre, 1024, 512, 512,
                                                 512, 512, 512, sSeq, sW, sChk);
        gemm_k<0,0,false><<<dim3(8,16,8), blk>>>(Vc, pw1, dh, 1024, 512, 512,
                                                 512, 512, 512, sSeq, sW, sChk);
        elem2<<<16384, 256>>>(fv, lr, gate, hpre, dh, hid, ck0);
        // W0 += (dgate*l0)^T @ K ; W2 += (dhpre*l2)^T @ K ; W1 += (v*l1)^T @ hid
        gemm_k<1,0,true><<<dim3(8,8,8), blk>>>(gate, Kc, pw0, 512, 512, 1024,
                                               512, 512, 512, sChk, sSeq, sW);
        gemm_k<1,0,true><<<dim3(8,8,8), blk>>>(hpre, Kc, pw2, 512, 512, 1024,
                                               512, 512, 512, sChk, sSeq, sW);
        gemm_k<1,0,true><<<dim3(8,8,8), blk>>>(dh, hid, pw1, 512, 512, 1024,
                                               512, 512, 512, sChk, sChk, sW);
        // query pass with updated weights
        gemm_k<0,1,false><<<dim3(8,16,8), blk>>>(Qc, pw0, gate, 1024, 512, 512,
                                                 512, 512, 512, sSeq, sW, sChk);
        gemm_k<0,1,false><<<dim3(8,16,8), blk>>>(Qc, pw2, hpre, 1024, 512, 512,
                                                 512, 512, 512, sSeq, sW, sChk);
        elem3<<<16384, 256>>>(gate, hpre, hid);
        gemm_k<0,1,false><<<dim3(8,16,8), blk>>>(hid, pw1, ttt + (long)ck0 * FDM,
                                                 1024, 512, 512,
                                                 512, 512, 512, sChk, sW, sSeq);
    }

    post_kernel<<<dim3(4,4096), 128>>>(ttt, tttw, sum);
    // out = (attn + ttt_norm) @ Wo^T
    gemm_k<0,1,false><<<dim3(32,64,1), blk>>>(sum, Wo, out, 4096, 2048, 2048,
                                              2048, 2048, 2048, 0, 0, 0);
}

// round 3
// speedup vs baseline: 1.0993x; 1.0993x over previous
#include <cuda_runtime.h>
#include <math.h>

#define SEQ 2048
#define DIMD 2048
#define FDM 512

// ------------------------- scratch (device globals) -------------------------
__device__ float g_qkv [(size_t)4096 * 6144];
__device__ float g_lrpre[(size_t)4096 * 12];
__device__ float g_lr  [(size_t)4096 * 12];
__device__ float g_aq  [(size_t)4096 * 2048];
__device__ float g_ak  [(size_t)4096 * 2048];
__device__ float g_fq  [(size_t)8 * SEQ * FDM];
__device__ float g_fk  [(size_t)8 * SEQ * FDM];
__device__ float g_fv  [(size_t)8 * SEQ * FDM];
__device__ float g_w0  [(size_t)8 * FDM * FDM];
__device__ float g_w1  [(size_t)8 * FDM * FDM];
__device__ float g_w2  [(size_t)8 * FDM * FDM];
__device__ float g_gate[(size_t)8 * 1024 * FDM];
__device__ float g_hpre[(size_t)8 * 1024 * FDM];
__device__ float g_dh  [(size_t)8 * 1024 * FDM];
__device__ float g_hid [(size_t)8 * 1024 * FDM];
__device__ float g_ttt [(size_t)8 * SEQ * FDM];
__device__ float g_sum [(size_t)4096 * 2048];

// ------------- fast batched SGEMM 128x128x8, double buffered -----------------
// C = op(A)*op(B) (+C).  Requires M,N multiples of 128, K multiple of 8,
// all leading dims multiples of 4 (float4 aligned).
// TA=0: Aop[m,k]=A[m*lda+k], TA=1: Aop[m,k]=A[k*lda+m]
// TB=0: Bop[k,n]=B[k*ldb+n], TB=1: Bop[k,n]=B[n*ldb+k]
template<int TA, int TB, bool ACC>
__global__ void __launch_bounds__(256, 2)
gemm128(const float* __restrict__ Ag, const float* __restrict__ Bg,
        float* __restrict__ Cg, int M, int N, int K,
        int lda, int ldb, int ldc, long sA, long sB, long sC)
{
    __shared__ float As[2][8][128];
    __shared__ float Bs[2][8][128];
    const float* A = Ag + (long)blockIdx.z * sA;
    const float* B = Bg + (long)blockIdx.z * sB;
    float*       C = Cg + (long)blockIdx.z * sC;
    int tid = threadIdx.x;
    int tx = tid & 15, ty = tid >> 4;
    int m0 = blockIdx.y * 128, n0 = blockIdx.x * 128;

    float acc[8][8] = {};
    float4 ra, rb;

    // ---- prologue: load first tile ----
    if (TA == 0) ra = *(const float4*)&A[(long)(m0 + (tid >> 1)) * lda + (tid & 1) * 4];
    else         ra = *(const float4*)&A[(long)(tid >> 5) * lda + m0 + (tid & 31) * 4];
    if (TB == 0) rb = *(const float4*)&B[(long)(tid >> 5) * ldb + n0 + (tid & 31) * 4];
    else         rb = *(const float4*)&B[(long)(n0 + (tid >> 1)) * ldb + (tid & 1) * 4];

    if (TA == 0) {
        int m = tid >> 1, kq = (tid & 1) * 4;
        As[0][kq][m] = ra.x; As[0][kq + 1][m] = ra.y;
        As[0][kq + 2][m] = ra.z; As[0][kq + 3][m] = ra.w;
    } else {
        *(float4*)&As[0][tid >> 5][(tid & 31) * 4] = ra;
    }
    if (TB == 0) {
        *(float4*)&Bs[0][tid >> 5][(tid & 31) * 4] = rb;
    } else {
        int n = tid >> 1, kq = (tid & 1) * 4;
        Bs[0][kq][n] = rb.x; Bs[0][kq + 1][n] = rb.y;
        Bs[0][kq + 2][n] = rb.z; Bs[0][kq + 3][n] = rb.w;
    }
    __syncthreads();

    int buf = 0;
    for (int k0 = 0; k0 < K; k0 += 8) {
        bool more = (k0 + 8 < K);
        if (more) {
            int kn = k0 + 8;
            if (TA == 0) ra = *(const float4*)&A[(long)(m0 + (tid >> 1)) * lda + kn + (tid & 1) * 4];
            else         ra = *(const float4*)&A[(long)(kn + (tid >> 5)) * lda + m0 + (tid & 31) * 4];
            if (TB == 0) rb = *(const float4*)&B[(long)(kn + (tid >> 5)) * ldb + n0 + (tid & 31) * 4];
            else         rb = *(const float4*)&B[(long)(n0 + (tid >> 1)) * ldb + kn + (tid & 1) * 4];
        }
        #pragma unroll
        for (int kk = 0; kk < 8; ++kk) {
            float4 a0 = *(const float4*)&As[buf][kk][ty * 8];
            float4 a1 = *(const float4*)&As[buf][kk][ty * 8 + 4];
            float4 b0 = *(const float4*)&Bs[buf][kk][tx * 8];
            float4 b1 = *(const float4*)&Bs[buf][kk][tx * 8 + 4];
            float av[8] = {a0.x, a0.y, a0.z, a0.w, a1.x, a1.y, a1.z, a1.w};
            float bv[8] = {b0.x, b0.y, b0.z, b0.w, b1.x, b1.y, b1.z, b1.w};
            #pragma unroll
            for (int i = 0; i < 8; ++i)
                #pragma unroll
                for (int j = 0; j < 8; ++j)
                    acc[i][j] = fmaf(av[i], bv[j], acc[i][j]);
        }
        if (more) {
            int nb = buf ^ 1;
            if (TA == 0) {
                int m = tid >> 1, kq = (tid & 1) * 4;
                As[nb][kq][m] = ra.x; As[nb][kq + 1][m] = ra.y;
                As[nb][kq + 2][m] = ra.z; As[nb][kq + 3][m] = ra.w;
            } else {
                *(float4*)&As[nb][tid >> 5][(tid & 31) * 4] = ra;
            }
            if (TB == 0) {
                *(float4*)&Bs[nb][tid >> 5][(tid & 31) * 4] = rb;
            } else {
                int n = tid >> 1, kq = (tid & 1) * 4;
                Bs[nb][kq][n] = rb.x; Bs[nb][kq + 1][n] = rb.y;
                Bs[nb][kq + 2][n] = rb.z; Bs[nb][kq + 3][n] = rb.w;
            }
            __syncthreads();
            buf = nb;
        }
    }
    // ---- epilogue ----
    #pragma unroll
    for (int i = 0; i < 8; ++i) {
        long gm = m0 + ty * 8 + i;
        #pragma unroll
        for (int j4 = 0; j4 < 2; ++j4) {
            long off = gm * ldc + n0 + tx * 8 + j4 * 4;
            if (ACC) {
                float4 c = *(float4*)&C[off];
                c.x += acc[i][j4 * 4 + 0]; c.y += acc[i][j4 * 4 + 1];
                c.z += acc[i][j4 * 4 + 2]; c.w += acc[i][j4 * 4 + 3];
                *(float4*)&C[off] = c;
            } else {
                float4 c = make_float4(acc[i][j4 * 4 + 0], acc[i][j4 * 4 + 1],
                                       acc[i][j4 * 4 + 2], acc[i][j4 * 4 + 3]);
                *(float4*)&C[off] = c;
            }
        }
    }
}

// ---------------- small SGEMM (kept only for the N=12 lr GEMM) ---------------
template<int TA, int TB, bool ACC>
__global__ void gemm_k(const float* __restrict__ Ag, const float* __restrict__ Bg,
                       float* __restrict__ Cg, int M, int N, int K,
                       int lda, int ldb, int ldc, long sA, long sB, long sC)
{
    __shared__ float As[16][64];
    __shared__ float Bs[16][64];
    const float* A = Ag + (long)blockIdx.z * sA;
    const float* B = Bg + (long)blockIdx.z * sB;
    float*       C = Cg + (long)blockIdx.z * sC;
    int tid = threadIdx.x;
    int tx = tid & 15, ty = tid >> 4;
    int m0 = blockIdx.y * 64, n0 = blockIdx.x * 64;
    float acc[4][4] = {};
    for (int k0 = 0; k0 < K; k0 += 16) {
        if (TA == 0) {
            int m = tid >> 2, k = (tid & 3) * 4;
            float4 v = make_float4(0.f, 0.f, 0.f, 0.f);
            if (m0 + m < M) v = *(const float4*)&A[(long)(m0 + m) * lda + k0 + k];
            As[k][m] = v.x; As[k + 1][m] = v.y; As[k + 2][m] = v.z; As[k + 3][m] = v.w;
        } else {
            #pragma unroll
            for (int p = 0; p < 4; ++p) {
                int m = tid & 63, k = (tid >> 6) + p * 4;
                As[k][m] = (m0 + m < M) ? A[(long)(k0 + k) * lda + m0 + m] : 0.f;
            }
        }
        if (TB == 0) {
            #pragma unroll
            for (int p = 0; p < 4; ++p) {
                int n = tid & 63, k = (tid >> 6) + p * 4;
                Bs[k][n] = (n0 + n < N) ? B[(long)(k0 + k) * ldb + n0 + n] : 0.f;
            }
        } else {
            int n = tid >> 2, k = (tid & 3) * 4;
            float4 v = make_float4(0.f, 0.f, 0.f, 0.f);
            if (n0 + n < N) v = *(const float4*)&B[(long)(n0 + n) * ldb + k0 + k];
            Bs[k][n] = v.x; Bs[k + 1][n] = v.y; Bs[k + 2][n] = v.z; Bs[k + 3][n] = v.w;
        }
        __syncthreads();
        #pragma unroll
        for (int kk = 0; kk < 16; ++kk) {
            float4 av = *(const float4*)&As[kk][ty * 4];
            float4 bv = *(const float4*)&Bs[kk][tx * 4];
            float a0[4] = {av.x, av.y, av.z, av.w};
            float b0[4] = {bv.x, bv.y, bv.z, bv.w};
            #pragma unroll
            for (int i = 0; i < 4; ++i)
                #pragma unroll
                for (int j = 0; j < 4; ++j)
                    acc[i][j] = fmaf(a0[i], b0[j], acc[i][j]);
        }
        __syncthreads();
    }
    #pragma unroll
    for (int i = 0; i < 4; ++i) {
        int gm = m0 + ty * 4 + i;
        if (gm >= M) continue;
        #pragma unroll
        for (int j = 0; j < 4; ++j) {
            int gn = n0 + tx * 4 + j;
            if (gn >= N) continue;
            long off = (long)gm * ldc + gn;
            if (ACC) C[off] += acc[i][j]; else C[off] = acc[i][j];
        }
    }
}

// ------------------------- block reduce (256 thr) ---------------------------
__device__ __forceinline__ float blockReduceSum(float v, float* sred)
{
    int lane = threadIdx.x & 31;
    #pragma unroll
    for (int o = 16; o > 0; o >>= 1) v += __shfl_down_sync(0xffffffffu, v, o);
    if (lane == 0) sred[threadIdx.x >> 5] = v;
    __syncthreads();
    if (threadIdx.x < 8) {
        float r = sred[threadIdx.x];
        #pragma unroll
        for (int o = 4; o > 0; o >>= 1) r += __shfl_down_sync(0xffu, r, o);
        if (threadIdx.x == 0) sred[0] = r;
    }
    __syncthreads();
    float out = sred[0];
    __syncthreads();
    return out;
}

// --------- prep: rmsnorm+rope (attn path) + silu/L2 (fast path) + lr --------
__global__ void prep_kernel(const float* __restrict__ qkv, const float* __restrict__ lrpre,
                            const float* __restrict__ qnw, const float* __restrict__ knw,
                            const float* __restrict__ qksc, const float* __restrict__ qkof,
                            const float* __restrict__ lrb, float base_lr_inv,
                            float* __restrict__ aq, float* __restrict__ ak,
                            float* __restrict__ fq, float* __restrict__ fk,
                            float* __restrict__ fv, float* __restrict__ lrout)
{
    __shared__ float s_q[2048];
    __shared__ float s_k[2048];
    __shared__ float sred[8];
    int row = blockIdx.x;
    int b = row >> 11, t = row & 2047;
    int tid = threadIdx.x;
    const float* qr = qkv + (long)row * 6144;
    const float* kr = qr + 2048;
    const float* vr = qr + 4096;

    float qv[8], kv[8], fqv[8], fkv[8], fvv[8];
    float sq = 0.f, sk = 0.f;
    float p2q[4] = {0, 0, 0, 0}, p2k[4] = {0, 0, 0, 0};
    #pragma unroll
    for (int j = 0; j < 8; ++j) {
        int i = j * 256 + tid;
        float q = qr[i], k = kr[i], v = vr[i];
        qv[j] = q; kv[j] = k;
        sq += q * q; sk += k * k;
        float fqe = (q / (1.f + expf(-q))) * qksc[i * 2 + 0] + qkof[i * 2 + 0];
        float fke = (k / (1.f + expf(-k))) * qksc[i * 2 + 1] + qkof[i * 2 + 1];
        fqv[j] = fqe; fkv[j] = fke; fvv[j] = v / (1.f + expf(-v));
        p2q[j >> 1] += fqe * fqe;
        p2k[j >> 1] += fke * fke;
    }
    float SQ = blockReduceSum(sq, sred);
    float SK = blockReduceSum(sk, sred);
    float G2Q[4], G2K[4];
    #pragma unroll
    for (int g = 0; g < 4; ++g) G2Q[g] = blockReduceSum(p2q[g], sred);
    #pragma unroll
    for (int g = 0; g < 4; ++g) G2K[g] = blockReduceSum(p2k[g], sred);
    float rq = rsqrtf(SQ * (1.f / 2048.f) + 1e-6f);
    float rk = rsqrtf(SK * (1.f / 2048.f) + 1e-6f);
    #pragma unroll
    for (int j = 0; j < 8; ++j) {
        int i = j * 256 + tid;
        s_q[i] = qv[j] * rq * qnw[i];
        s_k[i] = kv[j] * rk * knw[i];
        int g = j >> 1;
        long fb = (((long)(b * 4 + g)) * SEQ + t) * FDM + (i & 511);
        fq[fb] = fqv[j] / (sqrtf(G2Q[g]) + 1e-12f);
        fk[fb] = fkv[j] / (sqrtf(G2K[g]) + 1e-12f);
        fv[fb] = fvv[j];
    }
    __syncthreads();
    #pragma unroll
    for (int j = 0; j < 8; ++j) {
        int i = j * 256 + tid;
        int pos = i & 127;
        int fi = pos & 63;
        float invf = expf(-(float)fi * (logf(500000.f) / 64.f));
        float sn, cs;
        sincosf((float)t * invf, &sn, &cs);
        float oq, ok_;
        if (pos < 64) {
            oq  = s_q[i] * cs - s_q[i + 64] * sn;
            ok_ = s_k[i] * cs - s_k[i + 64] * sn;
        } else {
            oq  = s_q[i] * cs + s_q[i - 64] * sn;
            ok_ = s_k[i] * cs + s_k[i - 64] * sn;
        }
        aq[(long)row * DIMD + i] = oq;
        ak[(long)row * DIMD + i] = ok_;
    }
    if (tid < 12) {
        float x = lrpre[(long)row * 12 + tid] + lrb[tid] + base_lr_inv;
        lrout[(long)row * 12 + tid] = (x > 20.f) ? x : log1pf(expf(x));
    }
}

// ------------------- windowed flash attention (64q x 64k) -------------------
__global__ void attn_kernel(const float* __restrict__ Q, const float* __restrict__ K,
                            const float* __restrict__ QKV, float* __restrict__ O)
{
    extern __shared__ float sm[];
    float* Qs  = sm;               // 64 x 132
    float* KVs = sm + 64 * 132;    // 64 x 132
    float* Ss  = sm + 2 * 64 * 132; // 64 x 66
    int q0 = blockIdx.x << 6;
    int h = blockIdx.y, b = blockIdx.z;
    int tid = threadIdx.x;              // 256
    int tq = tid >> 2, td = tid & 3;
    const float qscale = 0.088388347648318447f * 1.4426950408889634f;

    for (int e = tid; e < 8192; e += 256) {
        int r = e >> 7, c = e & 127;
        Qs[r * 132 + c] = Q[((long)(b * SEQ + q0 + r)) * DIMD + h * 128 + c] * qscale;
    }
    float acc[32];
    #pragma unroll
    for (int d = 0; d < 32; ++d) acc[d] = 0.f;
    float m = -INFINITY, l = 0.f;

    int kt_hi = q0 >> 6;
    int kt_lo = (q0 >= 1024) ? ((q0 - 1023) >> 6) : 0;
    for (int kt = kt_lo; kt <= kt_hi; ++kt) {
        int j0 = kt << 6;
        __syncthreads();
        for (int e = tid; e < 8192; e += 256) {
            int r = e >> 7, c = e & 127;
            KVs[r * 132 + c] = K[((long)(b * SEQ + j0 + r)) * DIMD + h * 128 + c];
        }
        __syncthreads();

        float sacc[16];
        #pragma unroll
        for (int jj = 0; jj < 16; ++jj) sacc[jj] = 0.f;
        #pragma unroll 4
        for (int k4 = 0; k4 < 32; ++k4) {
            float4 qv = *(const float4*)&Qs[tq * 132 + k4 * 4];
            #pragma unroll
            for (int jj = 0; jj < 16; ++jj) {
                float4 kv = *(const float4*)&KVs[(td * 16 + jj) * 132 + k4 * 4];
                sacc[jj] += qv.x * kv.x + qv.y * kv.y + qv.z * kv.z + qv.w * kv.w;
            }
        }
        int ig = q0 + tq;
        float tmax = -INFINITY;
        #pragma unroll
        for (int jj = 0; jj < 16; ++jj) {
            int jg = j0 + td * 16 + jj;
            bool ok = (jg <= ig) && (ig - jg < 1024);
            float sv = ok ? sacc[jj] : -INFINITY;
            Ss[tq * 66 + td * 16 + jj] = sv;
            tmax = fmaxf(tmax, sv);
        }
        tmax = fmaxf(tmax, __shfl_xor_sync(0xffffffffu, tmax, 1));
        tmax = fmaxf(tmax, __shfl_xor_sync(0xffffffffu, tmax, 2));

        __syncthreads();  // everyone done with K in KVs
        for (int e = tid; e < 8192; e += 256) {
            int r = e >> 7, c = e & 127;
            KVs[r * 132 + c] = QKV[((long)(b * SEQ + j0 + r)) * 6144 + 4096 + h * 128 + c];
        }
        __syncthreads();

        float mt  = fmaxf(m, tmax);
        float mte = (mt > -INFINITY) ? mt : 0.f;
        float corr = exp2f(m - mte);
        l *= corr;
        #pragma unroll
        for (int d = 0; d < 32; ++d) acc[d] *= corr;
        float lpart = 0.f;
        #pragma unroll
        for (int jj = 0; jj < 16; ++jj) {
            float p = exp2f(Ss[tq * 66 + td * 16 + jj] - mte);
            Ss[tq * 66 + td * 16 + jj] = p;
            lpart += p;
        }
        lpart += __shfl_xor_sync(0xffffffffu, lpart, 1);
        lpart += __shfl_xor_sync(0xffffffffu, lpart, 2);
        l += lpart;
        __syncwarp();
        #pragma unroll 2
        for (int jj = 0; jj < 64; ++jj) {
            float pj = Ss[tq * 66 + jj];
            const float* vr = &KVs[jj * 132 + td * 32];
            #pragma unroll
            for (int d4 = 0; d4 < 8; ++d4) {
                float4 vv = *(const float4*)&vr[d4 * 4];
                acc[d4 * 4 + 0] = fmaf(pj, vv.x, acc[d4 * 4 + 0]);
                acc[d4 * 4 + 1] = fmaf(pj, vv.y, acc[d4 * 4 + 1]);
                acc[d4 * 4 + 2] = fmaf(pj, vv.z, acc[d4 * 4 + 2]);
                acc[d4 * 4 + 3] = fmaf(pj, vv.w, acc[d4 * 4 + 3]);
            }
        }
        m = mt;
        __syncwarp();
    }
    float rl = 1.f / l;
    float* orow = &O[((long)(b * SEQ + q0 + tq)) * DIMD + h * 128 + td * 32];
    #pragma unroll
    for (int d4 = 0; d4 < 8; ++d4) {
        float4 o;
        o.x = acc[d4 * 4 + 0] * rl; o.y = acc[d4 * 4 + 1] * rl;
        o.z = acc[d4 * 4 + 2] * rl; o.w = acc[d4 * 4 + 3] * rl;
        *(float4*)&orow[d4 * 4] = o;
    }
}

// --------------------------- TTT helper kernels -----------------------------
__global__ void copyw(const float* __restrict__ w0, const float* __restrict__ w1,
                      const float* __restrict__ w2, float* __restrict__ o0,
                      float* __restrict__ o1, float* __restrict__ o2)
{
    long idx = (long)blockIdx.x * 256 + threadIdx.x;   // total 8*512*512
    long src = idx & ((long)4 * 512 * 512 - 1);
    o0[idx] = w0[src]; o1[idx] = w1[src]; o2[idx] = w2[src];
}

__global__ void elem2(const float* __restrict__ fv, const float* __restrict__ lr,
                      float* __restrict__ gate, float* __restrict__ hpre,
                      float* __restrict__ dh, float* __restrict__ hid, int ck0)
{
    long idx = (long)blockIdx.x * 256 + threadIdx.x;   // 8*1024*512
    int col = idx & 511;
    long tt = idx >> 9;
    int c = tt & 1023, bh = tt >> 10;
    int b = bh >> 2, h = bh & 3;
    long row = (long)b * SEQ + ck0 + c;
    float l0 = lr[row * 12 + h], l1 = lr[row * 12 + 4 + h], l2 = lr[row * 12 + 8 + h];
    float g = gate[idx], hp = hpre[idx], d = dh[idx];
    float sig = 1.f / (1.f + expf(-g));
    float sg = g * sig;
    hid[idx] = sg * hp;
    float v = fv[((long)bh * SEQ + ck0 + c) * FDM + col];
    gate[idx] = d * hp * (sig * (1.f + g * (1.f - sig))) * l0;
    hpre[idx] = d * sg * l2;
    dh[idx]   = v * l1;
}

__global__ void elem3(const float* __restrict__ gate, const float* __restrict__ hpre,
                      float* __restrict__ hid)
{
    long idx = (long)blockIdx.x * 256 + threadIdx.x;
    float g = gate[idx];
    hid[idx] = (g / (1.f + expf(-g))) * hpre[idx];
}

// -------------------- ttt rmsnorm + add attention result --------------------
__global__ void post_kernel(const float* __restrict__ ttt, const float* __restrict__ tw,
                            float* __restrict__ sum)
{
    __shared__ float sr[4];
    int fh = blockIdx.x, row = blockIdx.y;
    int b = row >> 11, t = row & 2047;
    int bh = b * 4 + fh;
    const float* src = ttt + ((long)bh * SEQ + t) * FDM;
    int tid = threadIdx.x;   // 128
    float v[4], ss = 0.f;
    #pragma unroll
    for (int j = 0; j < 4; ++j) { v[j] = src[tid + 128 * j]; ss += v[j] * v[j]; }
    #pragma unroll
    for (int o = 16; o > 0; o >>= 1) ss += __shfl_down_sync(0xffffffffu, ss, o);
    if ((tid & 31) == 0) sr[tid >> 5] = ss;
    __syncthreads();
    float tot = sr[0] + sr[1] + sr[2] + sr[3];
    float r = rsqrtf(tot * (1.f / 512.f) + 1e-6f);
    #pragma unroll
    for (int j = 0; j < 4; ++j) {
        int i = tid + 128 * j;
        sum[(long)row * 2048 + fh * 512 + i] += v[j] * r * tw[i];
    }
}

// --------------------------------- launch -----------------------------------
extern "C" void kernel_launch(void* const* d_in, const int* in_sizes, int n_in,
                              void* d_out, int out_size)
{
    const float* hidden = (const float*)d_in[0];
    const float* Wqkv   = (const float*)d_in[1];
    const float* Wo     = (const float*)d_in[2];
    const float* qnw    = (const float*)d_in[3];
    const float* knw    = (const float*)d_in[4];
    const float* w0     = (const float*)d_in[5];
    const float* w1     = (const float*)d_in[6];
    const float* w2     = (const float*)d_in[7];
    const float* lrw    = (const float*)d_in[8];
    const float* lrb    = (const float*)d_in[9];
    const float* qksc   = (const float*)d_in[10];
    const float* qkof   = (const float*)d_in[11];
    const float* tttw   = (const float*)d_in[12];
    float* out = (float*)d_out;

    float *qkv, *lrpre, *lr, *aq, *ak, *fq, *fk, *fv, *pw0, *pw1, *pw2;
    float *gate, *hpre, *dh, *hid, *ttt, *sum;
    cudaGetSymbolAddress((void**)&qkv,   g_qkv);
    cudaGetSymbolAddress((void**)&lrpre, g_lrpre);
    cudaGetSymbolAddress((void**)&lr,    g_lr);
    cudaGetSymbolAddress((void**)&aq,    g_aq);
    cudaGetSymbolAddress((void**)&ak,    g_ak);
    cudaGetSymbolAddress((void**)&fq,    g_fq);
    cudaGetSymbolAddress((void**)&fk,    g_fk);
    cudaGetSymbolAddress((void**)&fv,    g_fv);
    cudaGetSymbolAddress((void**)&pw0,   g_w0);
    cudaGetSymbolAddress((void**)&pw1,   g_w1);
    cudaGetSymbolAddress((void**)&pw2,   g_w2);
    cudaGetSymbolAddress((void**)&gate,  g_gate);
    cudaGetSymbolAddress((void**)&hpre,  g_hpre);
    cudaGetSymbolAddress((void**)&dh,    g_dh);
    cudaGetSymbolAddress((void**)&hid,   g_hid);
    cudaGetSymbolAddress((void**)&ttt,   g_ttt);
    cudaGetSymbolAddress((void**)&sum,   g_sum);

    dim3 blk(256);
    // qkv = hidden @ Wqkv^T ; lrpre = hidden @ lr_w^T
    gemm128<0,1,false><<<dim3(48,32,1), blk>>>(hidden, Wqkv, qkv, 4096, 6144, 2048,
                                               2048, 2048, 6144, 0, 0, 0);
    gemm_k<0,1,false><<<dim3(1,64,1), blk>>>(hidden, lrw, lrpre, 4096, 12, 2048,
                                             2048, 2048, 12, 0, 0, 0);
    float base = (float)(0.001 + log(-expm1(-0.001)));
    prep_kernel<<<4096, 256>>>(qkv, lrpre, qnw, knw, qksc, qkof, lrb, base,
                               aq, ak, fq, fk, fv, lr);

    cudaFuncSetAttribute(attn_kernel, cudaFuncAttributeMaxDynamicSharedMemorySize, 84480);
    attn_kernel<<<dim3(32,16,2), 256, 84480>>>(aq, ak, qkv, sum);

    copyw<<<8192, 256>>>(w0, w1, w2, pw0, pw1, pw2);

    long sSeq = (long)SEQ * FDM;
    long sChk = (long)1024 * FDM;
    long sW   = (long)FDM * FDM;
    for (int ck = 0; ck < 2; ++ck) {
        int ck0 = ck * 1024;
        const float* Kc = fk + (long)ck0 * FDM;
        const float* Qc = fq + (long)ck0 * FDM;
        const float* Vc = fv + (long)ck0 * FDM;
        // gate = K@W0^T, hpre = K@W2^T, dh = V@W1
        gemm128<0,1,false><<<dim3(4,8,8), blk>>>(Kc, pw0, gate, 1024, 512, 512,
                                                 512, 512, 512, sSeq, sW, sChk);
        gemm128<0,1,false><<<dim3(4,8,8), blk>>>(Kc, pw2, hpre, 1024, 512, 512,
                                                 512, 512, 512, sSeq, sW, sChk);
        gemm128<0,0,false><<<dim3(4,8,8), blk>>>(Vc, pw1, dh, 1024, 512, 512,
                                                 512, 512, 512, sSeq, sW, sChk);
        elem2<<<16384, 256>>>(fv, lr, gate, hpre, dh, hid, ck0);
        // W0 += (dgate*l0)^T @ K ; W2 += (dhpre*l2)^T @ K ; W1 += (v*l1)^T @ hid
        gemm128<1,0,true><<<dim3(4,4,8), blk>>>(gate, Kc, pw0, 512, 512, 1024,
                                                512, 512, 512, sChk, sSeq, sW);
        gemm128<1,0,true><<<dim3(4,4,8), blk>>>(hpre, Kc, pw2, 512, 512, 1024,
                                                512, 512, 512, sChk, sSeq, sW);
        gemm128<1,0,true><<<dim3(4,4,8), blk>>>(dh, hid, pw1, 512, 512, 1024,
                                                512, 512, 512, sChk, sChk, sW);
        // query pass with updated weights
        gemm128<0,1,false><<<dim3(4,8,8), blk>>>(Qc, pw0, gate, 1024, 512, 512,
                                                 512, 512, 512, sSeq, sW, sChk);
        gemm128<0,1,false><<<dim3(4,8,8), blk>>>(Qc, pw2, hpre, 1024, 512, 512,
                                                 512, 512, 512, sSeq, sW, sChk);
        elem3<<<16384, 256>>>(gate, hpre, hid);
        gemm128<0,1,false><<<dim3(4,8,8), blk>>>(hid, pw1, ttt + (long)ck0 * FDM,
                                                 1024, 512, 512,
                                                 512, 512, 512, sChk, sW, sSeq);
    }

    post_kernel<<<dim3(4,4096), 128>>>(ttt, tttw, sum);
    // out = (attn + ttt_norm) @ Wo^T
    gemm128<0,1,false><<<dim3(16,32,1), blk>>>(sum, Wo, out, 4096, 2048, 2048,
                                               2048, 2048, 2048, 0, 0, 0);
}

// round 6
// speedup vs baseline: 1.4087x; 1.2815x over previous
#include <cuda_runtime.h>
#include <cuda_bf16.h>
#include <cstdint>
#include <math.h>

#define SEQ 2048
#define DIMD 2048
#define FDM 512

// ------------------------- fp32 scratch (device globals) --------------------
__device__ float g_qkv [(size_t)4096 * 6144];
__device__ float g_lrpre[(size_t)4096 * 12];
__device__ float g_lr  [(size_t)4096 * 12];
__device__ float g_aq  [(size_t)4096 * 2048];
__device__ float g_ak  [(size_t)4096 * 2048];
__device__ float g_fq  [(size_t)8 * SEQ * FDM];
__device__ float g_fk  [(size_t)8 * SEQ * FDM];
__device__ float g_fv  [(size_t)8 * SEQ * FDM];
__device__ float g_w0  [(size_t)8 * FDM * FDM];
__device__ float g_w1  [(size_t)8 * FDM * FDM];
__device__ float g_w2  [(size_t)8 * FDM * FDM];
__device__ float g_gate[(size_t)8 * 1024 * FDM];
__device__ float g_hpre[(size_t)8 * 1024 * FDM];
__device__ float g_dh  [(size_t)8 * 1024 * FDM];
__device__ float g_hid [(size_t)8 * 1024 * FDM];
__device__ float g_ttt [(size_t)8 * SEQ * FDM];
__device__ float g_sum [(size_t)4096 * 2048];

// ------------------------- bf16 hi/lo scratch -------------------------------
__device__ __nv_bfloat16 g_hx_h[(size_t)4096*2048],  g_hx_l[(size_t)4096*2048];
__device__ __nv_bfloat16 g_wq_h[(size_t)6144*2048],  g_wq_l[(size_t)6144*2048];
__device__ __nv_bfloat16 g_wo_h[(size_t)2048*2048],  g_wo_l[(size_t)2048*2048];
__device__ __nv_bfloat16 g_fq_h[(size_t)8*SEQ*FDM],  g_fq_l[(size_t)8*SEQ*FDM];
__device__ __nv_bfloat16 g_fk_h[(size_t)8*SEQ*FDM],  g_fk_l[(size_t)8*SEQ*FDM];
__device__ __nv_bfloat16 g_fv_h[(size_t)8*SEQ*FDM],  g_fv_l[(size_t)8*SEQ*FDM];
__device__ __nv_bfloat16 g_w0_h[(size_t)8*FDM*FDM],  g_w0_l[(size_t)8*FDM*FDM];
__device__ __nv_bfloat16 g_w2_h[(size_t)8*FDM*FDM],  g_w2_l[(size_t)8*FDM*FDM];
__device__ __nv_bfloat16 g_w1_h[(size_t)8*FDM*FDM],  g_w1_l[(size_t)8*FDM*FDM];
__device__ __nv_bfloat16 g_w1t_h[(size_t)8*FDM*FDM], g_w1t_l[(size_t)8*FDM*FDM];
__device__ __nv_bfloat16 g_dg_h[(size_t)8*FDM*1024], g_dg_l[(size_t)8*FDM*1024];
__device__ __nv_bfloat16 g_dp_h[(size_t)8*FDM*1024], g_dp_l[(size_t)8*FDM*1024];
__device__ __nv_bfloat16 g_vl_h[(size_t)8*FDM*1024], g_vl_l[(size_t)8*FDM*1024];
__device__ __nv_bfloat16 g_ht_h[(size_t)8*FDM*1024], g_ht_l[(size_t)8*FDM*1024];
__device__ __nv_bfloat16 g_fkt_h[(size_t)8*FDM*1024],g_fkt_l[(size_t)8*FDM*1024];
__device__ __nv_bfloat16 g_hn_h[(size_t)8*1024*FDM], g_hn_l[(size_t)8*1024*FDM];
__device__ __nv_bfloat16 g_sm_h[(size_t)4096*2048],  g_sm_l[(size_t)4096*2048];

// ------------------------------ helpers -------------------------------------
__device__ __forceinline__ uint32_t smem_u32(const void* p) {
    uint32_t a;
    asm("{ .reg .u64 t; cvta.to.shared.u64 t, %1; cvt.u32.u64 %0, t; }" : "=r"(a) : "l"(p));
    return a;
}
__device__ __forceinline__ void cpa16(uint32_t s, const void* g) {
    asm volatile("cp.async.cg.shared.global [%0], [%1], 16;" :: "r"(s), "l"(g));
}
#define CP_COMMIT() asm volatile("cp.async.commit_group;" ::: "memory")
#define MMA16816(d, a, b0, b1) \
    asm volatile("mma.sync.aligned.m16n8k16.row.col.f32.bf16.bf16.f32 " \
        "{%0,%1,%2,%3}, {%4,%5,%6,%7}, {%8,%9}, {%0,%1,%2,%3};" \
        : "+f"((d)[0]), "+f"((d)[1]), "+f"((d)[2]), "+f"((d)[3]) \
        : "r"((a)[0]), "r"((a)[1]), "r"((a)[2]), "r"((a)[3]), "r"(b0), "r"(b1))

// -------------------- mma.sync batched GEMM, bf16x3 split -------------------
// C[M,N] (+)= sum_k (Ah+Al)[m,k]*(Bh+Bl)[n,k]   (hi*hi + hi*lo + lo*hi)
// A,B row-major [rows, K] (ld=K). M,N mult of 128, K mult of 32.
// smem per stage: Ah(10240) Al(10240) Bh(10240) Bl(10240) = 40960, 2 stages.
// row stride 80B -> conflict-free 8-row fragment LDS.
#define STG 40960

__device__ __forceinline__ void gemm_issue(uint32_t sb, int buf,
    const __nv_bfloat16* ah, const __nv_bfloat16* al,
    const __nv_bfloat16* bh, const __nv_bfloat16* bl,
    int m0, int n0, int K, int k0, int tid)
{
    uint32_t st = sb + buf * STG;
    #pragma unroll
    for (int j = 0; j < 2; ++j) {
        int u = tid + j * 256;
        int r = u >> 2, s = u & 3;
        uint32_t so = r * 80 + s * 16;
        long ga = (long)(m0 + r) * K + k0 + s * 8;
        long gb = (long)(n0 + r) * K + k0 + s * 8;
        cpa16(st + so,         ah + ga);
        cpa16(st + 10240 + so, al + ga);
        cpa16(st + 20480 + so, bh + gb);
        cpa16(st + 30720 + so, bl + gb);
    }
    CP_COMMIT();
}

__global__ void __launch_bounds__(256, 2)
mma_gemm(const __nv_bfloat16* __restrict__ Ah, const __nv_bfloat16* __restrict__ Al,
         const __nv_bfloat16* __restrict__ Bh, const __nv_bfloat16* __restrict__ Bl,
         float* __restrict__ C, int M, int N, int K,
         long sA, long sB, long sC, int accum)
{
    extern __shared__ char smem[];
    uint32_t sb = smem_u32(smem);
    int tid = threadIdx.x, lane = tid & 31, wid = tid >> 5;
    int wm = wid >> 2, wn = wid & 3;
    long zb = blockIdx.z;
    const __nv_bfloat16* ah = Ah + zb * sA;
    const __nv_bfloat16* al = Al + zb * sA;
    const __nv_bfloat16* bh = Bh + zb * sB;
    const __nv_bfloat16* bl = Bl + zb * sB;
    float* c = C + zb * sC;
    int m0 = blockIdx.y << 7, n0 = blockIdx.x << 7;

    float acc[4][4][4];
    #pragma unroll
    for (int i = 0; i < 4; ++i)
        #pragma unroll
        for (int j = 0; j < 4; ++j)
            #pragma unroll
            for (int q = 0; q < 4; ++q) acc[i][j][q] = 0.f;

    const int n = K >> 5;
    gemm_issue(sb, 0, ah, al, bh, bl, m0, n0, K, 0, tid);
    int buf = 0;
    for (int i = 0; i < n; ++i) {
        if (i + 1 < n) {
            gemm_issue(sb, buf ^ 1, ah, al, bh, bl, m0, n0, K, (i + 1) * 32, tid);
            asm volatile("cp.async.wait_group 1;" ::: "memory");
        } else {
            asm volatile("cp.async.wait_group 0;" ::: "memory");
        }
        __syncthreads();
        const char* base = smem + buf * STG;
        #pragma unroll
        for (int kk = 0; kk < 32; kk += 16) {
            int co = (kk + (lane & 3) * 2) * 2;
            uint32_t ahf[4][4], alf[4][4];
            #pragma unroll
            for (int mt = 0; mt < 4; ++mt) {
                int r = wm * 64 + mt * 16 + (lane >> 2);
                const char* ph = base;
                const char* pl = base + 10240;
                ahf[mt][0] = *(const uint32_t*)(ph + r * 80 + co);
                ahf[mt][1] = *(const uint32_t*)(ph + (r + 8) * 80 + co);
                ahf[mt][2] = *(const uint32_t*)(ph + r * 80 + co + 16);
                ahf[mt][3] = *(const uint32_t*)(ph + (r + 8) * 80 + co + 16);
                alf[mt][0] = *(const uint32_t*)(pl + r * 80 + co);
                alf[mt][1] = *(const uint32_t*)(pl + (r + 8) * 80 + co);
                alf[mt][2] = *(const uint32_t*)(pl + r * 80 + co + 16);
                alf[mt][3] = *(const uint32_t*)(pl + (r + 8) * 80 + co + 16);
            }
            #pragma unroll
            for (int nt = 0; nt < 4; ++nt) {
                int rb = wn * 32 + nt * 8 + (lane >> 2);
                const char* pbh = base + 20480;
                const char* pbl = base + 30720;
                uint32_t bh0 = *(const uint32_t*)(pbh + rb * 80 + co);
                uint32_t bh1 = *(const uint32_t*)(pbh + rb * 80 + co + 16);
                uint32_t bl0 = *(const uint32_t*)(pbl + rb * 80 + co);
                uint32_t bl1 = *(const uint32_t*)(pbl + rb * 80 + co + 16);
                #pragma unroll
                for (int mt = 0; mt < 4; ++mt) {
                    MMA16816(acc[mt][nt], ahf[mt], bh0, bh1);
                    MMA16816(acc[mt][nt], ahf[mt], bl0, bl1);
                    MMA16816(acc[mt][nt], alf[mt], bh0, bh1);
                }
            }
        }
        __syncthreads();
        buf ^= 1;
    }
    // epilogue
    #pragma unroll
    for (int mt = 0; mt < 4; ++mt) {
        #pragma unroll
        for (int nt = 0; nt < 4; ++nt) {
            long r0 = m0 + wm * 64 + mt * 16 + (lane >> 2);
            int  cc = n0 + wn * 32 + nt * 8 + (lane & 3) * 2;
            float* p0 = c + r0 * (long)N + cc;
            float* p1 = c + (r0 + 8) * (long)N + cc;
            if (accum) {
                float2 o0 = *(float2*)p0, o1 = *(float2*)p1;
                o0.x += acc[mt][nt][0]; o0.y += acc[mt][nt][1];
                o1.x += acc[mt][nt][2]; o1.y += acc[mt][nt][3];
                *(float2*)p0 = o0; *(float2*)p1 = o1;
            } else {
                *(float2*)p0 = make_float2(acc[mt][nt][0], acc[mt][nt][1]);
                *(float2*)p1 = make_float2(acc[mt][nt][2], acc[mt][nt][3]);
            }
        }
    }
}

// ------------------------ conversion kernels --------------------------------
__global__ void cvt_hl(const float* __restrict__ x, __nv_bfloat16* __restrict__ h,
                       __nv_bfloat16* __restrict__ l, long n)
{
    long i = ((long)blockIdx.x * 256 + threadIdx.x) * 4;
    if (i >= n) return;
    float4 v = *(const float4*)(x + i);
    __nv_bfloat16 h0 = __float2bfloat16_rn(v.x), h1 = __float2bfloat16_rn(v.y);
    __nv_bfloat16 h2 = __float2bfloat16_rn(v.z), h3 = __float2bfloat16_rn(v.w);
    __nv_bfloat162 ha = {h0, h1}, hb = {h2, h3};
    __nv_bfloat162 la = {__float2bfloat16_rn(v.x - __bfloat162float(h0)),
                         __float2bfloat16_rn(v.y - __bfloat162float(h1))};
    __nv_bfloat162 lb = {__float2bfloat16_rn(v.z - __bfloat162float(h2)),
                         __float2bfloat16_rn(v.w - __bfloat162float(h3))};
    *(__nv_bfloat162*)(h + i) = ha; *(__nv_bfloat162*)(h + i + 2) = hb;
    *(__nv_bfloat162*)(l + i) = la; *(__nv_bfloat162*)(l + i + 2) = lb;
}

// transpose + split: in [R, Cc] row-major -> out [Cc, R] row-major (per batch)
__global__ void cvt_t(const float* __restrict__ x, __nv_bfloat16* __restrict__ h,
                      __nv_bfloat16* __restrict__ l, int R, int Cc, long sIn, long sOut)
{
    __shared__ float t[32][33];
    const float* src = x + (long)blockIdx.z * sIn;
    __nv_bfloat16* ho = h + (long)blockIdx.z * sOut;
    __nv_bfloat16* lo = l + (long)blockIdx.z * sOut;
    int r0 = blockIdx.y * 32, c0 = blockIdx.x * 32;
    int tx = threadIdx.x, ty = threadIdx.y;
    #pragma unroll
    for (int j = 0; j < 32; j += 8)
        t[ty + j][tx] = src[(long)(r0 + ty + j) * Cc + c0 + tx];
    __syncthreads();
    #pragma unroll
    for (int j = 0; j < 32; j += 8) {
        float v = t[tx][ty + j];
        __nv_bfloat16 hv = __float2bfloat16_rn(v);
        long o = (long)(c0 + ty + j) * R + r0 + tx;
        ho[o] = hv;
        lo[o] = __float2bfloat16_rn(v - __bfloat162float(hv));
    }
}

// ---------------- small SGEMM for the N=12 lr GEMM --------------------------
__global__ void lr_gemm(const float* __restrict__ A, const float* __restrict__ B,
                        float* __restrict__ C)
{
    __shared__ float bs[12][128];
    int row = blockIdx.x * 2 + (threadIdx.x >> 7);
    int tid = threadIdx.x & 127;
    float acc[12];
    #pragma unroll
    for (int c = 0; c < 12; ++c) acc[c] = 0.f;
    for (int k0 = 0; k0 < 2048; k0 += 128) {
        if (threadIdx.x < 128)
            #pragma unroll
            for (int c = 0; c < 12; ++c) bs[c][tid] = B[c * 2048 + k0 + tid];
        __syncthreads();
        float a = A[(long)row * 2048 + k0 + tid];
        #pragma unroll
        for (int c = 0; c < 12; ++c) acc[c] += a * bs[c][tid];
        __syncthreads();
    }
    __shared__ float red[2][12][4];
    #pragma unroll
    for (int c = 0; c < 12; ++c) {
        float v = acc[c];
        #pragma unroll
        for (int o = 16; o > 0; o >>= 1) v += __shfl_down_sync(0xffffffffu, v, o);
        if ((tid & 31) == 0) red[threadIdx.x >> 7][c][tid >> 5] = v;
    }
    __syncthreads();
    if (tid < 12) {
        int w = threadIdx.x >> 7;
        C[(long)row * 12 + tid] = red[w][tid][0] + red[w][tid][1] + red[w][tid][2] + red[w][tid][3];
    }
}

// ------------------------- block reduce (256 thr) ---------------------------
__device__ __forceinline__ float blockReduceSum(float v, float* sred)
{
    int lane = threadIdx.x & 31;
    #pragma unroll
    for (int o = 16; o > 0; o >>= 1) v += __shfl_down_sync(0xffffffffu, v, o);
    if (lane == 0) sred[threadIdx.x >> 5] = v;
    __syncthreads();
    if (threadIdx.x < 8) {
        float r = sred[threadIdx.x];
        #pragma unroll
        for (int o = 4; o > 0; o >>= 1) r += __shfl_down_sync(0xffu, r, o);
        if (threadIdx.x == 0) sred[0] = r;
    }
    __syncthreads();
    float out = sred[0];
    __syncthreads();
    return out;
}

// --------- prep: rmsnorm+rope (attn path) + silu/L2 (fast path) + lr --------
__global__ void prep_kernel(const float* __restrict__ qkv, const float* __restrict__ lrpre,
                            const float* __restrict__ qnw, const float* __restrict__ knw,
                            const float* __restrict__ qksc, const float* __restrict__ qkof,
                            const float* __restrict__ lrb, float base_lr_inv,
                            float* __restrict__ aq, float* __restrict__ ak,
                            float* __restrict__ fq, float* __restrict__ fk,
                            float* __restrict__ fv, float* __restrict__ lrout)
{
    __shared__ float s_q[2048];
    __shared__ float s_k[2048];
    __shared__ float sred[8];
    int row = blockIdx.x;
    int b = row >> 11, t = row & 2047;
    int tid = threadIdx.x;
    const float* qr = qkv + (long)row * 6144;
    const float* kr = qr + 2048;
    const float* vr = qr + 4096;

    float qv[8], kv[8], fqv[8], fkv[8], fvv[8];
    float sq = 0.f, sk = 0.f;
    float p2q[4] = {0, 0, 0, 0}, p2k[4] = {0, 0, 0, 0};
    #pragma unroll
    for (int j = 0; j < 8; ++j) {
        int i = j * 256 + tid;
        float q = qr[i], k = kr[i], v = vr[i];
        qv[j] = q; kv[j] = k;
        sq += q * q; sk += k * k;
        float fqe = (q / (1.f + expf(-q))) * qksc[i * 2 + 0] + qkof[i * 2 + 0];
        float fke = (k / (1.f + expf(-k))) * qksc[i * 2 + 1] + qkof[i * 2 + 1];
        fqv[j] = fqe; fkv[j] = fke; fvv[j] = v / (1.f + expf(-v));
        p2q[j >> 1] += fqe * fqe;
        p2k[j >> 1] += fke * fke;
    }
    float SQ = blockReduceSum(sq, sred);
    float SK = blockReduceSum(sk, sred);
    float G2Q[4], G2K[4];
    #pragma unroll
    for (int g = 0; g < 4; ++g) G2Q[g] = blockReduceSum(p2q[g], sred);
    #pragma unroll
    for (int g = 0; g < 4; ++g) G2K[g] = blockReduceSum(p2k[g], sred);
    float rq = rsqrtf(SQ * (1.f / 2048.f) + 1e-6f);
    float rk = rsqrtf(SK * (1.f / 2048.f) + 1e-6f);
    #pragma unroll
    for (int j = 0; j < 8; ++j) {
        int i = j * 256 + tid;
        s_q[i] = qv[j] * rq * qnw[i];
        s_k[i] = kv[j] * rk * knw[i];
        int g = j >> 1;
        long fb = (((long)(b * 4 + g)) * SEQ + t) * FDM + (i & 511);
        fq[fb] = fqv[j] / (sqrtf(G2Q[g]) + 1e-12f);
        fk[fb] = fkv[j] / (sqrtf(G2K[g]) + 1e-12f);
        fv[fb] = fvv[j];
    }
    __syncthreads();
    #pragma unroll
    for (int j = 0; j < 8; ++j) {
        int i = j * 256 + tid;
        int pos = i & 127;
        int fi = pos & 63;
        float invf = expf(-(float)fi * (logf(500000.f) / 64.f));
        float sn, cs;
        sincosf((float)t * invf, &sn, &cs);
        float oq, ok_;
        if (pos < 64) {
            oq  = s_q[i] * cs - s_q[i + 64] * sn;
            ok_ = s_k[i] * cs - s_k[i + 64] * sn;
        } else {
            oq  = s_q[i] * cs + s_q[i - 64] * sn;
            ok_ = s_k[i] * cs + s_k[i - 64] * sn;
        }
        aq[(long)row * DIMD + i] = oq;
        ak[(long)row * DIMD + i] = ok_;
    }
    if (tid < 12) {
        float x = lrpre[(long)row * 12 + tid] + lrb[tid] + base_lr_inv;
        lrout[(long)row * 12 + tid] = (x > 20.f) ? x : log1pf(expf(x));
    }
}

// ------------------- windowed flash attention (64q x 64k) -------------------
__global__ void attn_kernel(const float* __restrict__ Q, const float* __restrict__ K,
                            const float* __restrict__ QKV, float* __restrict__ O)
{
    extern __shared__ float sm[];
    float* Qs  = sm;
    float* KVs = sm + 64 * 132;
    float* Ss  = sm + 2 * 64 * 132;
    int q0 = blockIdx.x << 6;
    int h = blockIdx.y, b = blockIdx.z;
    int tid = threadIdx.x;
    int tq = tid >> 2, td = tid & 3;
    const float qscale = 0.088388347648318447f * 1.4426950408889634f;

    for (int e = tid; e < 8192; e += 256) {
        int r = e >> 7, c = e & 127;
        Qs[r * 132 + c] = Q[((long)(b * SEQ + q0 + r)) * DIMD + h * 128 + c] * qscale;
    }
    float acc[32];
    #pragma unroll
    for (int d = 0; d < 32; ++d) acc[d] = 0.f;
    float m = -INFINITY, l = 0.f;

    int kt_hi = q0 >> 6;
    int kt_lo = (q0 >= 1024) ? ((q0 - 1023) >> 6) : 0;
    for (int kt = kt_lo; kt <= kt_hi; ++kt) {
        int j0 = kt << 6;
        __syncthreads();
        for (int e = tid; e < 8192; e += 256) {
            int r = e >> 7, c = e & 127;
            KVs[r * 132 + c] = K[((long)(b * SEQ + j0 + r)) * DIMD + h * 128 + c];
        }
        __syncthreads();

        float sacc[16];
        #pragma unroll
        for (int jj = 0; jj < 16; ++jj) sacc[jj] = 0.f;
        #pragma unroll 4
        for (int k4 = 0; k4 < 32; ++k4) {
            float4 qv = *(const float4*)&Qs[tq * 132 + k4 * 4];
            #pragma unroll
            for (int jj = 0; jj < 16; ++jj) {
                float4 kv = *(const float4*)&KVs[(td * 16 + jj) * 132 + k4 * 4];
                sacc[jj] += qv.x * kv.x + qv.y * kv.y + qv.z * kv.z + qv.w * kv.w;
            }
        }
        int ig = q0 + tq;
        float tmax = -INFINITY;
        #pragma unroll
        for (int jj = 0; jj < 16; ++jj) {
            int jg = j0 + td * 16 + jj;
            bool ok = (jg <= ig) && (ig - jg < 1024);
            float sv = ok ? sacc[jj] : -INFINITY;
            Ss[tq * 66 + td * 16 + jj] = sv;
            tmax = fmaxf(tmax, sv);
        }
        tmax = fmaxf(tmax, __shfl_xor_sync(0xffffffffu, tmax, 1));
        tmax = fmaxf(tmax, __shfl_xor_sync(0xffffffffu, tmax, 2));

        __syncthreads();
        for (int e = tid; e < 8192; e += 256) {
            int r = e >> 7, c = e & 127;
            KVs[r * 132 + c] = QKV[((long)(b * SEQ + j0 + r)) * 6144 + 4096 + h * 128 + c];
        }
        __syncthreads();

        float mt  = fmaxf(m, tmax);
        float mte = (mt > -INFINITY) ? mt : 0.f;
        float corr = exp2f(m - mte);
        l *= corr;
        #pragma unroll
        for (int d = 0; d < 32; ++d) acc[d] *= corr;
        float lpart = 0.f;
        #pragma unroll
        for (int jj = 0; jj < 16; ++jj) {
            float p = exp2f(Ss[tq * 66 + td * 16 + jj] - mte);
            Ss[tq * 66 + td * 16 + jj] = p;
            lpart += p;
        }
        lpart += __shfl_xor_sync(0xffffffffu, lpart, 1);
        lpart += __shfl_xor_sync(0xffffffffu, lpart, 2);
        l += lpart;
        __syncwarp();
        #pragma unroll 2
        for (int jj = 0; jj < 64; ++jj) {
            float pj = Ss[tq * 66 + jj];
            const float* vr = &KVs[jj * 132 + td * 32];
            #pragma unroll
            for (int d4 = 0; d4 < 8; ++d4) {
                float4 vv = *(const float4*)&vr[d4 * 4];
                acc[d4 * 4 + 0] = fmaf(pj, vv.x, acc[d4 * 4 + 0]);
                acc[d4 * 4 + 1] = fmaf(pj, vv.y, acc[d4 * 4 + 1]);
                acc[d4 * 4 + 2] = fmaf(pj, vv.z, acc[d4 * 4 + 2]);
                acc[d4 * 4 + 3] = fmaf(pj, vv.w, acc[d4 * 4 + 3]);
            }
        }
        m = mt;
        __syncwarp();
    }
    float rl = 1.f / l;
    float* orow = &O[((long)(b * SEQ + q0 + tq)) * DIMD + h * 128 + td * 32];
    #pragma unroll
    for (int d4 = 0; d4 < 8; ++d4) {
        float4 o;
        o.x = acc[d4 * 4 + 0] * rl; o.y = acc[d4 * 4 + 1] * rl;
        o.z = acc[d4 * 4 + 2] * rl; o.w = acc[d4 * 4 + 3] * rl;
        *(float4*)&orow[d4 * 4] = o;
    }
}

// --------------------------- TTT helper kernels -----------------------------
__global__ void copyw(const float* __restrict__ w0, const float* __restrict__ w1,
                      const float* __restrict__ w2, float* __restrict__ o0,
                      float* __restrict__ o1, float* __restrict__ o2)
{
    long idx = (long)blockIdx.x * 256 + threadIdx.x;
    long src = idx & ((long)4 * 512 * 512 - 1);
    o0[idx] = w0[src]; o1[idx] = w1[src]; o2[idx] = w2[src];
}

__global__ void elem2(const float* __restrict__ fv, const float* __restrict__ lr,
                      float* __restrict__ gate, float* __restrict__ hpre,
                      float* __restrict__ dh, float* __restrict__ hid, int ck0)
{
    long idx = (long)blockIdx.x * 256 + threadIdx.x;
    int col = idx & 511;
    long tt = idx >> 9;
    int c = tt & 1023, bh = tt >> 10;
    int b = bh >> 2, h = bh & 3;
    long row = (long)b * SEQ + ck0 + c;
    float l0 = lr[row * 12 + h], l1 = lr[row * 12 + 4 + h], l2 = lr[row * 12 + 8 + h];
    float g = gate[idx], hp = hpre[idx], d = dh[idx];
    float sig = 1.f / (1.f + expf(-g));
    float sg = g * sig;
    hid[idx] = sg * hp;
    float v = fv[((long)bh * SEQ + ck0 + c) * FDM + col];
    gate[idx] = d * hp * (sig * (1.f + g * (1.f - sig))) * l0;
    hpre[idx] = d * sg * l2;
    dh[idx]   = v * l1;
}

__global__ void elem3(const float* __restrict__ gate, const float* __restrict__ hpre,
                      float* __restrict__ hid)
{
    long idx = (long)blockIdx.x * 256 + threadIdx.x;
    float g = gate[idx];
    hid[idx] = (g / (1.f + expf(-g))) * hpre[idx];
}

// -------------------- ttt rmsnorm + add attention result --------------------
__global__ void post_kernel(const float* __restrict__ ttt, const float* __restrict__ tw,
                            float* __restrict__ sum)
{
    __shared__ float sr[4];
    int fh = blockIdx.x, row = blockIdx.y;
    int b = row >> 11, t = row & 2047;
    int bh = b * 4 + fh;
    const float* src = ttt + ((long)bh * SEQ + t) * FDM;
    int tid = threadIdx.x;
    float v[4], ss = 0.f;
    #pragma unroll
    for (int j = 0; j < 4; ++j) { v[j] = src[tid + 128 * j]; ss += v[j] * v[j]; }
    #pragma unroll
    for (int o = 16; o > 0; o >>= 1) ss += __shfl_down_sync(0xffffffffu, ss, o);
    if ((tid & 31) == 0) sr[tid >> 5] = ss;
    __syncthreads();
    float tot = sr[0] + sr[1] + sr[2] + sr[3];
    float r = rsqrtf(tot * (1.f / 512.f) + 1e-6f);
    #pragma unroll
    for (int j = 0; j < 4; ++j) {
        int i = tid + 128 * j;
        sum[(long)row * 2048 + fh * 512 + i] += v[j] * r * tw[i];
    }
}

// --------------------------------- launch -----------------------------------
#define GSYM(p, s) cudaGetSymbolAddress((void**)&(p), s)

extern "C" void kernel_launch(void* const* d_in, const int* in_sizes, int n_in,
                              void* d_out, int out_size)
{
    const float* hidden = (const float*)d_in[0];
    const float* Wqkv   = (const float*)d_in[1];
    const float* Wo     = (const float*)d_in[2];
    const float* qnw    = (const float*)d_in[3];
    const float* knw    = (const float*)d_in[4];
    const float* w0     = (const float*)d_in[5];
    const float* w1     = (const float*)d_in[6];
    const float* w2     = (const float*)d_in[7];
    const float* lrw    = (const float*)d_in[8];
    const float* lrb    = (const float*)d_in[9];
    const float* qksc   = (const float*)d_in[10];
    const float* qkof   = (const float*)d_in[11];
    const float* tttw   = (const float*)d_in[12];
    float* out = (float*)d_out;

    float *qkv, *lrpre, *lr, *aq, *ak, *fq, *fk, *fv, *pw0, *pw1, *pw2;
    float *gate, *hpre, *dh, *hid, *ttt, *sum;
    GSYM(qkv, g_qkv);   GSYM(lrpre, g_lrpre); GSYM(lr, g_lr);
    GSYM(aq, g_aq);     GSYM(ak, g_ak);
    GSYM(fq, g_fq);     GSYM(fk, g_fk);       GSYM(fv, g_fv);
    GSYM(pw0, g_w0);    GSYM(pw1, g_w1);      GSYM(pw2, g_w2);
    GSYM(gate, g_gate); GSYM(hpre, g_hpre);   GSYM(dh, g_dh);
    GSYM(hid, g_hid);   GSYM(ttt, g_ttt);     GSYM(sum, g_sum);

    __nv_bfloat16 *hxh,*hxl,*wqh,*wql,*woh,*wol,*fqh,*fql,*fkh,*fkl,*fvh,*fvl;
    __nv_bfloat16 *w0h,*w0l,*w2h,*w2l,*w1h,*w1l,*w1th,*w1tl;
    __nv_bfloat16 *dgh,*dgl,*dph,*dpl,*vlh,*vll,*hth,*htl,*fkth,*fktl,*hnh,*hnl,*smh,*sml;
    GSYM(hxh, g_hx_h); GSYM(hxl, g_hx_l); GSYM(wqh, g_wq_h); GSYM(wql, g_wq_l);
    GSYM(woh, g_wo_h); GSYM(wol, g_wo_l);
    GSYM(fqh, g_fq_h); GSYM(fql, g_fq_l); GSYM(fkh, g_fk_h); GSYM(fkl, g_fk_l);
    GSYM(fvh, g_fv_h); GSYM(fvl, g_fv_l);
    GSYM(w0h, g_w0_h); GSYM(w0l, g_w0_l); GSYM(w2h, g_w2_h); GSYM(w2l, g_w2_l);
    GSYM(w1h, g_w1_h); GSYM(w1l, g_w1_l); GSYM(w1th, g_w1t_h); GSYM(w1tl, g_w1t_l);
    GSYM(dgh, g_dg_h); GSYM(dgl, g_dg_l); GSYM(dph, g_dp_h); GSYM(dpl, g_dp_l);
    GSYM(vlh, g_vl_h); GSYM(vll, g_vl_l); GSYM(hth, g_ht_h); GSYM(htl, g_ht_l);
    GSYM(fkth, g_fkt_h); GSYM(fktl, g_fkt_l);
    GSYM(hnh, g_hn_h); GSYM(hnl, g_hn_l); GSYM(smh, g_sm_h); GSYM(sml, g_sm_l);

    cudaFuncSetAttribute(mma_gemm, cudaFuncAttributeMaxDynamicSharedMemorySize, 2 * STG);
    cudaFuncSetAttribute(attn_kernel, cudaFuncAttributeMaxDynamicSharedMemorySize, 84480);

    #define MMAG(Ah,Al,Bh,Bl,C,M,N,K,sA,sB,sC,acc,bat) \
        mma_gemm<<<dim3((N)/128,(M)/128,(bat)),256,2*STG>>>(Ah,Al,Bh,Bl,C,M,N,K,sA,sB,sC,acc)

    // ---- inputs -> bf16 hi/lo ----
    cvt_hl<<<8192, 256>>>(hidden, hxh, hxl, (long)4096 * 2048);
    cvt_hl<<<12288, 256>>>(Wqkv, wqh, wql, (long)6144 * 2048);
    cvt_hl<<<4096, 256>>>(Wo, woh, wol, (long)2048 * 2048);

    // qkv = hidden @ Wqkv^T ; lrpre = hidden @ lr_w^T
    MMAG(hxh, hxl, wqh, wql, qkv, 4096, 6144, 2048, 0, 0, 0, 0, 1);
    lr_gemm<<<2048, 256>>>(hidden, lrw, lrpre);

    float base = (float)(0.001 + log(-expm1(-0.001)));
    prep_kernel<<<4096, 256>>>(qkv, lrpre, qnw, knw, qksc, qkof, lrb, base,
                               aq, ak, fq, fk, fv, lr);
    attn_kernel<<<dim3(32, 16, 2), 256, 84480>>>(aq, ak, qkv, sum);

    cvt_hl<<<8192, 256>>>(fq, fqh, fql, (long)8 * SEQ * FDM);
    cvt_hl<<<8192, 256>>>(fk, fkh, fkl, (long)8 * SEQ * FDM);
    cvt_hl<<<8192, 256>>>(fv, fvh, fvl, (long)8 * SEQ * FDM);

    copyw<<<8192, 256>>>(w0, w1, w2, pw0, pw1, pw2);
    cvt_hl<<<2048, 256>>>(pw0, w0h, w0l, (long)8 * FDM * FDM);
    cvt_hl<<<2048, 256>>>(pw2, w2h, w2l, (long)8 * FDM * FDM);
    cvt_t<<<dim3(16, 16, 8), dim3(32, 8)>>>(pw1, w1th, w1tl, 512, 512, 262144, 262144);

    long sSeq = (long)SEQ * FDM;     // 1048576
    long sChk = (long)1024 * FDM;    // 524288
    long sW   = (long)FDM * FDM;     // 262144
    for (int ck = 0; ck < 2; ++ck) {
        int ck0 = ck * 1024;
        // forward with old weights
        MMAG(fkh + (long)ck0 * FDM, fkl + (long)ck0 * FDM, w0h, w0l, gate,
             1024, 512, 512, sSeq, sW, sChk, 0, 8);
        MMAG(fkh + (long)ck0 * FDM, fkl + (long)ck0 * FDM, w2h, w2l, hpre,
             1024, 512, 512, sSeq, sW, sChk, 0, 8);
        MMAG(fvh + (long)ck0 * FDM, fvl + (long)ck0 * FDM, w1th, w1tl, dh,
             1024, 512, 512, sSeq, sW, sChk, 0, 8);
        elem2<<<16384, 256>>>(fv, lr, gate, hpre, dh, hid, ck0);
        // transposed bf16 operands for updates
        cvt_t<<<dim3(16, 32, 8), dim3(32, 8)>>>(gate, dgh, dgl, 1024, 512, sChk, sChk);
        cvt_t<<<dim3(16, 32, 8), dim3(32, 8)>>>(hpre, dph, dpl, 1024, 512, sChk, sChk);
        cvt_t<<<dim3(16, 32, 8), dim3(32, 8)>>>(dh, vlh, vll, 1024, 512, sChk, sChk);
        cvt_t<<<dim3(16, 32, 8), dim3(32, 8)>>>(hid, hth, htl, 1024, 512, sChk, sChk);
        cvt_t<<<dim3(16, 32, 8), dim3(32, 8)>>>(fk + (long)ck0 * FDM, fkth, fktl,
                                                1024, 512, sSeq, sChk);
        // weight updates (fp32 accumulate)
        MMAG(dgh, dgl, fkth, fktl, pw0, 512, 512, 1024, sChk, sChk, sW, 1, 8);
        MMAG(dph, dpl, fkth, fktl, pw2, 512, 512, 1024, sChk, sChk, sW, 1, 8);
        MMAG(vlh, vll, hth, htl, pw1, 512, 512, 1024, sChk, sChk, sW, 1, 8);
        // re-convert updated weights
        cvt_hl<<<2048, 256>>>(pw0, w0h, w0l, (long)8 * FDM * FDM);
        cvt_hl<<<2048, 256>>>(pw2, w2h, w2l, (long)8 * FDM * FDM);
        cvt_hl<<<2048, 256>>>(pw1, w1h, w1l, (long)8 * FDM * FDM);
        cvt_t<<<dim3(16, 16, 8), dim3(32, 8)>>>(pw1, w1th, w1tl, 512, 512, 262144, 262144);
        // query pass with updated weights
        MMAG(fqh + (long)ck0 * FDM, fql + (long)ck0 * FDM, w0h, w0l, gate,
             1024, 512, 512, sSeq, sW, sChk, 0, 8);
        MMAG(fqh + (long)ck0 * FDM, fql + (long)ck0 * FDM, w2h, w2l, hpre,
             1024, 512, 512, sSeq, sW, sChk, 0, 8);
        elem3<<<16384, 256>>>(gate, hpre, hid);
        cvt_hl<<<4096, 256>>>(hid, hnh, hnl, (long)8 * 1024 * FDM);
        MMAG(hnh, hnl, w1h, w1l, ttt + (long)ck0 * FDM,
             1024, 512, 512, sChk, sW, sSeq, 0, 8);
    }

    post_kernel<<<dim3(4, 4096), 128>>>(ttt, tttw, sum);
    cvt_hl<<<8192, 256>>>(sum, smh, sml, (long)4096 * 2048);
    // out = (attn + ttt_norm) @ Wo^T
    MMAG(smh, sml, woh, wol, out, 4096, 2048, 2048, 0, 0, 0, 0, 1);
    #undef MMAG
}

// round 7
// speedup vs baseline: 3.2283x; 2.2916x over previous
#include <cuda_runtime.h>
#include <cuda_bf16.h>
#include <cstdint>
#include <math.h>

#define SEQ 2048
#define DIMD 2048
#define FDM 512

// ------------------------- fp32 scratch (device globals) --------------------
__device__ float g_qkv [(size_t)4096 * 6144];
__device__ float g_lrpre[(size_t)4096 * 12];
__device__ float g_lr  [(size_t)4096 * 12];
__device__ float g_aq  [(size_t)4096 * 2048];
__device__ float g_ak  [(size_t)4096 * 2048];
__device__ float g_fq  [(size_t)8 * SEQ * FDM];
__device__ float g_fk  [(size_t)8 * SEQ * FDM];
__device__ float g_fv  [(size_t)8 * SEQ * FDM];
__device__ float g_w02 [(size_t)8 * 1024 * FDM];     // rows 0-511 = W0, 512-1023 = W2
__device__ float g_w1  [(size_t)8 * FDM * FDM];
__device__ float g_gh  [(size_t)8 * 1024 * 1024];    // gate | hpre combined
__device__ float g_dgp [(size_t)8 * 1024 * 1024];    // dgate*l0 | dhpre*l2 combined
__device__ float g_dh  [(size_t)8 * 1024 * FDM];
__device__ float g_hid [(size_t)8 * 1024 * FDM];
__device__ float g_ttt [(size_t)8 * SEQ * FDM];
__device__ float g_sum [(size_t)4096 * 2048];

// ------------------------- bf16 hi/lo scratch -------------------------------
__device__ __nv_bfloat16 g_hx_h[(size_t)4096*2048],  g_hx_l[(size_t)4096*2048];
__device__ __nv_bfloat16 g_wq_h[(size_t)6144*2048],  g_wq_l[(size_t)6144*2048];
__device__ __nv_bfloat16 g_wo_h[(size_t)2048*2048],  g_wo_l[(size_t)2048*2048];
__device__ __nv_bfloat16 g_fq_h[(size_t)8*SEQ*FDM],  g_fq_l[(size_t)8*SEQ*FDM];
__device__ __nv_bfloat16 g_fk_h[(size_t)8*SEQ*FDM],  g_fk_l[(size_t)8*SEQ*FDM];
__device__ __nv_bfloat16 g_fv_h[(size_t)8*SEQ*FDM],  g_fv_l[(size_t)8*SEQ*FDM];
__device__ __nv_bfloat16 g_w02_h[(size_t)8*1024*FDM], g_w02_l[(size_t)8*1024*FDM];
__device__ __nv_bfloat16 g_w1_h[(size_t)8*FDM*FDM],  g_w1_l[(size_t)8*FDM*FDM];
__device__ __nv_bfloat16 g_w1t_h[(size_t)8*FDM*FDM], g_w1t_l[(size_t)8*FDM*FDM];
__device__ __nv_bfloat16 g_dgpt_h[(size_t)8*1024*1024], g_dgpt_l[(size_t)8*1024*1024];
__device__ __nv_bfloat16 g_vl_h[(size_t)8*FDM*1024], g_vl_l[(size_t)8*FDM*1024];
__device__ __nv_bfloat16 g_ht_h[(size_t)8*FDM*1024], g_ht_l[(size_t)8*FDM*1024];
__device__ __nv_bfloat16 g_fkt_h[(size_t)8*FDM*1024],g_fkt_l[(size_t)8*FDM*1024];
__device__ __nv_bfloat16 g_hn_h[(size_t)8*1024*FDM], g_hn_l[(size_t)8*1024*FDM];
__device__ __nv_bfloat16 g_sm_h[(size_t)4096*2048],  g_sm_l[(size_t)4096*2048];

// ------------------------------ helpers -------------------------------------
__device__ __forceinline__ uint32_t smem_u32(const void* p) {
    uint32_t a;
    asm("{ .reg .u64 t; cvta.to.shared.u64 t, %1; cvt.u32.u64 %0, t; }" : "=r"(a) : "l"(p));
    return a;
}
__device__ __forceinline__ void cpa16(uint32_t s, const void* g) {
    asm volatile("cp.async.cg.shared.global [%0], [%1], 16;" :: "r"(s), "l"(g));
}
#define CP_COMMIT() asm volatile("cp.async.commit_group;" ::: "memory")
#define MMA16816(d, a, b0, b1) \
    asm volatile("mma.sync.aligned.m16n8k16.row.col.f32.bf16.bf16.f32 " \
        "{%0,%1,%2,%3}, {%4,%5,%6,%7}, {%8,%9}, {%0,%1,%2,%3};" \
        : "+f"((d)[0]), "+f"((d)[1]), "+f"((d)[2]), "+f"((d)[3]) \
        : "r"((a)[0]), "r"((a)[1]), "r"((a)[2]), "r"((a)[3]), "r"(b0), "r"(b1))
__device__ __forceinline__ void ldmx4(uint32_t* r, uint32_t addr) {
    asm volatile("ldmatrix.sync.aligned.m8n8.x4.shared.b16 {%0,%1,%2,%3}, [%4];"
        : "=r"(r[0]), "=r"(r[1]), "=r"(r[2]), "=r"(r[3]) : "r"(addr));
}

// -------------------- mma.sync batched GEMM, bf16x3 split -------------------
// C[M,N] (+)= sum_k (Ah+Al)[m,k]*(Bh+Bl)[n,k]   (hi*hi + hi*lo + lo*hi)
// A,B row-major [rows, K] (ld=K). M,N mult of 128, K mult of 32.
#define STG 40960

__device__ __forceinline__ void gemm_issue(uint32_t sb, int buf,
    const __nv_bfloat16* ah, const __nv_bfloat16* al,
    const __nv_bfloat16* bh, const __nv_bfloat16* bl,
    int m0, int n0, int K, int k0, int tid)
{
    uint32_t st = sb + buf * STG;
    #pragma unroll
    for (int j = 0; j < 2; ++j) {
        int u = tid + j * 256;
        int r = u >> 2, s = u & 3;
        uint32_t so = r * 80 + s * 16;
        long ga = (long)(m0 + r) * K + k0 + s * 8;
        long gb = (long)(n0 + r) * K + k0 + s * 8;
        cpa16(st + so,         ah + ga);
        cpa16(st + 10240 + so, al + ga);
        cpa16(st + 20480 + so, bh + gb);
        cpa16(st + 30720 + so, bl + gb);
    }
    CP_COMMIT();
}

__global__ void __launch_bounds__(256, 2)
mma_gemm(const __nv_bfloat16* __restrict__ Ah, const __nv_bfloat16* __restrict__ Al,
         const __nv_bfloat16* __restrict__ Bh, const __nv_bfloat16* __restrict__ Bl,
         float* __restrict__ C, int M, int N, int K,
         long sA, long sB, long sC, int accum)
{
    extern __shared__ char smem[];
    uint32_t sb = smem_u32(smem);
    int tid = threadIdx.x, lane = tid & 31, wid = tid >> 5;
    int wm = wid >> 2, wn = wid & 3;
    long zb = blockIdx.z;
    const __nv_bfloat16* ah = Ah + zb * sA;
    const __nv_bfloat16* al = Al + zb * sA;
    const __nv_bfloat16* bh = Bh + zb * sB;
    const __nv_bfloat16* bl = Bl + zb * sB;
    float* c = C + zb * sC;
    int m0 = blockIdx.y << 7, n0 = blockIdx.x << 7;

    float acc[4][4][4];
    #pragma unroll
    for (int i = 0; i < 4; ++i)
        #pragma unroll
        for (int j = 0; j < 4; ++j)
            #pragma unroll
            for (int q = 0; q < 4; ++q) acc[i][j][q] = 0.f;

    // ldmatrix per-lane offsets
    uint32_t a_row = (lane & 7) + ((lane >> 3) & 1) * 8;
    uint32_t a_kb  = ((lane >> 4) & 1) * 16;
    uint32_t b_row = (lane & 7) + ((lane >> 4) & 1) * 8;
    uint32_t b_kb  = ((lane >> 3) & 1) * 16;

    const int n = K >> 5;
    gemm_issue(sb, 0, ah, al, bh, bl, m0, n0, K, 0, tid);
    int buf = 0;
    for (int i = 0; i < n; ++i) {
        if (i + 1 < n) {
            gemm_issue(sb, buf ^ 1, ah, al, bh, bl, m0, n0, K, (i + 1) * 32, tid);
            asm volatile("cp.async.wait_group 1;" ::: "memory");
        } else {
            asm volatile("cp.async.wait_group 0;" ::: "memory");
        }
        __syncthreads();
        uint32_t st = sb + buf * STG;
        #pragma unroll
        for (int kk = 0; kk < 32; kk += 16) {
            uint32_t ahf[4][4], alf[4][4];
            #pragma unroll
            for (int mt = 0; mt < 4; ++mt) {
                uint32_t ra = st + (wm * 64 + mt * 16 + a_row) * 80 + kk * 2 + a_kb;
                ldmx4(ahf[mt], ra);
                ldmx4(alf[mt], ra + 10240);
            }
            uint32_t bhf[2][4], blf[2][4];
            #pragma unroll
            for (int p = 0; p < 2; ++p) {
                uint32_t rb = st + 20480 + (wn * 32 + p * 16 + b_row) * 80 + kk * 2 + b_kb;
                ldmx4(bhf[p], rb);
                ldmx4(blf[p], rb + 10240);
            }
            #pragma unroll
            for (int nt = 0; nt < 4; ++nt) {
                uint32_t bh0 = bhf[nt >> 1][(nt & 1) * 2 + 0];
                uint32_t bh1 = bhf[nt >> 1][(nt & 1) * 2 + 1];
                uint32_t bl0 = blf[nt >> 1][(nt & 1) * 2 + 0];
                uint32_t bl1 = blf[nt >> 1][(nt & 1) * 2 + 1];
                #pragma unroll
                for (int mt = 0; mt < 4; ++mt) {
                    MMA16816(acc[mt][nt], ahf[mt], bh0, bh1);
                    MMA16816(acc[mt][nt], ahf[mt], bl0, bl1);
                    MMA16816(acc[mt][nt], alf[mt], bh0, bh1);
                }
            }
        }
        __syncthreads();
        buf ^= 1;
    }
    // epilogue
    #pragma unroll
    for (int mt = 0; mt < 4; ++mt) {
        #pragma unroll
        for (int nt = 0; nt < 4; ++nt) {
            long r0 = m0 + wm * 64 + mt * 16 + (lane >> 2);
            int  cc = n0 + wn * 32 + nt * 8 + (lane & 3) * 2;
            float* p0 = c + r0 * (long)N + cc;
            float* p1 = c + (r0 + 8) * (long)N + cc;
            if (accum) {
                float2 o0 = *(float2*)p0, o1 = *(float2*)p1;
                o0.x += acc[mt][nt][0]; o0.y += acc[mt][nt][1];
                o1.x += acc[mt][nt][2]; o1.y += acc[mt][nt][3];
                *(float2*)p0 = o0; *(float2*)p1 = o1;
            } else {
                *(float2*)p0 = make_float2(acc[mt][nt][0], acc[mt][nt][1]);
                *(float2*)p1 = make_float2(acc[mt][nt][2], acc[mt][nt][3]);
            }
        }
    }
}

// ------------------------ conversion kernels --------------------------------
__global__ void cvt_hl(const float* __restrict__ x, __nv_bfloat16* __restrict__ h,
                       __nv_bfloat16* __restrict__ l, long n)
{
    long i = ((long)blockIdx.x * 256 + threadIdx.x) * 4;
    if (i >= n) return;
    float4 v = *(const float4*)(x + i);
    __nv_bfloat16 h0 = __float2bfloat16_rn(v.x), h1 = __float2bfloat16_rn(v.y);
    __nv_bfloat16 h2 = __float2bfloat16_rn(v.z), h3 = __float2bfloat16_rn(v.w);
    __nv_bfloat162 ha = {h0, h1}, hb = {h2, h3};
    __nv_bfloat162 la = {__float2bfloat16_rn(v.x - __bfloat162float(h0)),
                         __float2bfloat16_rn(v.y - __bfloat162float(h1))};
    __nv_bfloat162 lb = {__float2bfloat16_rn(v.z - __bfloat162float(h2)),
                         __float2bfloat16_rn(v.w - __bfloat162float(h3))};
    *(__nv_bfloat162*)(h + i) = ha; *(__nv_bfloat162*)(h + i + 2) = hb;
    *(__nv_bfloat162*)(l + i) = la; *(__nv_bfloat162*)(l + i + 2) = lb;
}

// transpose + split: in [R, Cc] row-major -> out [Cc, R] row-major (per batch)
__global__ void cvt_t(const float* __restrict__ x, __nv_bfloat16* __restrict__ h,
                      __nv_bfloat16* __restrict__ l, int R, int Cc, long sIn, long sOut)
{
    __shared__ float t[32][33];
    const float* src = x + (long)blockIdx.z * sIn;
    __nv_bfloat16* ho = h + (long)blockIdx.z * sOut;
    __nv_bfloat16* lo = l + (long)blockIdx.z * sOut;
    int r0 = blockIdx.y * 32, c0 = blockIdx.x * 32;
    int tx = threadIdx.x, ty = threadIdx.y;
    #pragma unroll
    for (int j = 0; j < 32; j += 8)
        t[ty + j][tx] = src[(long)(r0 + ty + j) * Cc + c0 + tx];
    __syncthreads();
    #pragma unroll
    for (int j = 0; j < 32; j += 8) {
        float v = t[tx][ty + j];
        __nv_bfloat16 hv = __float2bfloat16_rn(v);
        long o = (long)(c0 + ty + j) * R + r0 + tx;
        ho[o] = hv;
        lo[o] = __float2bfloat16_rn(v - __bfloat162float(hv));
    }
}

// ---------------- small SGEMM for the N=12 lr GEMM --------------------------
__global__ void lr_gemm(const float* __restrict__ A, const float* __restrict__ B,
                        float* __restrict__ C)
{
    __shared__ float bs[12][128];
    int row = blockIdx.x * 2 + (threadIdx.x >> 7);
    int tid = threadIdx.x & 127;
    float acc[12];
    #pragma unroll
    for (int c = 0; c < 12; ++c) acc[c] = 0.f;
    for (int k0 = 0; k0 < 2048; k0 += 128) {
        if (threadIdx.x < 128)
            #pragma unroll
            for (int c = 0; c < 12; ++c) bs[c][tid] = B[c * 2048 + k0 + tid];
        __syncthreads();
        float a = A[(long)row * 2048 + k0 + tid];
        #pragma unroll
        for (int c = 0; c < 12; ++c) acc[c] += a * bs[c][tid];
        __syncthreads();
    }
    __shared__ float red[2][12][4];
    #pragma unroll
    for (int c = 0; c < 12; ++c) {
        float v = acc[c];
        #pragma unroll
        for (int o = 16; o > 0; o >>= 1) v += __shfl_down_sync(0xffffffffu, v, o);
        if ((tid & 31) == 0) red[threadIdx.x >> 7][c][tid >> 5] = v;
    }
    __syncthreads();
    if (tid < 12) {
        int w = threadIdx.x >> 7;
        C[(long)row * 12 + tid] = red[w][tid][0] + red[w][tid][1] + red[w][tid][2] + red[w][tid][3];
    }
}

// ------------------------- block reduce (256 thr) ---------------------------
__device__ __forceinline__ float blockReduceSum(float v, float* sred)
{
    int lane = threadIdx.x & 31;
    #pragma unroll
    for (int o = 16; o > 0; o >>= 1) v += __shfl_down_sync(0xffffffffu, v, o);
    if (lane == 0) sred[threadIdx.x >> 5] = v;
    __syncthreads();
    if (threadIdx.x < 8) {
        float r = sred[threadIdx.x];
        #pragma unroll
        for (int o = 4; o > 0; o >>= 1) r += __shfl_down_sync(0xffu, r, o);
        if (threadIdx.x == 0) sred[0] = r;
    }
    __syncthreads();
    float out = sred[0];
    __syncthreads();
    return out;
}

// --------- prep: rmsnorm+rope (attn path) + silu/L2 (fast path) + lr --------
__global__ void prep_kernel(const float* __restrict__ qkv, const float* __restrict__ lrpre,
                            const float* __restrict__ qnw, const float* __restrict__ knw,
                            const float* __restrict__ qksc, const float* __restrict__ qkof,
                            const float* __restrict__ lrb, float base_lr_inv,
                            float* __restrict__ aq, float* __restrict__ ak,
                            float* __restrict__ fq, float* __restrict__ fk,
                            float* __restrict__ fv, float* __restrict__ lrout)
{
    __shared__ float s_q[2048];
    __shared__ float s_k[2048];
    __shared__ float sred[8];
    int row = blockIdx.x;
    int b = row >> 11, t = row & 2047;
    int tid = threadIdx.x;
    const float* qr = qkv + (long)row * 6144;
    const float* kr = qr + 2048;
    const float* vr = qr + 4096;

    float qv[8], kv[8], fqv[8], fkv[8], fvv[8];
    float sq = 0.f, sk = 0.f;
    float p2q[4] = {0, 0, 0, 0}, p2k[4] = {0, 0, 0, 0};
    #pragma unroll
    for (int j = 0; j < 8; ++j) {
        int i = j * 256 + tid;
        float q = qr[i], k = kr[i], v = vr[i];
        qv[j] = q; kv[j] = k;
        sq += q * q; sk += k * k;
        float fqe = (q / (1.f + expf(-q))) * qksc[i * 2 + 0] + qkof[i * 2 + 0];
        float fke = (k / (1.f + expf(-k))) * qksc[i * 2 + 1] + qkof[i * 2 + 1];
        fqv[j] = fqe; fkv[j] = fke; fvv[j] = v / (1.f + expf(-v));
        p2q[j >> 1] += fqe * fqe;
        p2k[j >> 1] += fke * fke;
    }
    float SQ = blockReduceSum(sq, sred);
    float SK = blockReduceSum(sk, sred);
    float G2Q[4], G2K[4];
    #pragma unroll
    for (int g = 0; g < 4; ++g) G2Q[g] = blockReduceSum(p2q[g], sred);
    #pragma unroll
    for (int g = 0; g < 4; ++g) G2K[g] = blockReduceSum(p2k[g], sred);
    float rq = rsqrtf(SQ * (1.f / 2048.f) + 1e-6f);
    float rk = rsqrtf(SK * (1.f / 2048.f) + 1e-6f);
    #pragma unroll
    for (int j = 0; j < 8; ++j) {
        int i = j * 256 + tid;
        s_q[i] = qv[j] * rq * qnw[i];
        s_k[i] = kv[j] * rk * knw[i];
        int g = j >> 1;
        long fb = (((long)(b * 4 + g)) * SEQ + t) * FDM + (i & 511);
        fq[fb] = fqv[j] / (sqrtf(G2Q[g]) + 1e-12f);
        fk[fb] = fkv[j] / (sqrtf(G2K[g]) + 1e-12f);
        fv[fb] = fvv[j];
    }
    __syncthreads();
    #pragma unroll
    for (int j = 0; j < 8; ++j) {
        int i = j * 256 + tid;
        int pos = i & 127;
        int fi = pos & 63;
        float invf = expf(-(float)fi * (logf(500000.f) / 64.f));
        float sn, cs;
        sincosf((float)t * invf, &sn, &cs);
        float oq, ok_;
        if (pos < 64) {
            oq  = s_q[i] * cs - s_q[i + 64] * sn;
            ok_ = s_k[i] * cs - s_k[i + 64] * sn;
        } else {
            oq  = s_q[i] * cs + s_q[i - 64] * sn;
            ok_ = s_k[i] * cs + s_k[i - 64] * sn;
        }
        aq[(long)row * DIMD + i] = oq;
        ak[(long)row * DIMD + i] = ok_;
    }
    if (tid < 12) {
        float x = lrpre[(long)row * 12 + tid] + lrb[tid] + base_lr_inv;
        lrout[(long)row * 12 + tid] = (x > 20.f) ? x : log1pf(expf(x));
    }
}

// ------------------- windowed flash attention (64q x 64k) -------------------
#define ASTR 140
#define ATTN_SMEM 88576
__global__ void attn_kernel(const float* __restrict__ Q, const float* __restrict__ K,
                            const float* __restrict__ QKV, float* __restrict__ O)
{
    extern __shared__ float sm[];
    float* Qs  = sm;
    float* KVs = sm + 64 * ASTR;
    float* Ss  = sm + 2 * 64 * ASTR;
    int q0 = blockIdx.x << 6;
    int h = blockIdx.y, b = blockIdx.z;
    int tid = threadIdx.x;
    int tq = tid >> 2, td = tid & 3;
    const float qscale = 0.088388347648318447f * 1.4426950408889634f;

    for (int e = tid; e < 8192; e += 256) {
        int r = e >> 7, c = e & 127;
        Qs[r * ASTR + c] = Q[((long)(b * SEQ + q0 + r)) * DIMD + h * 128 + c] * qscale;
    }
    float acc[32];
    #pragma unroll
    for (int d = 0; d < 32; ++d) acc[d] = 0.f;
    float m = -INFINITY, l = 0.f;

    int kt_hi = q0 >> 6;
    int kt_lo = (q0 >= 1024) ? ((q0 - 1023) >> 6) : 0;
    for (int kt = kt_lo; kt <= kt_hi; ++kt) {
        int j0 = kt << 6;
        __syncthreads();
        for (int e = tid; e < 8192; e += 256) {
            int r = e >> 7, c = e & 127;
            KVs[r * ASTR + c] = K[((long)(b * SEQ + j0 + r)) * DIMD + h * 128 + c];
        }
        __syncthreads();

        float sacc[16];
        #pragma unroll
        for (int jj = 0; jj < 16; ++jj) sacc[jj] = 0.f;
        #pragma unroll 4
        for (int k4 = 0; k4 < 32; ++k4) {
            float4 qv = *(const float4*)&Qs[tq * ASTR + k4 * 4];
            #pragma unroll
            for (int jj = 0; jj < 16; ++jj) {
                float4 kv = *(const float4*)&KVs[(jj * 4 + td) * ASTR + k4 * 4];
                sacc[jj] += qv.x * kv.x + qv.y * kv.y + qv.z * kv.z + qv.w * kv.w;
            }
        }
        int ig = q0 + tq;
        float tmax = -INFINITY;
        #pragma unroll
        for (int jj = 0; jj < 16; ++jj) {
            int jg = j0 + jj * 4 + td;
            bool ok = (jg <= ig) && (ig - jg < 1024);
            float sv = ok ? sacc[jj] : -INFINITY;
            Ss[tq * 66 + jj * 4 + td] = sv;
            tmax = fmaxf(tmax, sv);
        }
        tmax = fmaxf(tmax, __shfl_xor_sync(0xffffffffu, tmax, 1));
        tmax = fmaxf(tmax, __shfl_xor_sync(0xffffffffu, tmax, 2));

        __syncthreads();
        for (int e = tid; e < 8192; e += 256) {
            int r = e >> 7, c = e & 127;
            KVs[r * ASTR + c] = QKV[((long)(b * SEQ + j0 + r)) * 6144 + 4096 + h * 128 + c];
        }
        __syncthreads();

        float mt  = fmaxf(m, tmax);
        float mte = (mt > -INFINITY) ? mt : 0.f;
        float corr = exp2f(m - mte);
        l *= corr;
        #pragma unroll
        for (int d = 0; d < 32; ++d) acc[d] *= corr;
        float lpart = 0.f;
        #pragma unroll
        for (int jj = 0; jj < 16; ++jj) {
            float p = exp2f(Ss[tq * 66 + jj * 4 + td] - mte);
            Ss[tq * 66 + jj * 4 + td] = p;
            lpart += p;
        }
        lpart += __shfl_xor_sync(0xffffffffu, lpart, 1);
        lpart += __shfl_xor_sync(0xffffffffu, lpart, 2);
        l += lpart;
        __syncwarp();
        #pragma unroll 2
        for (int jj = 0; jj < 64; ++jj) {
            float pj = Ss[tq * 66 + jj];
            const float* vr = &KVs[jj * ASTR + td * 4];
            #pragma unroll
            for (int d4 = 0; d4 < 8; ++d4) {
                float4 vv = *(const float4*)&vr[d4 * 16];
                acc[d4 * 4 + 0] = fmaf(pj, vv.x, acc[d4 * 4 + 0]);
                acc[d4 * 4 + 1] = fmaf(pj, vv.y, acc[d4 * 4 + 1]);
                acc[d4 * 4 + 2] = fmaf(pj, vv.z, acc[d4 * 4 + 2]);
                acc[d4 * 4 + 3] = fmaf(pj, vv.w, acc[d4 * 4 + 3]);
            }
        }
        m = mt;
        __syncwarp();
    }
    float rl = 1.f / l;
    float* orow = &O[((long)(b * SEQ + q0 + tq)) * DIMD + h * 128 + td * 4];
    #pragma unroll
    for (int d4 = 0; d4 < 8; ++d4) {
        float4 o;
        o.x = acc[d4 * 4 + 0] * rl; o.y = acc[d4 * 4 + 1] * rl;
        o.z = acc[d4 * 4 + 2] * rl; o.w = acc[d4 * 4 + 3] * rl;
        *(float4*)&orow[d4 * 16] = o;
    }
}

// --------------------------- TTT helper kernels -----------------------------
// fill combined W02 [8][1024][512] (rows 0-511=W0, 512-1023=W2) and W1 copy
__global__ void copyw(const float* __restrict__ w0, const float* __restrict__ w1,
                      const float* __restrict__ w2,
                      float* __restrict__ o02, float* __restrict__ o1)
{
    long idx = (long)blockIdx.x * 256 + threadIdx.x;   // 8*1024*512 = 4M
    int col = idx & 511;
    int row = (idx >> 9) & 1023;
    int h = (idx >> 19) & 3;
    long src = (long)h * 262144 + (long)(row & 511) * 512 + col;
    o02[idx] = (row < 512) ? w0[src] : w2[src];
    if (idx < (long)2 * 1024 * 1024)
        o1[idx] = w1[idx & ((long)4 * 262144 - 1)];
}

__global__ void elem2(const float* __restrict__ fv, const float* __restrict__ lr,
                      const float* __restrict__ gh, float* __restrict__ dgp,
                      float* __restrict__ dh, float* __restrict__ hid, int ck0)
{
    long idx = (long)blockIdx.x * 256 + threadIdx.x;   // 8*1024*512
    int col = idx & 511;
    long tt = idx >> 9;
    int c = tt & 1023, bh = tt >> 10;
    int b = bh >> 2, h = bh & 3;
    long row = (long)b * SEQ + ck0 + c;
    float l0 = lr[row * 12 + h], l1 = lr[row * 12 + 4 + h], l2 = lr[row * 12 + 8 + h];
    long gi = (long)bh * 1048576 + (long)c * 1024 + col;
    float g = gh[gi], hp = gh[gi + 512], d = dh[idx];
    float sig = 1.f / (1.f + expf(-g));
    float sg = g * sig;
    hid[idx] = sg * hp;
    float v = fv[((long)bh * SEQ + ck0 + c) * FDM + col];
    dgp[gi]       = d * hp * (sig * (1.f + g * (1.f - sig))) * l0;
    dgp[gi + 512] = d * sg * l2;
    dh[idx]       = v * l1;
}

__global__ void elem3(const float* __restrict__ gh, float* __restrict__ hid)
{
    long idx = (long)blockIdx.x * 256 + threadIdx.x;   // 8*1024*512
    int col = idx & 511;
    long tt = idx >> 9;
    int c = tt & 1023, bh = tt >> 10;
    long gi = (long)bh * 1048576 + (long)c * 1024 + col;
    float g = gh[gi];
    hid[idx] = (g / (1.f + expf(-g))) * gh[gi + 512];
}

// -------------------- ttt rmsnorm + add attention result --------------------
__global__ void post_kernel(const float* __restrict__ ttt, const float* __restrict__ tw,
                            float* __restrict__ sum)
{
    __shared__ float sr[4];
    int fh = blockIdx.x, row = blockIdx.y;
    int b = row >> 11, t = row & 2047;
    int bh = b * 4 + fh;
    const float* src = ttt + ((long)bh * SEQ + t) * FDM;
    int tid = threadIdx.x;
    float v[4], ss = 0.f;
    #pragma unroll
    for (int j = 0; j < 4; ++j) { v[j] = src[tid + 128 * j]; ss += v[j] * v[j]; }
    #pragma unroll
    for (int o = 16; o > 0; o >>= 1) ss += __shfl_down_sync(0xffffffffu, ss, o);
    if ((tid & 31) == 0) sr[tid >> 5] = ss;
    __syncthreads();
    float tot = sr[0] + sr[1] + sr[2] + sr[3];
    float r = rsqrtf(tot * (1.f / 512.f) + 1e-6f);
    #pragma unroll
    for (int j = 0; j < 4; ++j) {
        int i = tid + 128 * j;
        sum[(long)row * 2048 + fh * 512 + i] += v[j] * r * tw[i];
    }
}

// --------------------------------- launch -----------------------------------
#define GSYM(p, s) cudaGetSymbolAddress((void**)&(p), s)

extern "C" void kernel_launch(void* const* d_in, const int* in_sizes, int n_in,
                              void* d_out, int out_size)
{
    const float* hidden = (const float*)d_in[0];
    const float* Wqkv   = (const float*)d_in[1];
    const float* Wo     = (const float*)d_in[2];
    const float* qnw    = (const float*)d_in[3];
    const float* knw    = (const float*)d_in[4];
    const float* w0     = (const float*)d_in[5];
    const float* w1     = (const float*)d_in[6];
    const float* w2     = (const float*)d_in[7];
    const float* lrw    = (const float*)d_in[8];
    const float* lrb    = (const float*)d_in[9];
    const float* qksc   = (const float*)d_in[10];
    const float* qkof   = (const float*)d_in[11];
    const float* tttw   = (const float*)d_in[12];
    float* out = (float*)d_out;

    float *qkv, *lrpre, *lr, *aq, *ak, *fq, *fk, *fv, *pw02, *pw1;
    float *gh, *dgp, *dh, *hid, *ttt, *sum;
    GSYM(qkv, g_qkv);   GSYM(lrpre, g_lrpre); GSYM(lr, g_lr);
    GSYM(aq, g_aq);     GSYM(ak, g_ak);
    GSYM(fq, g_fq);     GSYM(fk, g_fk);       GSYM(fv, g_fv);
    GSYM(pw02, g_w02);  GSYM(pw1, g_w1);
    GSYM(gh, g_gh);     GSYM(dgp, g_dgp);     GSYM(dh, g_dh);
    GSYM(hid, g_hid);   GSYM(ttt, g_ttt);     GSYM(sum, g_sum);

    __nv_bfloat16 *hxh,*hxl,*wqh,*wql,*woh,*wol,*fqh,*fql,*fkh,*fkl,*fvh,*fvl;
    __nv_bfloat16 *w02h,*w02l,*w1h,*w1l,*w1th,*w1tl;
    __nv_bfloat16 *dgth,*dgtl,*vlh,*vll,*hth,*htl,*fkth,*fktl,*hnh,*hnl,*smh,*sml;
    GSYM(hxh, g_hx_h); GSYM(hxl, g_hx_l); GSYM(wqh, g_wq_h); GSYM(wql, g_wq_l);
    GSYM(woh, g_wo_h); GSYM(wol, g_wo_l);
    GSYM(fqh, g_fq_h); GSYM(fql, g_fq_l); GSYM(fkh, g_fk_h); GSYM(fkl, g_fk_l);
    GSYM(fvh, g_fv_h); GSYM(fvl, g_fv_l);
    GSYM(w02h, g_w02_h); GSYM(w02l, g_w02_l);
    GSYM(w1h, g_w1_h); GSYM(w1l, g_w1_l); GSYM(w1th, g_w1t_h); GSYM(w1tl, g_w1t_l);
    GSYM(dgth, g_dgpt_h); GSYM(dgtl, g_dgpt_l);
    GSYM(vlh, g_vl_h); GSYM(vll, g_vl_l); GSYM(hth, g_ht_h); GSYM(htl, g_ht_l);
    GSYM(fkth, g_fkt_h); GSYM(fktl, g_fkt_l);
    GSYM(hnh, g_hn_h); GSYM(hnl, g_hn_l); GSYM(smh, g_sm_h); GSYM(sml, g_sm_l);

    cudaFuncSetAttribute(mma_gemm, cudaFuncAttributeMaxDynamicSharedMemorySize, 2 * STG);
    cudaFuncSetAttribute(attn_kernel, cudaFuncAttributeMaxDynamicSharedMemorySize, ATTN_SMEM);

    #define MMAG(Ah,Al,Bh,Bl,C,M,N,K,sA,sB,sC,acc,bat) \
        mma_gemm<<<dim3((N)/128,(M)/128,(bat)),256,2*STG>>>(Ah,Al,Bh,Bl,C,M,N,K,sA,sB,sC,acc)

    // ---- inputs -> bf16 hi/lo ----
    cvt_hl<<<8192, 256>>>(hidden, hxh, hxl, (long)4096 * 2048);
    cvt_hl<<<12288, 256>>>(Wqkv, wqh, wql, (long)6144 * 2048);
    cvt_hl<<<4096, 256>>>(Wo, woh, wol, (long)2048 * 2048);

    // qkv = hidden @ Wqkv^T ; lrpre = hidden @ lr_w^T
    MMAG(hxh, hxl, wqh, wql, qkv, 4096, 6144, 2048, 0, 0, 0, 0, 1);
    lr_gemm<<<2048, 256>>>(hidden, lrw, lrpre);

    float base = (float)(0.001 + log(-expm1(-0.001)));
    prep_kernel<<<4096, 256>>>(qkv, lrpre, qnw, knw, qksc, qkof, lrb, base,
                               aq, ak, fq, fk, fv, lr);
    attn_kernel<<<dim3(32, 16, 2), 256, ATTN_SMEM>>>(aq, ak, qkv, sum);

    cvt_hl<<<8192, 256>>>(fq, fqh, fql, (long)8 * SEQ * FDM);
    cvt_hl<<<8192, 256>>>(fk, fkh, fkl, (long)8 * SEQ * FDM);
    cvt_hl<<<8192, 256>>>(fv, fvh, fvl, (long)8 * SEQ * FDM);

    copyw<<<16384, 256>>>(w0, w1, w2, pw02, pw1);
    cvt_hl<<<4096, 256>>>(pw02, w02h, w02l, (long)8 * 1024 * FDM);
    cvt_t<<<dim3(16, 16, 8), dim3(32, 8)>>>(pw1, w1th, w1tl, 512, 512, 262144, 262144);

    long sSeq = (long)SEQ * FDM;     // 1048576
    long sChk = (long)1024 * FDM;    // 524288
    long sW   = (long)FDM * FDM;     // 262144
    long sW02 = (long)1024 * FDM;    // 524288
    long sGH  = (long)1024 * 1024;   // 1048576
    for (int ck = 0; ck < 2; ++ck) {
        int ck0 = ck * 1024;
        // forward with old weights: gh = K @ W02^T (gate|hpre), dh = V @ W1
        MMAG(fkh + (long)ck0 * FDM, fkl + (long)ck0 * FDM, w02h, w02l, gh,
             1024, 1024, 512, sSeq, sW02, sGH, 0, 8);
        MMAG(fvh + (long)ck0 * FDM, fvl + (long)ck0 * FDM, w1th, w1tl, dh,
             1024, 512, 512, sSeq, sW, sChk, 0, 8);
        elem2<<<16384, 256>>>(fv, lr, gh, dgp, dh, hid, ck0);
        // transposed bf16 operands for updates
        cvt_t<<<dim3(32, 32, 8), dim3(32, 8)>>>(dgp, dgth, dgtl, 1024, 1024, sGH, sGH);
        cvt_t<<<dim3(16, 32, 8), dim3(32, 8)>>>(dh, vlh, vll, 1024, 512, sChk, sChk);
        cvt_t<<<dim3(16, 32, 8), dim3(32, 8)>>>(hid, hth, htl, 1024, 512, sChk, sChk);
        cvt_t<<<dim3(16, 32, 8), dim3(32, 8)>>>(fk + (long)ck0 * FDM, fkth, fktl,
                                                1024, 512, sSeq, sChk);
        // weight updates (fp32 accumulate): W02 += dgp^T @ K ; W1 += vl^T @ hid
        MMAG(dgth, dgtl, fkth, fktl, pw02, 1024, 512, 1024, sGH, sChk, sW02, 1, 8);
        MMAG(vlh, vll, hth, htl, pw1, 512, 512, 1024, sChk, sChk, sW, 1, 8);
        // re-convert updated weights
        cvt_hl<<<4096, 256>>>(pw02, w02h, w02l, (long)8 * 1024 * FDM);
        cvt_hl<<<2048, 256>>>(pw1, w1h, w1l, (long)8 * FDM * FDM);
        cvt_t<<<dim3(16, 16, 8), dim3(32, 8)>>>(pw1, w1th, w1tl, 512, 512, 262144, 262144);
        // query pass with updated weights
        MMAG(fqh + (long)ck0 * FDM, fql + (long)ck0 * FDM, w02h, w02l, gh,
             1024, 1024, 512, sSeq, sW02, sGH, 0, 8);
        elem3<<<16384, 256>>>(gh, hid);
        cvt_hl<<<4096, 256>>>(hid, hnh, hnl, (long)8 * 1024 * FDM);
        MMAG(hnh, hnl, w1h, w1l, ttt + (long)ck0 * FDM,
             1024, 512, 512, sChk, sW, sSeq, 0, 8);
    }

    post_kernel<<<dim3(4, 4096), 128>>>(ttt, tttw, sum);
    cvt_hl<<<8192, 256>>>(sum, smh, sml, (long)4096 * 2048);
    // out = (attn + ttt_norm) @ Wo^T
    MMAG(smh, sml, woh, wol, out, 4096, 2048, 2048, 0, 0, 0, 0, 1);
    #undef MMAG
}

// round 8
// speedup vs baseline: 3.2920x; 1.0197x over previous
#include <cuda_runtime.h>
#include <cuda_bf16.h>
#include <cstdint>
#include <math.h>

#define SEQ 2048
#define DIMD 2048
#define FDM 512

// ------------------------- fp32 scratch (device globals) --------------------
__device__ float g_qkv [(size_t)4096 * 6144];
__device__ float g_lrpre[(size_t)4096 * 12];
__device__ float g_lr  [(size_t)4096 * 12];
__device__ float g_aq  [(size_t)4096 * 2048];
__device__ float g_ak  [(size_t)4096 * 2048];
__device__ float g_fv  [(size_t)8 * SEQ * FDM];
__device__ float g_w02 [(size_t)8 * 1024 * FDM];   // rows 0-511 = W0, 512-1023 = W2
__device__ float g_w1  [(size_t)8 * FDM * FDM];
__device__ float g_gh  [(size_t)8 * 1024 * 1024];  // gate | hpre combined
__device__ float g_dh  [(size_t)8 * 1024 * FDM];
__device__ float g_ttt [(size_t)8 * SEQ * FDM];
__device__ float g_sum [(size_t)4096 * 2048];

// ------------------------- bf16 hi/lo scratch -------------------------------
__device__ __nv_bfloat16 g_hx_h[(size_t)4096*2048],  g_hx_l[(size_t)4096*2048];
__device__ __nv_bfloat16 g_wq_h[(size_t)6144*2048],  g_wq_l[(size_t)6144*2048];
__device__ __nv_bfloat16 g_wo_h[(size_t)2048*2048],  g_wo_l[(size_t)2048*2048];
__device__ __nv_bfloat16 g_fq_h[(size_t)8*SEQ*FDM],  g_fq_l[(size_t)8*SEQ*FDM];
__device__ __nv_bfloat16 g_fk_h[(size_t)8*SEQ*FDM],  g_fk_l[(size_t)8*SEQ*FDM];
__device__ __nv_bfloat16 g_fv_h[(size_t)8*SEQ*FDM],  g_fv_l[(size_t)8*SEQ*FDM];
__device__ __nv_bfloat16 g_w02_h[(size_t)8*1024*FDM], g_w02_l[(size_t)8*1024*FDM];
__device__ __nv_bfloat16 g_w1_h[(size_t)8*FDM*FDM],  g_w1_l[(size_t)8*FDM*FDM];
__device__ __nv_bfloat16 g_dgp_h[(size_t)8*1024*1024], g_dgp_l[(size_t)8*1024*1024];
__device__ __nv_bfloat16 g_vl_h[(size_t)8*1024*FDM], g_vl_l[(size_t)8*1024*FDM];
__device__ __nv_bfloat16 g_ht_h[(size_t)8*1024*FDM], g_ht_l[(size_t)8*1024*FDM];
__device__ __nv_bfloat16 g_hn_h[(size_t)8*1024*FDM], g_hn_l[(size_t)8*1024*FDM];
__device__ __nv_bfloat16 g_sm_h[(size_t)4096*2048],  g_sm_l[(size_t)4096*2048];

// ------------------------------ helpers -------------------------------------
__device__ __forceinline__ uint32_t smem_u32(const void* p) {
    uint32_t a;
    asm("{ .reg .u64 t; cvta.to.shared.u64 t, %1; cvt.u32.u64 %0, t; }" : "=r"(a) : "l"(p));
    return a;
}
__device__ __forceinline__ void cpa16(uint32_t s, const void* g) {
    asm volatile("cp.async.cg.shared.global [%0], [%1], 16;" :: "r"(s), "l"(g));
}
#define CP_COMMIT() asm volatile("cp.async.commit_group;" ::: "memory")
#define MMA16816(d, a, b0, b1) \
    asm volatile("mma.sync.aligned.m16n8k16.row.col.f32.bf16.bf16.f32 " \
        "{%0,%1,%2,%3}, {%4,%5,%6,%7}, {%8,%9}, {%0,%1,%2,%3};" \
        : "+f"((d)[0]), "+f"((d)[1]), "+f"((d)[2]), "+f"((d)[3]) \
        : "r"((a)[0]), "r"((a)[1]), "r"((a)[2]), "r"((a)[3]), "r"(b0), "r"(b1))
__device__ __forceinline__ void ldmx4(uint32_t* r, uint32_t addr) {
    asm volatile("ldmatrix.sync.aligned.m8n8.x4.shared.b16 {%0,%1,%2,%3}, [%4];"
        : "=r"(r[0]), "=r"(r[1]), "=r"(r[2]), "=r"(r[3]) : "r"(addr));
}
__device__ __forceinline__ void ldmx4t(uint32_t* r, uint32_t addr) {
    asm volatile("ldmatrix.sync.aligned.m8n8.x4.trans.shared.b16 {%0,%1,%2,%3}, [%4];"
        : "=r"(r[0]), "=r"(r[1]), "=r"(r[2]), "=r"(r[3]) : "r"(addr));
}
__device__ __forceinline__ void split_w(float v, __nv_bfloat16* h, __nv_bfloat16* l, long i) {
    __nv_bfloat16 hv = __float2bfloat16_rn(v);
    h[i] = hv;
    l[i] = __float2bfloat16_rn(v - __bfloat162float(hv));
}

// -------------------- mma.sync batched GEMM, bf16x3 split -------------------
// AT=0: A stored [M,K] (ld=lda along K).  AT=1: A stored [K,M] (ld=lda along M).
// BT=0: B stored [N,K].                   BT=1: B stored [K,N].
// C[M,N] (+)= sum_k Aop[m,k]*Bop[n,k]. SPLIT also writes bf16 hi/lo of C.
template<int AT, int BT, bool ACC, bool SPLIT>
__global__ void __launch_bounds__(256, 2)
mma_gemm(const __nv_bfloat16* __restrict__ Ah, const __nv_bfloat16* __restrict__ Al,
         const __nv_bfloat16* __restrict__ Bh, const __nv_bfloat16* __restrict__ Bl,
         float* __restrict__ C, __nv_bfloat16* __restrict__ Ch,
         __nv_bfloat16* __restrict__ Cl, int M, int N, int K,
         int lda, int ldb, long sA, long sB, long sC)
{
    constexpr int SA = AT ? 8704 : 10240;
    constexpr int SB = BT ? 8704 : 10240;
    constexpr int STAGE = 2 * (SA + SB);
    extern __shared__ char smem[];
    uint32_t sb = smem_u32(smem);
    int tid = threadIdx.x, lane = tid & 31, wid = tid >> 5;
    int wm = wid >> 2, wn = wid & 3;
    long zb = blockIdx.z;
    const __nv_bfloat16* ah = Ah + zb * sA;
    const __nv_bfloat16* al = Al + zb * sA;
    const __nv_bfloat16* bh = Bh + zb * sB;
    const __nv_bfloat16* bl = Bl + zb * sB;
    int m0 = blockIdx.y << 7, n0 = blockIdx.x << 7;

    float acc[4][4][4];
    #pragma unroll
    for (int i = 0; i < 4; ++i)
        #pragma unroll
        for (int j = 0; j < 4; ++j)
            #pragma unroll
            for (int q = 0; q < 4; ++q) acc[i][j][q] = 0.f;

    // lane constants
    uint32_t a_row = (lane & 7) + ((lane >> 3) & 1) * 8;   // k-major A
    uint32_t a_kb  = ((lane >> 4) & 1) * 16;
    uint32_t a_kr  = (lane & 7) + ((lane >> 4) & 1) * 8;   // mn-major A (trans)
    uint32_t a_mo  = ((lane >> 3) & 1) * 8;
    uint32_t b_row = (lane & 7) + ((lane >> 4) & 1) * 8;   // k-major B
    uint32_t b_kb  = ((lane >> 3) & 1) * 16;
    uint32_t b_kr  = (lane & 7) + ((lane >> 3) & 1) * 8;   // mn-major B (trans)
    uint32_t b_no  = ((lane >> 4) & 1) * 8;

    // ---- issue lambda ----
    auto issue = [&](int buf, int k0) {
        uint32_t st = sb + buf * STAGE;
        #pragma unroll
        for (int j = 0; j < 2; ++j) {
            int u = tid + j * 256;
            uint32_t soA; long gA;
            if (AT == 0) { int r = u >> 2, s = u & 3; soA = r * 80 + s * 16;
                           gA = (long)(m0 + r) * lda + k0 + s * 8; }
            else         { int r = u >> 4, s = u & 15; soA = r * 272 + s * 16;
                           gA = (long)(k0 + r) * lda + m0 + s * 8; }
            cpa16(st + soA,      ah + gA);
            cpa16(st + SA + soA, al + gA);
            uint32_t soB; long gB;
            if (BT == 0) { int r = u >> 2, s = u & 3; soB = r * 80 + s * 16;
                           gB = (long)(n0 + r) * ldb + k0 + s * 8; }
            else         { int r = u >> 4, s = u & 15; soB = r * 272 + s * 16;
                           gB = (long)(k0 + r) * ldb + n0 + s * 8; }
            cpa16(st + 2 * SA + soB,      bh + gB);
            cpa16(st + 2 * SA + SB + soB, bl + gB);
        }
        CP_COMMIT();
    };

    const int n = K >> 5;
    issue(0, 0);
    int buf = 0;
    for (int i = 0; i < n; ++i) {
        if (i + 1 < n) {
            issue(buf ^ 1, (i + 1) * 32);
            asm volatile("cp.async.wait_group 1;" ::: "memory");
        } else {
            asm volatile("cp.async.wait_group 0;" ::: "memory");
        }
        __syncthreads();
        uint32_t st = sb + buf * STAGE;
        uint32_t stB = st + 2 * SA;
        #pragma unroll
        for (int kk = 0; kk < 32; kk += 16) {
            uint32_t ahf[4][4], alf[4][4];
            #pragma unroll
            for (int mt = 0; mt < 4; ++mt) {
                if (AT == 0) {
                    uint32_t ra = st + (wm * 64 + mt * 16 + a_row) * 80 + kk * 2 + a_kb;
                    ldmx4(ahf[mt], ra);
                    ldmx4(alf[mt], ra + SA);
                } else {
                    uint32_t ra = st + (kk + a_kr) * 272 + (wm * 64 + mt * 16 + a_mo) * 2;
                    ldmx4t(ahf[mt], ra);
                    ldmx4t(alf[mt], ra + SA);
                }
            }
            uint32_t bhf[2][4], blf[2][4];
            #pragma unroll
            for (int p = 0; p < 2; ++p) {
                if (BT == 0) {
                    uint32_t rb = stB + (wn * 32 + p * 16 + b_row) * 80 + kk * 2 + b_kb;
                    ldmx4(bhf[p], rb);
                    ldmx4(blf[p], rb + SB);
                } else {
                    uint32_t rb = stB + (kk + b_kr) * 272 + (wn * 32 + p * 16 + b_no) * 2;
                    ldmx4t(bhf[p], rb);
                    ldmx4t(blf[p], rb + SB);
                }
            }
            #pragma unroll
            for (int nt = 0; nt < 4; ++nt) {
                uint32_t bh0 = bhf[nt >> 1][(nt & 1) * 2 + 0];
                uint32_t bh1 = bhf[nt >> 1][(nt & 1) * 2 + 1];
                uint32_t bl0 = blf[nt >> 1][(nt & 1) * 2 + 0];
                uint32_t bl1 = blf[nt >> 1][(nt & 1) * 2 + 1];
                #pragma unroll
                for (int mt = 0; mt < 4; ++mt) {
                    MMA16816(acc[mt][nt], ahf[mt], bh0, bh1);
                    MMA16816(acc[mt][nt], ahf[mt], bl0, bl1);
                    MMA16816(acc[mt][nt], alf[mt], bh0, bh1);
                }
            }
        }
        __syncthreads();
        buf ^= 1;
    }
    // epilogue
    float* c = C + zb * sC;
    __nv_bfloat16* ch = SPLIT ? Ch + zb * sC : nullptr;
    __nv_bfloat16* cl = SPLIT ? Cl + zb * sC : nullptr;
    #pragma unroll
    for (int mt = 0; mt < 4; ++mt) {
        #pragma unroll
        for (int nt = 0; nt < 4; ++nt) {
            long r0 = m0 + wm * 64 + mt * 16 + (lane >> 2);
            int  cc = n0 + wn * 32 + nt * 8 + (lane & 3) * 2;
            long o0 = r0 * (long)N + cc;
            long o1 = (r0 + 8) * (long)N + cc;
            float v00 = acc[mt][nt][0], v01 = acc[mt][nt][1];
            float v10 = acc[mt][nt][2], v11 = acc[mt][nt][3];
            if (ACC) {
                float2 t0 = *(float2*)(c + o0), t1 = *(float2*)(c + o1);
                v00 += t0.x; v01 += t0.y; v10 += t1.x; v11 += t1.y;
            }
            *(float2*)(c + o0) = make_float2(v00, v01);
            *(float2*)(c + o1) = make_float2(v10, v11);
            if (SPLIT) {
                split_w(v00, ch, cl, o0); split_w(v01, ch, cl, o0 + 1);
                split_w(v10, ch, cl, o1); split_w(v11, ch, cl, o1 + 1);
            }
        }
    }
}

// ------------------------ conversion kernel ---------------------------------
__global__ void cvt_hl(const float* __restrict__ x, __nv_bfloat16* __restrict__ h,
                       __nv_bfloat16* __restrict__ l, long n)
{
    long i = ((long)blockIdx.x * 256 + threadIdx.x) * 4;
    if (i >= n) return;
    float4 v = *(const float4*)(x + i);
    split_w(v.x, h, l, i);     split_w(v.y, h, l, i + 1);
    split_w(v.z, h, l, i + 2); split_w(v.w, h, l, i + 3);
}

// ---------------- small SGEMM for the N=12 lr GEMM --------------------------
__global__ void lr_gemm(const float* __restrict__ A, const float* __restrict__ B,
                        float* __restrict__ C)
{
    __shared__ float bs[12][128];
    int row = blockIdx.x * 2 + (threadIdx.x >> 7);
    int tid = threadIdx.x & 127;
    float acc[12];
    #pragma unroll
    for (int c = 0; c < 12; ++c) acc[c] = 0.f;
    for (int k0 = 0; k0 < 2048; k0 += 128) {
        if (threadIdx.x < 128)
            #pragma unroll
            for (int c = 0; c < 12; ++c) bs[c][tid] = B[c * 2048 + k0 + tid];
        __syncthreads();
        float a = A[(long)row * 2048 + k0 + tid];
        #pragma unroll
        for (int c = 0; c < 12; ++c) acc[c] += a * bs[c][tid];
        __syncthreads();
    }
    __shared__ float red[2][12][4];
    #pragma unroll
    for (int c = 0; c < 12; ++c) {
        float v = acc[c];
        #pragma unroll
        for (int o = 16; o > 0; o >>= 1) v += __shfl_down_sync(0xffffffffu, v, o);
        if ((tid & 31) == 0) red[threadIdx.x >> 7][c][tid >> 5] = v;
    }
    __syncthreads();
    if (tid < 12) {
        int w = threadIdx.x >> 7;
        C[(long)row * 12 + tid] = red[w][tid][0] + red[w][tid][1] + red[w][tid][2] + red[w][tid][3];
    }
}

// ------------------------- block reduce (256 thr) ---------------------------
__device__ __forceinline__ float blockReduceSum(float v, float* sred)
{
    int lane = threadIdx.x & 31;
    #pragma unroll
    for (int o = 16; o > 0; o >>= 1) v += __shfl_down_sync(0xffffffffu, v, o);
    if (lane == 0) sred[threadIdx.x >> 5] = v;
    __syncthreads();
    if (threadIdx.x < 8) {
        float r = sred[threadIdx.x];
        #pragma unroll
        for (int o = 4; o > 0; o >>= 1) r += __shfl_down_sync(0xffu, r, o);
        if (threadIdx.x == 0) sred[0] = r;
    }
    __syncthreads();
    float out = sred[0];
    __syncthreads();
    return out;
}

// --------- prep: rmsnorm+rope (attn path) + silu/L2 (fast path) + lr --------
__global__ void prep_kernel(const float* __restrict__ qkv, const float* __restrict__ lrpre,
                            const float* __restrict__ qnw, const float* __restrict__ knw,
                            const float* __restrict__ qksc, const float* __restrict__ qkof,
                            const float* __restrict__ lrb, float base_lr_inv,
                            float* __restrict__ aq, float* __restrict__ ak,
                            __nv_bfloat16* __restrict__ fqh, __nv_bfloat16* __restrict__ fql,
                            __nv_bfloat16* __restrict__ fkh, __nv_bfloat16* __restrict__ fkl,
                            __nv_bfloat16* __restrict__ fvh, __nv_bfloat16* __restrict__ fvl,
                            float* __restrict__ fv, float* __restrict__ lrout)
{
    __shared__ float s_q[2048];
    __shared__ float s_k[2048];
    __shared__ float sred[8];
    int row = blockIdx.x;
    int b = row >> 11, t = row & 2047;
    int tid = threadIdx.x;
    const float* qr = qkv + (long)row * 6144;
    const float* kr = qr + 2048;
    const float* vr = qr + 4096;

    float qv[8], kv[8], fqv[8], fkv[8], fvv[8];
    float sq = 0.f, sk = 0.f;
    float p2q[4] = {0, 0, 0, 0}, p2k[4] = {0, 0, 0, 0};
    #pragma unroll
    for (int j = 0; j < 8; ++j) {
        int i = j * 256 + tid;
        float q = qr[i], k = kr[i], v = vr[i];
        qv[j] = q; kv[j] = k;
        sq += q * q; sk += k * k;
        float fqe = (q / (1.f + expf(-q))) * qksc[i * 2 + 0] + qkof[i * 2 + 0];
        float fke = (k / (1.f + expf(-k))) * qksc[i * 2 + 1] + qkof[i * 2 + 1];
        fqv[j] = fqe; fkv[j] = fke; fvv[j] = v / (1.f + expf(-v));
        p2q[j >> 1] += fqe * fqe;
        p2k[j >> 1] += fke * fke;
    }
    float SQ = blockReduceSum(sq, sred);
    float SK = blockReduceSum(sk, sred);
    float G2Q[4], G2K[4];
    #pragma unroll
    for (int g = 0; g < 4; ++g) G2Q[g] = blockReduceSum(p2q[g], sred);
    #pragma unroll
    for (int g = 0; g < 4; ++g) G2K[g] = blockReduceSum(p2k[g], sred);
    float rq = rsqrtf(SQ * (1.f / 2048.f) + 1e-6f);
    float rk = rsqrtf(SK * (1.f / 2048.f) + 1e-6f);
    #pragma unroll
    for (int j = 0; j < 8; ++j) {
        int i = j * 256 + tid;
        s_q[i] = qv[j] * rq * qnw[i];
        s_k[i] = kv[j] * rk * knw[i];
        int g = j >> 1;
        long fb = (((long)(b * 4 + g)) * SEQ + t) * FDM + (i & 511);
        float fqn = fqv[j] / (sqrtf(G2Q[g]) + 1e-12f);
        float fkn = fkv[j] / (sqrtf(G2K[g]) + 1e-12f);
        split_w(fqn, fqh, fql, fb);
        split_w(fkn, fkh, fkl, fb);
        split_w(fvv[j], fvh, fvl, fb);
        fv[fb] = fvv[j];
    }
    __syncthreads();
    #pragma unroll
    for (int j = 0; j < 8; ++j) {
        int i = j * 256 + tid;
        int pos = i & 127;
        int fi = pos & 63;
        float invf = expf(-(float)fi * (logf(500000.f) / 64.f));
        float sn, cs;
        sincosf((float)t * invf, &sn, &cs);
        float oq, ok_;
        if (pos < 64) {
            oq  = s_q[i] * cs - s_q[i + 64] * sn;
            ok_ = s_k[i] * cs - s_k[i + 64] * sn;
        } else {
            oq  = s_q[i] * cs + s_q[i - 64] * sn;
            ok_ = s_k[i] * cs + s_k[i - 64] * sn;
        }
        aq[(long)row * DIMD + i] = oq;
        ak[(long)row * DIMD + i] = ok_;
    }
    if (tid < 12) {
        float x = lrpre[(long)row * 12 + tid] + lrb[tid] + base_lr_inv;
        lrout[(long)row * 12 + tid] = (x > 20.f) ? x : log1pf(expf(x));
    }
}

// ------------------- windowed flash attention (64q x 64k) -------------------
#define ASTR 140
#define ATTN_SMEM 88576
__global__ void attn_kernel(const float* __restrict__ Q, const float* __restrict__ K,
                            const float* __restrict__ QKV, float* __restrict__ O)
{
    extern __shared__ float sm[];
    float* Qs  = sm;
    float* KVs = sm + 64 * ASTR;
    float* Ss  = sm + 2 * 64 * ASTR;
    int q0 = blockIdx.x << 6;
    int h = blockIdx.y, b = blockIdx.z;
    int tid = threadIdx.x;
    int tq = tid >> 2, td = tid & 3;
    const float qscale = 0.088388347648318447f * 1.4426950408889634f;

    for (int e = tid; e < 8192; e += 256) {
        int r = e >> 7, c = e & 127;
        Qs[r * ASTR + c] = Q[((long)(b * SEQ + q0 + r)) * DIMD + h * 128 + c] * qscale;
    }
    float acc[32];
    #pragma unroll
    for (int d = 0; d < 32; ++d) acc[d] = 0.f;
    float m = -INFINITY, l = 0.f;

    int kt_hi = q0 >> 6;
    int kt_lo = (q0 >= 1024) ? ((q0 - 1023) >> 6) : 0;
    for (int kt = kt_lo; kt <= kt_hi; ++kt) {
        int j0 = kt << 6;
        __syncthreads();
        for (int e = tid; e < 8192; e += 256) {
            int r = e >> 7, c = e & 127;
            KVs[r * ASTR + c] = K[((long)(b * SEQ + j0 + r)) * DIMD + h * 128 + c];
        }
        __syncthreads();

        float sacc[16];
        #pragma unroll
        for (int jj = 0; jj < 16; ++jj) sacc[jj] = 0.f;
        #pragma unroll 4
        for (int k4 = 0; k4 < 32; ++k4) {
            float4 qv = *(const float4*)&Qs[tq * ASTR + k4 * 4];
            #pragma unroll
            for (int jj = 0; jj < 16; ++jj) {
                float4 kv = *(const float4*)&KVs[(jj * 4 + td) * ASTR + k4 * 4];
                sacc[jj] += qv.x * kv.x + qv.y * kv.y + qv.z * kv.z + qv.w * kv.w;
            }
        }
        int ig = q0 + tq;
        float tmax = -INFINITY;
        #pragma unroll
        for (int jj = 0; jj < 16; ++jj) {
            int jg = j0 + jj * 4 + td;
            bool ok = (jg <= ig) && (ig - jg < 1024);
            float sv = ok ? sacc[jj] : -INFINITY;
            Ss[tq * 66 + jj * 4 + td] = sv;
            tmax = fmaxf(tmax, sv);
        }
        tmax = fmaxf(tmax, __shfl_xor_sync(0xffffffffu, tmax, 1));
        tmax = fmaxf(tmax, __shfl_xor_sync(0xffffffffu, tmax, 2));

        __syncthreads();
        for (int e = tid; e < 8192; e += 256) {
            int r = e >> 7, c = e & 127;
            KVs[r * ASTR + c] = QKV[((long)(b * SEQ + j0 + r)) * 6144 + 4096 + h * 128 + c];
        }
        __syncthreads();

        float mt  = fmaxf(m, tmax);
        float mte = (mt > -INFINITY) ? mt : 0.f;
        float corr = exp2f(m - mte);
        l *= corr;
        #pragma unroll
        for (int d = 0; d < 32; ++d) acc[d] *= corr;
        float lpart = 0.f;
        #pragma unroll
        for (int jj = 0; jj < 16; ++jj) {
            float p = exp2f(Ss[tq * 66 + jj * 4 + td] - mte);
            Ss[tq * 66 + jj * 4 + td] = p;
            lpart += p;
        }
        lpart += __shfl_xor_sync(0xffffffffu, lpart, 1);
        lpart += __shfl_xor_sync(0xffffffffu, lpart, 2);
        l += lpart;
        __syncwarp();
        #pragma unroll 2
        for (int jj = 0; jj < 64; ++jj) {
            float pj = Ss[tq * 66 + jj];
            const float* vr = &KVs[jj * ASTR + td * 4];
            #pragma unroll
            for (int d4 = 0; d4 < 8; ++d4) {
                float4 vv = *(const float4*)&vr[d4 * 16];
                acc[d4 * 4 + 0] = fmaf(pj, vv.x, acc[d4 * 4 + 0]);
                acc[d4 * 4 + 1] = fmaf(pj, vv.y, acc[d4 * 4 + 1]);
                acc[d4 * 4 + 2] = fmaf(pj, vv.z, acc[d4 * 4 + 2]);
                acc[d4 * 4 + 3] = fmaf(pj, vv.w, acc[d4 * 4 + 3]);
            }
        }
        m = mt;
        __syncwarp();
    }
    float rl = 1.f / l;
    float* orow = &O[((long)(b * SEQ + q0 + tq)) * DIMD + h * 128 + td * 4];
    #pragma unroll
    for (int d4 = 0; d4 < 8; ++d4) {
        float4 o;
        o.x = acc[d4 * 4 + 0] * rl; o.y = acc[d4 * 4 + 1] * rl;
        o.z = acc[d4 * 4 + 2] * rl; o.w = acc[d4 * 4 + 3] * rl;
        *(float4*)&orow[d4 * 16] = o;
    }
}

// --------------------------- TTT helper kernels -----------------------------
// fill W02 fp32 + splits, W1 fp32 + splits
__global__ void copyw(const float* __restrict__ w0, const float* __restrict__ w1,
                      const float* __restrict__ w2,
                      float* __restrict__ o02, __nv_bfloat16* __restrict__ o02h,
                      __nv_bfloat16* __restrict__ o02l,
                      float* __restrict__ o1, __nv_bfloat16* __restrict__ o1h,
                      __nv_bfloat16* __restrict__ o1l)
{
    long idx = (long)blockIdx.x * 256 + threadIdx.x;   // 8*1024*512 = 4M
    int col = idx & 511;
    int row = (idx >> 9) & 1023;
    int h = (idx >> 19) & 3;
    long src = (long)h * 262144 + (long)(row & 511) * 512 + col;
    float v = (row < 512) ? w0[src] : w2[src];
    o02[idx] = v;
    split_w(v, o02h, o02l, idx);
    if (idx < (long)2 * 1024 * 1024) {
        float v1 = w1[idx & ((long)4 * 262144 - 1)];
        o1[idx] = v1;
        split_w(v1, o1h, o1l, idx);
    }
}

__global__ void elem2(const float* __restrict__ fv, const float* __restrict__ lr,
                      const float* __restrict__ gh, const float* __restrict__ dhin,
                      __nv_bfloat16* __restrict__ dgph, __nv_bfloat16* __restrict__ dgpl,
                      __nv_bfloat16* __restrict__ vlh, __nv_bfloat16* __restrict__ vll,
                      __nv_bfloat16* __restrict__ hth, __nv_bfloat16* __restrict__ htl,
                      int ck0)
{
    long idx = (long)blockIdx.x * 256 + threadIdx.x;   // 8*1024*512
    int col = idx & 511;
    long tt = idx >> 9;
    int c = tt & 1023, bh = tt >> 10;
    int b = bh >> 2, h = bh & 3;
    long row = (long)b * SEQ + ck0 + c;
    float l0 = lr[row * 12 + h], l1 = lr[row * 12 + 4 + h], l2 = lr[row * 12 + 8 + h];
    long gi = (long)bh * 1048576 + (long)c * 1024 + col;
    float g = gh[gi], hp = gh[gi + 512], d = dhin[idx];
    float sig = 1.f / (1.f + expf(-g));
    float sg = g * sig;
    split_w(sg * hp, hth, htl, idx);
    float v = fv[((long)bh * SEQ + ck0 + c) * FDM + col];
    split_w(d * hp * (sig * (1.f + g * (1.f - sig))) * l0, dgph, dgpl, gi);
    split_w(d * sg * l2, dgph, dgpl, gi + 512);
    split_w(v * l1, vlh, vll, idx);
}

__global__ void elem3(const float* __restrict__ gh,
                      __nv_bfloat16* __restrict__ hnh, __nv_bfloat16* __restrict__ hnl)
{
    long idx = (long)blockIdx.x * 256 + threadIdx.x;   // 8*1024*512
    int col = idx & 511;
    long tt = idx >> 9;
    int c = tt & 1023, bh = tt >> 10;
    long gi = (long)bh * 1048576 + (long)c * 1024 + col;
    float g = gh[gi];
    split_w((g / (1.f + expf(-g))) * gh[gi + 512], hnh, hnl, idx);
}

// -------------------- ttt rmsnorm + add attention result --------------------
__global__ void post_kernel(const float* __restrict__ ttt, const float* __restrict__ tw,
                            const float* __restrict__ sum,
                            __nv_bfloat16* __restrict__ smh, __nv_bfloat16* __restrict__ sml)
{
    __shared__ float sr[4];
    int fh = blockIdx.x, row = blockIdx.y;
    int b = row >> 11, t = row & 2047;
    int bh = b * 4 + fh;
    const float* src = ttt + ((long)bh * SEQ + t) * FDM;
    int tid = threadIdx.x;
    float v[4], ss = 0.f;
    #pragma unroll
    for (int j = 0; j < 4; ++j) { v[j] = src[tid + 128 * j]; ss += v[j] * v[j]; }
    #pragma unroll
    for (int o = 16; o > 0; o >>= 1) ss += __shfl_down_sync(0xffffffffu, ss, o);
    if ((tid & 31) == 0) sr[tid >> 5] = ss;
    __syncthreads();
    float tot = sr[0] + sr[1] + sr[2] + sr[3];
    float r = rsqrtf(tot * (1.f / 512.f) + 1e-6f);
    #pragma unroll
    for (int j = 0; j < 4; ++j) {
        int i = tid + 128 * j;
        long o = (long)row * 2048 + fh * 512 + i;
        split_w(sum[o] + v[j] * r * tw[i], smh, sml, o);
    }
}

// --------------------------------- launch -----------------------------------
#define GSYM(p, s) cudaGetSymbolAddress((void**)&(p), s)

extern "C" void kernel_launch(void* const* d_in, const int* in_sizes, int n_in,
                              void* d_out, int out_size)
{
    const float* hidden = (const float*)d_in[0];
    const float* Wqkv   = (const float*)d_in[1];
    const float* Wo     = (const float*)d_in[2];
    const float* qnw    = (const float*)d_in[3];
    const float* knw    = (const float*)d_in[4];
    const float* w0     = (const float*)d_in[5];
    const float* w1     = (const float*)d_in[6];
    const float* w2     = (const float*)d_in[7];
    const float* lrw    = (const float*)d_in[8];
    const float* lrb    = (const float*)d_in[9];
    const float* qksc   = (const float*)d_in[10];
    const float* qkof   = (const float*)d_in[11];
    const float* tttw   = (const float*)d_in[12];
    float* out = (float*)d_out;

    float *qkv, *lrpre, *lr, *aq, *ak, *fv, *pw02, *pw1, *gh, *dh, *ttt, *sum;
    GSYM(qkv, g_qkv);   GSYM(lrpre, g_lrpre); GSYM(lr, g_lr);
    GSYM(aq, g_aq);     GSYM(ak, g_ak);       GSYM(fv, g_fv);
    GSYM(pw02, g_w02);  GSYM(pw1, g_w1);
    GSYM(gh, g_gh);     GSYM(dh, g_dh);
    GSYM(ttt, g_ttt);   GSYM(sum, g_sum);

    __nv_bfloat16 *hxh,*hxl,*wqh,*wql,*woh,*wol,*fqh,*fql,*fkh,*fkl,*fvh,*fvl;
    __nv_bfloat16 *w02h,*w02l,*w1h,*w1l,*dgph,*dgpl,*vlh,*vll,*hth,*htl,*hnh,*hnl,*smh,*sml;
    GSYM(hxh, g_hx_h); GSYM(hxl, g_hx_l); GSYM(wqh, g_wq_h); GSYM(wql, g_wq_l);
    GSYM(woh, g_wo_h); GSYM(wol, g_wo_l);
    GSYM(fqh, g_fq_h); GSYM(fql, g_fq_l); GSYM(fkh, g_fk_h); GSYM(fkl, g_fk_l);
    GSYM(fvh, g_fv_h); GSYM(fvl, g_fv_l);
    GSYM(w02h, g_w02_h); GSYM(w02l, g_w02_l);
    GSYM(w1h, g_w1_h); GSYM(w1l, g_w1_l);
    GSYM(dgph, g_dgp_h); GSYM(dgpl, g_dgp_l);
    GSYM(vlh, g_vl_h); GSYM(vll, g_vl_l); GSYM(hth, g_ht_h); GSYM(htl, g_ht_l);
    GSYM(hnh, g_hn_h); GSYM(hnl, g_hn_l); GSYM(smh, g_sm_h); GSYM(sml, g_sm_l);

    cudaFuncSetAttribute(mma_gemm<0,0,false,false>,
                         cudaFuncAttributeMaxDynamicSharedMemorySize, 81920);
    cudaFuncSetAttribute(mma_gemm<0,1,false,false>,
                         cudaFuncAttributeMaxDynamicSharedMemorySize, 75776);
    cudaFuncSetAttribute(mma_gemm<1,1,true,true>,
                         cudaFuncAttributeMaxDynamicSharedMemorySize, 69632);
    cudaFuncSetAttribute(attn_kernel, cudaFuncAttributeMaxDynamicSharedMemorySize, ATTN_SMEM);

    // NT: A[m,k], B[n,k]
    #define G_NT(Ah,Al,Bh,Bl,C,M,N,K,lda,ldb,sA,sB,sC,bat) \
        mma_gemm<0,0,false,false><<<dim3((N)/128,(M)/128,(bat)),256,81920>>>( \
            Ah,Al,Bh,Bl,C,nullptr,nullptr,M,N,K,lda,ldb,sA,sB,sC)
    // NN: A[m,k], B[k,n]
    #define G_NN(Ah,Al,Bh,Bl,C,M,N,K,lda,ldb,sA,sB,sC,bat) \
        mma_gemm<0,1,false,false><<<dim3((N)/128,(M)/128,(bat)),256,75776>>>( \
            Ah,Al,Bh,Bl,C,nullptr,nullptr,M,N,K,lda,ldb,sA,sB,sC)
    // TN + accumulate + split-out: A[k,m], B[k,n]
    #define G_TN_AS(Ah,Al,Bh,Bl,C,Ch,Cl,M,N,K,lda,ldb,sA,sB,sC,bat) \
        mma_gemm<1,1,true,true><<<dim3((N)/128,(M)/128,(bat)),256,69632>>>( \
            Ah,Al,Bh,Bl,C,Ch,Cl,M,N,K,lda,ldb,sA,sB,sC)

    // ---- inputs -> bf16 hi/lo ----
    cvt_hl<<<8192, 256>>>(hidden, hxh, hxl, (long)4096 * 2048);
    cvt_hl<<<12288, 256>>>(Wqkv, wqh, wql, (long)6144 * 2048);
    cvt_hl<<<4096, 256>>>(Wo, woh, wol, (long)2048 * 2048);

    // qkv = hidden @ Wqkv^T ; lrpre = hidden @ lr_w^T
    G_NT(hxh, hxl, wqh, wql, qkv, 4096, 6144, 2048, 2048, 2048, 0, 0, 0, 1);
    lr_gemm<<<2048, 256>>>(hidden, lrw, lrpre);

    float base = (float)(0.001 + log(-expm1(-0.001)));
    prep_kernel<<<4096, 256>>>(qkv, lrpre, qnw, knw, qksc, qkof, lrb, base,
                               aq, ak, fqh, fql, fkh, fkl, fvh, fvl, fv, lr);
    attn_kernel<<<dim3(32, 16, 2), 256, ATTN_SMEM>>>(aq, ak, qkv, sum);

    copyw<<<16384, 256>>>(w0, w1, w2, pw02, w02h, w02l, pw1, w1h, w1l);

    long sSeq = (long)SEQ * FDM;     // 1048576
    long sChk = (long)1024 * FDM;    // 524288
    long sW   = (long)FDM * FDM;     // 262144
    long sW02 = (long)1024 * FDM;    // 524288
    long sGH  = (long)1024 * 1024;   // 1048576
    for (int ck = 0; ck < 2; ++ck) {
        int ck0 = ck * 1024;
        long co = (long)ck0 * FDM;
        // forward: gh = K @ W02^T (NT), dh = V @ W1 (NN)
        G_NT(fkh + co, fkl + co, w02h, w02l, gh, 1024, 1024, 512,
             512, 512, sSeq, sW02, sGH, 8);
        G_NN(fvh + co, fvl + co, w1h, w1l, dh, 1024, 512, 512,
             512, 512, sSeq, sW, sChk, 8);
        elem2<<<16384, 256>>>(fv, lr, gh, dh, dgph, dgpl, vlh, vll, hth, htl, ck0);
        // updates: W02 += dgp^T @ K (TN);  W1 += vl^T @ ht (TN); splits fused
        G_TN_AS(dgph, dgpl, fkh + co, fkl + co, pw02, w02h, w02l,
                1024, 512, 1024, 1024, 512, sGH, sSeq, sW02, 8);
        G_TN_AS(vlh, vll, hth, htl, pw1, w1h, w1l,
                512, 512, 1024, 512, 512, sChk, sChk, sW, 8);
        // query pass: gh = Q @ W02^T (NT)
        G_NT(fqh + co, fql + co, w02h, w02l, gh, 1024, 1024, 512,
             512, 512, sSeq, sW02, sGH, 8);
        elem3<<<16384, 256>>>(gh, hnh, hnl);
        // out = hq @ W1^T (NT: B[n=o, k=h] = W1 natural)
        G_NT(hnh, hnl, w1h, w1l, ttt + co, 1024, 512, 512,
             512, 512, sChk, sW, sSeq, 8);
    }

    post_kernel<<<dim3(4, 4096), 128>>>(ttt, tttw, sum, smh, sml);
    // out = (attn + ttt_norm) @ Wo^T
    G_NT(smh, sml, woh, wol, out, 4096, 2048, 2048, 2048, 2048, 0, 0, 0, 1);
    #undef G_NT
    #undef G_NN
    #undef G_TN_AS
}

// round 9
// speedup vs baseline: 5.1374x; 1.5606x over previous
#include <cuda_runtime.h>
#include <cuda_bf16.h>
#include <cstdint>
#include <math.h>

#define SEQ 2048
#define DIMD 2048
#define FDM 512

// ------------------------- fp32 scratch (device globals) --------------------
__device__ float g_qkv [(size_t)4096 * 6144];
__device__ float g_lrpre[(size_t)4096 * 12];
__device__ float g_lr  [(size_t)4096 * 12];
__device__ float g_fv  [(size_t)8 * SEQ * FDM];
__device__ float g_w02 [(size_t)8 * 1024 * FDM];
__device__ float g_w1  [(size_t)8 * FDM * FDM];
__device__ float g_gh  [(size_t)8 * 1024 * 1024];
__device__ float g_dh  [(size_t)8 * 1024 * FDM];
__device__ float g_ttt [(size_t)8 * SEQ * FDM];
__device__ float g_sum [(size_t)4096 * 2048];

// ------------------------- bf16 hi/lo scratch -------------------------------
__device__ __nv_bfloat16 g_hx_h[(size_t)4096*2048],  g_hx_l[(size_t)4096*2048];
__device__ __nv_bfloat16 g_wq_h[(size_t)6144*2048],  g_wq_l[(size_t)6144*2048];
__device__ __nv_bfloat16 g_wo_h[(size_t)2048*2048],  g_wo_l[(size_t)2048*2048];
__device__ __nv_bfloat16 g_aq_h[(size_t)4096*2048],  g_aq_l[(size_t)4096*2048];
__device__ __nv_bfloat16 g_ak_h[(size_t)4096*2048],  g_ak_l[(size_t)4096*2048];
__device__ __nv_bfloat16 g_av_h[(size_t)4096*2048],  g_av_l[(size_t)4096*2048];
__device__ __nv_bfloat16 g_fq_h[(size_t)8*SEQ*FDM],  g_fq_l[(size_t)8*SEQ*FDM];
__device__ __nv_bfloat16 g_fk_h[(size_t)8*SEQ*FDM],  g_fk_l[(size_t)8*SEQ*FDM];
__device__ __nv_bfloat16 g_fv_h[(size_t)8*SEQ*FDM],  g_fv_l[(size_t)8*SEQ*FDM];
__device__ __nv_bfloat16 g_w02_h[(size_t)8*1024*FDM], g_w02_l[(size_t)8*1024*FDM];
__device__ __nv_bfloat16 g_w1_h[(size_t)8*FDM*FDM],  g_w1_l[(size_t)8*FDM*FDM];
__device__ __nv_bfloat16 g_dgp_h[(size_t)8*1024*1024], g_dgp_l[(size_t)8*1024*1024];
__device__ __nv_bfloat16 g_vl_h[(size_t)8*1024*FDM], g_vl_l[(size_t)8*1024*FDM];
__device__ __nv_bfloat16 g_ht_h[(size_t)8*1024*FDM], g_ht_l[(size_t)8*1024*FDM];
__device__ __nv_bfloat16 g_hn_h[(size_t)8*1024*FDM], g_hn_l[(size_t)8*1024*FDM];
__device__ __nv_bfloat16 g_sm_h[(size_t)4096*2048],  g_sm_l[(size_t)4096*2048];

// ------------------------------ helpers -------------------------------------
__device__ __forceinline__ uint32_t smem_u32(const void* p) {
    uint32_t a;
    asm("{ .reg .u64 t; cvta.to.shared.u64 t, %1; cvt.u32.u64 %0, t; }" : "=r"(a) : "l"(p));
    return a;
}
__device__ __forceinline__ void cpa16(uint32_t s, const void* g) {
    asm volatile("cp.async.cg.shared.global [%0], [%1], 16;" :: "r"(s), "l"(g));
}
#define CP_COMMIT() asm volatile("cp.async.commit_group;" ::: "memory")
#define MMA16816(d, a, b0, b1) \
    asm volatile("mma.sync.aligned.m16n8k16.row.col.f32.bf16.bf16.f32 " \
        "{%0,%1,%2,%3}, {%4,%5,%6,%7}, {%8,%9}, {%0,%1,%2,%3};" \
        : "+f"((d)[0]), "+f"((d)[1]), "+f"((d)[2]), "+f"((d)[3]) \
        : "r"((a)[0]), "r"((a)[1]), "r"((a)[2]), "r"((a)[3]), "r"(b0), "r"(b1))
__device__ __forceinline__ void ldmx4(uint32_t* r, uint32_t addr) {
    asm volatile("ldmatrix.sync.aligned.m8n8.x4.shared.b16 {%0,%1,%2,%3}, [%4];"
        : "=r"(r[0]), "=r"(r[1]), "=r"(r[2]), "=r"(r[3]) : "r"(addr));
}
__device__ __forceinline__ void ldmx4t(uint32_t* r, uint32_t addr) {
    asm volatile("ldmatrix.sync.aligned.m8n8.x4.trans.shared.b16 {%0,%1,%2,%3}, [%4];"
        : "=r"(r[0]), "=r"(r[1]), "=r"(r[2]), "=r"(r[3]) : "r"(addr));
}
__device__ __forceinline__ void split_w(float v, __nv_bfloat16* h, __nv_bfloat16* l, long i) {
    __nv_bfloat16 hv = __float2bfloat16_rn(v);
    h[i] = hv;
    l[i] = __float2bfloat16_rn(v - __bfloat162float(hv));
}

// -------------------- mma.sync batched GEMM, bf16x3 split -------------------
template<int AT, int BT, bool ACC, bool SPLIT>
__global__ void __launch_bounds__(256, 2)
mma_gemm(const __nv_bfloat16* __restrict__ Ah, const __nv_bfloat16* __restrict__ Al,
         const __nv_bfloat16* __restrict__ Bh, const __nv_bfloat16* __restrict__ Bl,
         float* __restrict__ C, __nv_bfloat16* __restrict__ Ch,
         __nv_bfloat16* __restrict__ Cl, int M, int N, int K,
         int lda, int ldb, long sA, long sB, long sC)
{
    constexpr int SA = AT ? 8704 : 10240;
    constexpr int SB = BT ? 8704 : 10240;
    constexpr int STAGE = 2 * (SA + SB);
    extern __shared__ char smem[];
    uint32_t sb = smem_u32(smem);
    int tid = threadIdx.x, lane = tid & 31, wid = tid >> 5;
    int wm = wid >> 2, wn = wid & 3;
    long zb = blockIdx.z;
    const __nv_bfloat16* ah = Ah + zb * sA;
    const __nv_bfloat16* al = Al + zb * sA;
    const __nv_bfloat16* bh = Bh + zb * sB;
    const __nv_bfloat16* bl = Bl + zb * sB;
    int m0 = blockIdx.y << 7, n0 = blockIdx.x << 7;

    float acc[4][4][4];
    #pragma unroll
    for (int i = 0; i < 4; ++i)
        #pragma unroll
        for (int j = 0; j < 4; ++j)
            #pragma unroll
            for (int q = 0; q < 4; ++q) acc[i][j][q] = 0.f;

    uint32_t a_row = (lane & 7) + ((lane >> 3) & 1) * 8;
    uint32_t a_kb  = ((lane >> 4) & 1) * 16;
    uint32_t a_kr  = (lane & 7) + ((lane >> 4) & 1) * 8;
    uint32_t a_mo  = ((lane >> 3) & 1) * 8;
    uint32_t b_row = (lane & 7) + ((lane >> 4) & 1) * 8;
    uint32_t b_kb  = ((lane >> 3) & 1) * 16;
    uint32_t b_kr  = (lane & 7) + ((lane >> 3) & 1) * 8;
    uint32_t b_no  = ((lane >> 4) & 1) * 8;

    auto issue = [&](int buf, int k0) {
        uint32_t st = sb + buf * STAGE;
        #pragma unroll
        for (int j = 0; j < 2; ++j) {
            int u = tid + j * 256;
            uint32_t soA; long gA;
            if (AT == 0) { int r = u >> 2, s = u & 3; soA = r * 80 + s * 16;
                           gA = (long)(m0 + r) * lda + k0 + s * 8; }
            else         { int r = u >> 4, s = u & 15; soA = r * 272 + s * 16;
                           gA = (long)(k0 + r) * lda + m0 + s * 8; }
            cpa16(st + soA,      ah + gA);
            cpa16(st + SA + soA, al + gA);
            uint32_t soB; long gB;
            if (BT == 0) { int r = u >> 2, s = u & 3; soB = r * 80 + s * 16;
                           gB = (long)(n0 + r) * ldb + k0 + s * 8; }
            else         { int r = u >> 4, s = u & 15; soB = r * 272 + s * 16;
                           gB = (long)(k0 + r) * ldb + n0 + s * 8; }
            cpa16(st + 2 * SA + soB,      bh + gB);
            cpa16(st + 2 * SA + SB + soB, bl + gB);
        }
        CP_COMMIT();
    };

    const int n = K >> 5;
    issue(0, 0);
    int buf = 0;
    for (int i = 0; i < n; ++i) {
        if (i + 1 < n) {
            issue(buf ^ 1, (i + 1) * 32);
            asm volatile("cp.async.wait_group 1;" ::: "memory");
        } else {
            asm volatile("cp.async.wait_group 0;" ::: "memory");
        }
        __syncthreads();
        uint32_t st = sb + buf * STAGE;
        uint32_t stB = st + 2 * SA;
        #pragma unroll
        for (int kk = 0; kk < 32; kk += 16) {
            uint32_t ahf[4][4], alf[4][4];
            #pragma unroll
            for (int mt = 0; mt < 4; ++mt) {
                if (AT == 0) {
                    uint32_t ra = st + (wm * 64 + mt * 16 + a_row) * 80 + kk * 2 + a_kb;
                    ldmx4(ahf[mt], ra);
                    ldmx4(alf[mt], ra + SA);
                } else {
                    uint32_t ra = st + (kk + a_kr) * 272 + (wm * 64 + mt * 16 + a_mo) * 2;
                    ldmx4t(ahf[mt], ra);
                    ldmx4t(alf[mt], ra + SA);
                }
            }
            uint32_t bhf[2][4], blf[2][4];
            #pragma unroll
            for (int p = 0; p < 2; ++p) {
                if (BT == 0) {
                    uint32_t rb = stB + (wn * 32 + p * 16 + b_row) * 80 + kk * 2 + b_kb;
                    ldmx4(bhf[p], rb);
                    ldmx4(blf[p], rb + SB);
                } else {
                    uint32_t rb = stB + (kk + b_kr) * 272 + (wn * 32 + p * 16 + b_no) * 2;
                    ldmx4t(bhf[p], rb);
                    ldmx4t(blf[p], rb + SB);
                }
            }
            #pragma unroll
            for (int nt = 0; nt < 4; ++nt) {
                uint32_t bh0 = bhf[nt >> 1][(nt & 1) * 2 + 0];
                uint32_t bh1 = bhf[nt >> 1][(nt & 1) * 2 + 1];
                uint32_t bl0 = blf[nt >> 1][(nt & 1) * 2 + 0];
                uint32_t bl1 = blf[nt >> 1][(nt & 1) * 2 + 1];
                #pragma unroll
                for (int mt = 0; mt < 4; ++mt) {
                    MMA16816(acc[mt][nt], ahf[mt], bh0, bh1);
                    MMA16816(acc[mt][nt], ahf[mt], bl0, bl1);
                    MMA16816(acc[mt][nt], alf[mt], bh0, bh1);
                }
            }
        }
        __syncthreads();
        buf ^= 1;
    }
    float* c = C + zb * sC;
    __nv_bfloat16* ch = SPLIT ? Ch + zb * sC : nullptr;
    __nv_bfloat16* cl = SPLIT ? Cl + zb * sC : nullptr;
    #pragma unroll
    for (int mt = 0; mt < 4; ++mt) {
        #pragma unroll
        for (int nt = 0; nt < 4; ++nt) {
            long r0 = m0 + wm * 64 + mt * 16 + (lane >> 2);
            int  cc = n0 + wn * 32 + nt * 8 + (lane & 3) * 2;
            long o0 = r0 * (long)N + cc;
            long o1 = (r0 + 8) * (long)N + cc;
            float v00 = acc[mt][nt][0], v01 = acc[mt][nt][1];
            float v10 = acc[mt][nt][2], v11 = acc[mt][nt][3];
            if (ACC) {
                float2 t0 = *(float2*)(c + o0), t1 = *(float2*)(c + o1);
                v00 += t0.x; v01 += t0.y; v10 += t1.x; v11 += t1.y;
            }
            *(float2*)(c + o0) = make_float2(v00, v01);
            *(float2*)(c + o1) = make_float2(v10, v11);
            if (SPLIT) {
                split_w(v00, ch, cl, o0); split_w(v01, ch, cl, o0 + 1);
                split_w(v10, ch, cl, o1); split_w(v11, ch, cl, o1 + 1);
            }
        }
    }
}

// ------------------------ conversion kernel ---------------------------------
__global__ void cvt_hl(const float* __restrict__ x, __nv_bfloat16* __restrict__ h,
                       __nv_bfloat16* __restrict__ l, long n)
{
    long i = ((long)blockIdx.x * 256 + threadIdx.x) * 4;
    if (i >= n) return;
    float4 v = *(const float4*)(x + i);
    split_w(v.x, h, l, i);     split_w(v.y, h, l, i + 1);
    split_w(v.z, h, l, i + 2); split_w(v.w, h, l, i + 3);
}

// ---------------- small SGEMM for the N=12 lr GEMM --------------------------
__global__ void lr_gemm(const float* __restrict__ A, const float* __restrict__ B,
                        float* __restrict__ C)
{
    __shared__ float bs[12][128];
    int row = blockIdx.x * 2 + (threadIdx.x >> 7);
    int tid = threadIdx.x & 127;
    float acc[12];
    #pragma unroll
    for (int c = 0; c < 12; ++c) acc[c] = 0.f;
    for (int k0 = 0; k0 < 2048; k0 += 128) {
        if (threadIdx.x < 128)
            #pragma unroll
            for (int c = 0; c < 12; ++c) bs[c][tid] = B[c * 2048 + k0 + tid];
        __syncthreads();
        float a = A[(long)row * 2048 + k0 + tid];
        #pragma unroll
        for (int c = 0; c < 12; ++c) acc[c] += a * bs[c][tid];
        __syncthreads();
    }
    __shared__ float red[2][12][4];
    #pragma unroll
    for (int c = 0; c < 12; ++c) {
        float v = acc[c];
        #pragma unroll
        for (int o = 16; o > 0; o >>= 1) v += __shfl_down_sync(0xffffffffu, v, o);
        if ((tid & 31) == 0) red[threadIdx.x >> 7][c][tid >> 5] = v;
    }
    __syncthreads();
    if (tid < 12) {
        int w = threadIdx.x >> 7;
        C[(long)row * 12 + tid] = red[w][tid][0] + red[w][tid][1] + red[w][tid][2] + red[w][tid][3];
    }
}

// ------------------------- block reduce (256 thr) ---------------------------
__device__ __forceinline__ float blockReduceSum(float v, float* sred)
{
    int lane = threadIdx.x & 31;
    #pragma unroll
    for (int o = 16; o > 0; o >>= 1) v += __shfl_down_sync(0xffffffffu, v, o);
    if (lane == 0) sred[threadIdx.x >> 5] = v;
    __syncthreads();
    if (threadIdx.x < 8) {
        float r = sred[threadIdx.x];
        #pragma unroll
        for (int o = 4; o > 0; o >>= 1) r += __shfl_down_sync(0xffu, r, o);
        if (threadIdx.x == 0) sred[0] = r;
    }
    __syncthreads();
    float out = sred[0];
    __syncthreads();
    return out;
}

// --------- prep: rmsnorm+rope + silu/L2 + lr; bf16 hi/lo outputs ------------
__global__ void prep_kernel(const float* __restrict__ qkv, const float* __restrict__ lrpre,
                            const float* __restrict__ qnw, const float* __restrict__ knw,
                            const float* __restrict__ qksc, const float* __restrict__ qkof,
                            const float* __restrict__ lrb, float base_lr_inv,
                            __nv_bfloat16* __restrict__ aqh, __nv_bfloat16* __restrict__ aql,
                            __nv_bfloat16* __restrict__ akh, __nv_bfloat16* __restrict__ akl,
                            __nv_bfloat16* __restrict__ avh, __nv_bfloat16* __restrict__ avl,
                            __nv_bfloat16* __restrict__ fqh, __nv_bfloat16* __restrict__ fql,
                            __nv_bfloat16* __restrict__ fkh, __nv_bfloat16* __restrict__ fkl,
                            __nv_bfloat16* __restrict__ fvh, __nv_bfloat16* __restrict__ fvl,
                            float* __restrict__ fv, float* __restrict__ lrout)
{
    __shared__ float s_q[2048];
    __shared__ float s_k[2048];
    __shared__ float sred[8];
    int row = blockIdx.x;
    int b = row >> 11, t = row & 2047;
    int tid = threadIdx.x;
    const float* qr = qkv + (long)row * 6144;
    const float* kr = qr + 2048;
    const float* vr = qr + 4096;
    const float qscale = 0.088388347648318447f * 1.4426950408889634f;

    float qv[8], kv[8], fqv[8], fkv[8], fvv[8];
    float sq = 0.f, sk = 0.f;
    float p2q[4] = {0, 0, 0, 0}, p2k[4] = {0, 0, 0, 0};
    #pragma unroll
    for (int j = 0; j < 8; ++j) {
        int i = j * 256 + tid;
        float q = qr[i], k = kr[i], v = vr[i];
        qv[j] = q; kv[j] = k;
        sq += q * q; sk += k * k;
        float fqe = (q / (1.f + expf(-q))) * qksc[i * 2 + 0] + qkof[i * 2 + 0];
        float fke = (k / (1.f + expf(-k))) * qksc[i * 2 + 1] + qkof[i * 2 + 1];
        fqv[j] = fqe; fkv[j] = fke; fvv[j] = v / (1.f + expf(-v));
        p2q[j >> 1] += fqe * fqe;
        p2k[j >> 1] += fke * fke;
        split_w(v, avh, avl, (long)row * DIMD + i);
    }
    float SQ = blockReduceSum(sq, sred);
    float SK = blockReduceSum(sk, sred);
    float G2Q[4], G2K[4];
    #pragma unroll
    for (int g = 0; g < 4; ++g) G2Q[g] = blockReduceSum(p2q[g], sred);
    #pragma unroll
    for (int g = 0; g < 4; ++g) G2K[g] = blockReduceSum(p2k[g], sred);
    float rq = rsqrtf(SQ * (1.f / 2048.f) + 1e-6f);
    float rk = rsqrtf(SK * (1.f / 2048.f) + 1e-6f);
    #pragma unroll
    for (int j = 0; j < 8; ++j) {
        int i = j * 256 + tid;
        s_q[i] = qv[j] * rq * qnw[i];
        s_k[i] = kv[j] * rk * knw[i];
        int g = j >> 1;
        long fb = (((long)(b * 4 + g)) * SEQ + t) * FDM + (i & 511);
        float fqn = fqv[j] / (sqrtf(G2Q[g]) + 1e-12f);
        float fkn = fkv[j] / (sqrtf(G2K[g]) + 1e-12f);
        split_w(fqn, fqh, fql, fb);
        split_w(fkn, fkh, fkl, fb);
        split_w(fvv[j], fvh, fvl, fb);
        fv[fb] = fvv[j];
    }
    __syncthreads();
    #pragma unroll
    for (int j = 0; j < 8; ++j) {
        int i = j * 256 + tid;
        int pos = i & 127;
        int fi = pos & 63;
        float invf = expf(-(float)fi * (logf(500000.f) / 64.f));
        float sn, cs;
        sincosf((float)t * invf, &sn, &cs);
        float oq, ok_;
        if (pos < 64) {
            oq  = s_q[i] * cs - s_q[i + 64] * sn;
            ok_ = s_k[i] * cs - s_k[i + 64] * sn;
        } else {
            oq  = s_q[i] * cs + s_q[i - 64] * sn;
            ok_ = s_k[i] * cs + s_k[i - 64] * sn;
        }
        split_w(oq * qscale, aqh, aql, (long)row * DIMD + i);
        split_w(ok_, akh, akl, (long)row * DIMD + i);
    }
    if (tid < 12) {
        float x = lrpre[(long)row * 12 + tid] + lrb[tid] + base_lr_inv;
        lrout[(long)row * 12 + tid] = (x > 20.f) ? x : log1pf(expf(x));
    }
}

// -------------------- HMMA windowed flash attention --------------------------
#define ATS 272
#define PST 144
#define O_QH 0
#define O_QL 17408
#define O_KH 34816
#define O_KL 52224
#define O_VH 69632
#define O_VL 87040
#define O_S  104448
#define O_PH 121856
#define O_PL 131072
#define O_CR 140288
#define O_LR 140544
#define ATTN_SMEM 140800

__global__ void __launch_bounds__(256, 1)
attn_mma(const __nv_bfloat16* __restrict__ Qh, const __nv_bfloat16* __restrict__ Ql,
         const __nv_bfloat16* __restrict__ Kh, const __nv_bfloat16* __restrict__ Kl,
         const __nv_bfloat16* __restrict__ Vh, const __nv_bfloat16* __restrict__ Vl,
         float* __restrict__ O)
{
    extern __shared__ char smc[];
    uint32_t sb = smem_u32(smc);
    float* Sf = (float*)(smc + O_S);
    float* carr = (float*)(smc + O_CR);
    float* larr = (float*)(smc + O_LR);
    __nv_bfloat16* Pho = (__nv_bfloat16*)(smc + O_PH);
    __nv_bfloat16* Plo = (__nv_bfloat16*)(smc + O_PL);

    int tid = threadIdx.x, lane = tid & 31, wid = tid >> 5;
    int q0 = blockIdx.x << 6, h = blockIdx.y, b = blockIdx.z;
    int wr = (wid & 3) * 16;
    int wc = wid >> 2;
    uint32_t a_row = (lane & 7) + ((lane >> 3) & 1) * 8;
    uint32_t a_kb  = ((lane >> 4) & 1) * 16;
    uint32_t b_row = (lane & 7) + ((lane >> 4) & 1) * 8;
    uint32_t b_kb  = ((lane >> 3) & 1) * 16;
    uint32_t b_kr  = (lane & 7) + ((lane >> 3) & 1) * 8;
    uint32_t b_no  = ((lane >> 4) & 1) * 8;
    int tq = tid >> 2, td = tid & 3;

    // load Q hi/lo (resident)
    #pragma unroll
    for (int j = 0; j < 4; ++j) {
        int u = tid + j * 256;
        int r = u >> 4, s = u & 15;
        long g = ((long)(b * SEQ + q0 + r)) * DIMD + h * 128 + s * 8;
        cpa16(sb + O_QH + r * ATS + s * 16, Qh + g);
        cpa16(sb + O_QL + r * ATS + s * 16, Ql + g);
    }
    CP_COMMIT();

    float oacc[8][4];
    #pragma unroll
    for (int i = 0; i < 8; ++i)
        #pragma unroll
        for (int q = 0; q < 4; ++q) oacc[i][q] = 0.f;
    float m = -INFINITY, lrow = 0.f;

    int kt_hi = q0 >> 6;
    int kt_lo = (q0 >= 1024) ? ((q0 - 1023) >> 6) : 0;
    for (int kt = kt_lo; kt <= kt_hi; ++kt) {
        int j0 = kt << 6;
        __syncthreads();
        #pragma unroll
        for (int j = 0; j < 4; ++j) {
            int u = tid + j * 256;
            int r = u >> 4, s = u & 15;
            long g = ((long)(b * SEQ + j0 + r)) * DIMD + h * 128 + s * 8;
            uint32_t so = r * ATS + s * 16;
            cpa16(sb + O_KH + so, Kh + g);
            cpa16(sb + O_KL + so, Kl + g);
            cpa16(sb + O_VH + so, Vh + g);
            cpa16(sb + O_VL + so, Vl + g);
        }
        CP_COMMIT();
        asm volatile("cp.async.wait_group 0;" ::: "memory");
        __syncthreads();

        // ---- S = Q K^T (each warp: 16 rows x 32 cols) ----
        float sacc[4][4];
        #pragma unroll
        for (int i = 0; i < 4; ++i)
            #pragma unroll
            for (int q = 0; q < 4; ++q) sacc[i][q] = 0.f;
        #pragma unroll
        for (int kk = 0; kk < 8; ++kk) {
            uint32_t ah4[4], al4[4];
            uint32_t ra = sb + O_QH + (wr + a_row) * ATS + kk * 32 + a_kb;
            ldmx4(ah4, ra);
            ldmx4(al4, ra + (O_QL - O_QH));
            uint32_t bh4[2][4], bl4[2][4];
            #pragma unroll
            for (int p = 0; p < 2; ++p) {
                uint32_t rb = sb + O_KH + (wc * 32 + p * 16 + b_row) * ATS + kk * 32 + b_kb;
                ldmx4(bh4[p], rb);
                ldmx4(bl4[p], rb + (O_KL - O_KH));
            }
            #pragma unroll
            for (int nt = 0; nt < 4; ++nt) {
                uint32_t b0h = bh4[nt >> 1][(nt & 1) * 2 + 0];
                uint32_t b1h = bh4[nt >> 1][(nt & 1) * 2 + 1];
                uint32_t b0l = bl4[nt >> 1][(nt & 1) * 2 + 0];
                uint32_t b1l = bl4[nt >> 1][(nt & 1) * 2 + 1];
                MMA16816(sacc[nt], ah4, b0h, b1h);
                MMA16816(sacc[nt], ah4, b0l, b1l);
                MMA16816(sacc[nt], al4, b0h, b1h);
            }
        }
        #pragma unroll
        for (int nt = 0; nt < 4; ++nt) {
            int col = wc * 32 + nt * 8 + (lane & 3) * 2;
            int r0 = wr + (lane >> 2);
            Sf[r0 * 68 + col] = sacc[nt][0];
            Sf[r0 * 68 + col + 1] = sacc[nt][1];
            Sf[(r0 + 8) * 68 + col] = sacc[nt][2];
            Sf[(r0 + 8) * 68 + col + 1] = sacc[nt][3];
        }
        __syncthreads();

        // ---- softmax (4 threads per row, 16 cols each) ----
        int ig = q0 + tq;
        float sv[16], tmax = -INFINITY;
        #pragma unroll
        for (int j = 0; j < 16; ++j) {
            int col = td * 16 + j;
            int jg = j0 + col;
            bool ok = (jg <= ig) && (ig - jg < 1024);
            float s = ok ? Sf[tq * 68 + col] : -INFINITY;
            sv[j] = s;
            tmax = fmaxf(tmax, s);
        }
        tmax = fmaxf(tmax, __shfl_xor_sync(0xffffffffu, tmax, 1));
        tmax = fmaxf(tmax, __shfl_xor_sync(0xffffffffu, tmax, 2));
        float mt = fmaxf(m, tmax);
        float mte = (mt > -INFINITY) ? mt : 0.f;
        float corr = exp2f(m - mte);
        float ls = 0.f;
        #pragma unroll
        for (int j = 0; j < 16; ++j) {
            int col = td * 16 + j;
            float p = exp2f(sv[j] - mte);
            ls += p;
            __nv_bfloat16 ph = __float2bfloat16_rn(p);
            Pho[tq * 72 + col] = ph;
            Plo[tq * 72 + col] = __float2bfloat16_rn(p - __bfloat162float(ph));
        }
        ls += __shfl_xor_sync(0xffffffffu, ls, 1);
        ls += __shfl_xor_sync(0xffffffffu, ls, 2);
        lrow = lrow * corr + ls;
        m = mt;
        if (td == 0) carr[tq] = corr;
        __syncthreads();

        // ---- O = P V (each warp: 16 rows x 64 d-cols) ----
        {
            float c0 = carr[wr + (lane >> 2)];
            float c1 = carr[wr + 8 + (lane >> 2)];
            #pragma unroll
            for (int nt = 0; nt < 8; ++nt) {
                oacc[nt][0] *= c0; oacc[nt][1] *= c0;
                oacc[nt][2] *= c1; oacc[nt][3] *= c1;
            }
        }
        #pragma unroll
        for (int ktile = 0; ktile < 4; ++ktile) {
            uint32_t ph4[4], pl4[4];
            uint32_t ra = sb + O_PH + (wr + a_row) * PST + ktile * 32 + a_kb;
            ldmx4(ph4, ra);
            ldmx4(pl4, ra + (O_PL - O_PH));
            #pragma unroll
            for (int p2 = 0; p2 < 4; ++p2) {
                uint32_t vh4[4], vl4[4];
                uint32_t rb = sb + O_VH + (ktile * 16 + b_kr) * ATS + (wc * 64 + p2 * 16 + b_no) * 2;
                ldmx4t(vh4, rb);
                ldmx4t(vl4, rb + (O_VL - O_VH));
                #pragma unroll
                for (int sub = 0; sub < 2; ++sub) {
                    int nt = p2 * 2 + sub;
                    uint32_t b0h = vh4[sub * 2], b1h = vh4[sub * 2 + 1];
                    uint32_t b0l = vl4[sub * 2], b1l = vl4[sub * 2 + 1];
                    MMA16816(oacc[nt], ph4, b0h, b1h);
                    MMA16816(oacc[nt], ph4, b0l, b1l);
                    MMA16816(oacc[nt], pl4, b0h, b1h);
                }
            }
        }
    }
    if (td == 0) larr[tq] = lrow;
    __syncthreads();
    {
        int r0 = wr + (lane >> 2);
        float l0 = 1.f / larr[r0], l1 = 1.f / larr[r0 + 8];
        #pragma unroll
        for (int nt = 0; nt < 8; ++nt) {
            int col = wc * 64 + nt * 8 + (lane & 3) * 2;
            long o0 = ((long)(b * SEQ + q0 + r0)) * 2048 + h * 128 + col;
            long o1 = ((long)(b * SEQ + q0 + r0 + 8)) * 2048 + h * 128 + col;
            *(float2*)(O + o0) = make_float2(oacc[nt][0] * l0, oacc[nt][1] * l0);
            *(float2*)(O + o1) = make_float2(oacc[nt][2] * l1, oacc[nt][3] * l1);
        }
    }
}

// --------------------------- TTT helper kernels -----------------------------
__global__ void copyw(const float* __restrict__ w0, const float* __restrict__ w1,
                      const float* __restrict__ w2,
                      float* __restrict__ o02, __nv_bfloat16* __restrict__ o02h,
                      __nv_bfloat16* __restrict__ o02l,
                      float* __restrict__ o1, __nv_bfloat16* __restrict__ o1h,
                      __nv_bfloat16* __restrict__ o1l)
{
    long idx = (long)blockIdx.x * 256 + threadIdx.x;
    int col = idx & 511;
    int row = (idx >> 9) & 1023;
    int h = (idx >> 19) & 3;
    long src = (long)h * 262144 + (long)(row & 511) * 512 + col;
    float v = (row < 512) ? w0[src] : w2[src];
    o02[idx] = v;
    split_w(v, o02h, o02l, idx);
    if (idx < (long)2 * 1024 * 1024) {
        float v1 = w1[idx & ((long)4 * 262144 - 1)];
        o1[idx] = v1;
        split_w(v1, o1h, o1l, idx);
    }
}

__global__ void elem2(const float* __restrict__ fv, const float* __restrict__ lr,
                      const float* __restrict__ gh, const float* __restrict__ dhin,
                      __nv_bfloat16* __restrict__ dgph, __nv_bfloat16* __restrict__ dgpl,
                      __nv_bfloat16* __restrict__ vlh, __nv_bfloat16* __restrict__ vll,
                      __nv_bfloat16* __restrict__ hth, __nv_bfloat16* __restrict__ htl,
                      int ck0)
{
    long idx = (long)blockIdx.x * 256 + threadIdx.x;
    int col = idx & 511;
    long tt = idx >> 9;
    int c = tt & 1023, bh = tt >> 10;
    int b = bh >> 2, h = bh & 3;
    long row = (long)b * SEQ + ck0 + c;
    float l0 = lr[row * 12 + h], l1 = lr[row * 12 + 4 + h], l2 = lr[row * 12 + 8 + h];
    long gi = (long)bh * 1048576 + (long)c * 1024 + col;
    float g = gh[gi], hp = gh[gi + 512], d = dhin[idx];
    float sig = 1.f / (1.f + expf(-g));
    float sg = g * sig;
    split_w(sg * hp, hth, htl, idx);
    float v = fv[((long)bh * SEQ + ck0 + c) * FDM + col];
    split_w(d * hp * (sig * (1.f + g * (1.f - sig))) * l0, dgph, dgpl, gi);
    split_w(d * sg * l2, dgph, dgpl, gi + 512);
    split_w(v * l1, vlh, vll, idx);
}

__global__ void elem3(const float* __restrict__ gh,
                      __nv_bfloat16* __restrict__ hnh, __nv_bfloat16* __restrict__ hnl)
{
    long idx = (long)blockIdx.x * 256 + threadIdx.x;
    int col = idx & 511;
    long tt = idx >> 9;
    int c = tt & 1023, bh = tt >> 10;
    long gi = (long)bh * 1048576 + (long)c * 1024 + col;
    float g = gh[gi];
    split_w((g / (1.f + expf(-g))) * gh[gi + 512], hnh, hnl, idx);
}

// -------------------- ttt rmsnorm + add attention result --------------------
__global__ void post_kernel(const float* __restrict__ ttt, const float* __restrict__ tw,
                            const float* __restrict__ sum,
                            __nv_bfloat16* __restrict__ smh, __nv_bfloat16* __restrict__ sml)
{
    __shared__ float sr[4];
    int fh = blockIdx.x, row = blockIdx.y;
    int b = row >> 11, t = row & 2047;
    int bh = b * 4 + fh;
    const float* src = ttt + ((long)bh * SEQ + t) * FDM;
    int tid = threadIdx.x;
    float v[4], ss = 0.f;
    #pragma unroll
    for (int j = 0; j < 4; ++j) { v[j] = src[tid + 128 * j]; ss += v[j] * v[j]; }
    #pragma unroll
    for (int o = 16; o > 0; o >>= 1) ss += __shfl_down_sync(0xffffffffu, ss, o);
    if ((tid & 31) == 0) sr[tid >> 5] = ss;
    __syncthreads();
    float tot = sr[0] + sr[1] + sr[2] + sr[3];
    float r = rsqrtf(tot * (1.f / 512.f) + 1e-6f);
    #pragma unroll
    for (int j = 0; j < 4; ++j) {
        int i = tid + 128 * j;
        long o = (long)row * 2048 + fh * 512 + i;
        split_w(sum[o] + v[j] * r * tw[i], smh, sml, o);
    }
}

// --------------------------------- launch -----------------------------------
#define GSYM(p, s) cudaGetSymbolAddress((void**)&(p), s)

extern "C" void kernel_launch(void* const* d_in, const int* in_sizes, int n_in,
                              void* d_out, int out_size)
{
    const float* hidden = (const float*)d_in[0];
    const float* Wqkv   = (const float*)d_in[1];
    const float* Wo     = (const float*)d_in[2];
    const float* qnw    = (const float*)d_in[3];
    const float* knw    = (const float*)d_in[4];
    const float* w0     = (const float*)d_in[5];
    const float* w1     = (const float*)d_in[6];
    const float* w2     = (const float*)d_in[7];
    const float* lrw    = (const float*)d_in[8];
    const float* lrb    = (const float*)d_in[9];
    const float* qksc   = (const float*)d_in[10];
    const float* qkof   = (const float*)d_in[11];
    const float* tttw   = (const float*)d_in[12];
    float* out = (float*)d_out;

    float *qkv, *lrpre, *lr, *fv, *pw02, *pw1, *gh, *dh, *ttt, *sum;
    GSYM(qkv, g_qkv);   GSYM(lrpre, g_lrpre); GSYM(lr, g_lr);
    GSYM(fv, g_fv);
    GSYM(pw02, g_w02);  GSYM(pw1, g_w1);
    GSYM(gh, g_gh);     GSYM(dh, g_dh);
    GSYM(ttt, g_ttt);   GSYM(sum, g_sum);

    __nv_bfloat16 *hxh,*hxl,*wqh,*wql,*woh,*wol,*aqh,*aql,*akh,*akl,*avh,*avl;
    __nv_bfloat16 *fqh,*fql,*fkh,*fkl,*fvh,*fvl;
    __nv_bfloat16 *w02h,*w02l,*w1h,*w1l,*dgph,*dgpl,*vlh,*vll,*hth,*htl,*hnh,*hnl,*smh,*sml;
    GSYM(hxh, g_hx_h); GSYM(hxl, g_hx_l); GSYM(wqh, g_wq_h); GSYM(wql, g_wq_l);
    GSYM(woh, g_wo_h); GSYM(wol, g_wo_l);
    GSYM(aqh, g_aq_h); GSYM(aql, g_aq_l); GSYM(akh, g_ak_h); GSYM(akl, g_ak_l);
    GSYM(avh, g_av_h); GSYM(avl, g_av_l);
    GSYM(fqh, g_fq_h); GSYM(fql, g_fq_l); GSYM(fkh, g_fk_h); GSYM(fkl, g_fk_l);
    GSYM(fvh, g_fv_h); GSYM(fvl, g_fv_l);
    GSYM(w02h, g_w02_h); GSYM(w02l, g_w02_l);
    GSYM(w1h, g_w1_h); GSYM(w1l, g_w1_l);
    GSYM(dgph, g_dgp_h); GSYM(dgpl, g_dgp_l);
    GSYM(vlh, g_vl_h); GSYM(vll, g_vl_l); GSYM(hth, g_ht_h); GSYM(htl, g_ht_l);
    GSYM(hnh, g_hn_h); GSYM(hnl, g_hn_l); GSYM(smh, g_sm_h); GSYM(sml, g_sm_l);

    cudaFuncSetAttribute(mma_gemm<0,0,false,false>,
                         cudaFuncAttributeMaxDynamicSharedMemorySize, 81920);
    cudaFuncSetAttribute(mma_gemm<0,1,false,false>,
                         cudaFuncAttributeMaxDynamicSharedMemorySize, 75776);
    cudaFuncSetAttribute(mma_gemm<1,1,true,true>,
                         cudaFuncAttributeMaxDynamicSharedMemorySize, 69632);
    cudaFuncSetAttribute(attn_mma, cudaFuncAttributeMaxDynamicSharedMemorySize, ATTN_SMEM);

    #define G_NT(Ah,Al,Bh,Bl,C,M,N,K,lda,ldb,sA,sB,sC,bat) \
        mma_gemm<0,0,false,false><<<dim3((N)/128,(M)/128,(bat)),256,81920>>>( \
            Ah,Al,Bh,Bl,C,nullptr,nullptr,M,N,K,lda,ldb,sA,sB,sC)
    #define G_NN(Ah,Al,Bh,Bl,C,M,N,K,lda,ldb,sA,sB,sC,bat) \
        mma_gemm<0,1,false,false><<<dim3((N)/128,(M)/128,(bat)),256,75776>>>( \
            Ah,Al,Bh,Bl,C,nullptr,nullptr,M,N,K,lda,ldb,sA,sB,sC)
    #define G_TN_AS(Ah,Al,Bh,Bl,C,Ch,Cl,M,N,K,lda,ldb,sA,sB,sC,bat) \
        mma_gemm<1,1,true,true><<<dim3((N)/128,(M)/128,(bat)),256,69632>>>( \
            Ah,Al,Bh,Bl,C,Ch,Cl,M,N,K,lda,ldb,sA,sB,sC)

    cvt_hl<<<8192, 256>>>(hidden, hxh, hxl, (long)4096 * 2048);
    cvt_hl<<<12288, 256>>>(Wqkv, wqh, wql, (long)6144 * 2048);
    cvt_hl<<<4096, 256>>>(Wo, woh, wol, (long)2048 * 2048);

    G_NT(hxh, hxl, wqh, wql, qkv, 4096, 6144, 2048, 2048, 2048, 0, 0, 0, 1);
    lr_gemm<<<2048, 256>>>(hidden, lrw, lrpre);

    float base = (float)(0.001 + log(-expm1(-0.001)));
    prep_kernel<<<4096, 256>>>(qkv, lrpre, qnw, knw, qksc, qkof, lrb, base,
                               aqh, aql, akh, akl, avh, avl,
                               fqh, fql, fkh, fkl, fvh, fvl, fv, lr);
    attn_mma<<<dim3(32, 16, 2), 256, ATTN_SMEM>>>(aqh, aql, akh, akl, avh, avl, sum);

    copyw<<<16384, 256>>>(w0, w1, w2, pw02, w02h, w02l, pw1, w1h, w1l);

    long sSeq = (long)SEQ * FDM;
    long sChk = (long)1024 * FDM;
    long sW   = (long)FDM * FDM;
    long sW02 = (long)1024 * FDM;
    long sGH  = (long)1024 * 1024;
    for (int ck = 0; ck < 2; ++ck) {
        int ck0 = ck * 1024;
        long co = (long)ck0 * FDM;
        G_NT(fkh + co, fkl + co, w02h, w02l, gh, 1024, 1024, 512,
             512, 512, sSeq, sW02, sGH, 8);
        G_NN(fvh + co, fvl + co, w1h, w1l, dh, 1024, 512, 512,
             512, 512, sSeq, sW, sChk, 8);
        elem2<<<16384, 256>>>(fv, lr, gh, dh, dgph, dgpl, vlh, vll, hth, htl, ck0);
        G_TN_AS(dgph, dgpl, fkh + co, fkl + co, pw02, w02h, w02l,
                1024, 512, 1024, 1024, 512, sGH, sSeq, sW02, 8);
        G_TN_AS(vlh, vll, hth, htl, pw1, w1h, w1l,
                512, 512, 1024, 512, 512, sChk, sChk, sW, 8);
        G_NT(fqh + co, fql + co, w02h, w02l, gh, 1024, 1024, 512,
             512, 512, sSeq, sW02, sGH, 8);
        elem3<<<16384, 256>>>(gh, hnh, hnl);
        G_NT(hnh, hnl, w1h, w1l, ttt + co, 1024, 512, 512,
             512, 512, sChk, sW, sSeq, 8);
    }

    post_kernel<<<dim3(4, 4096), 128>>>(ttt, tttw, sum, smh, sml);
    G_NT(smh, sml, woh, wol, out, 4096, 2048, 2048, 2048, 2048, 0, 0, 0, 1);
    #undef G_NT
    #undef G_NN
    #undef G_TN_AS
}

// round 10
// speedup vs baseline: 6.3559x; 1.2372x over previous
#include <cuda_runtime.h>
#include <cuda_bf16.h>
#include <cstdint>
#include <math.h>

#define SEQ 2048
#define DIMD 2048
#define FDM 512

// ------------------------- fp32 scratch (device globals) --------------------
__device__ float g_qkv [(size_t)4096 * 6144];
__device__ float g_lrpre[(size_t)4096 * 12];
__device__ float g_lr  [(size_t)4096 * 12];
__device__ float g_w02 [(size_t)8 * 1024 * FDM];
__device__ float g_w1  [(size_t)8 * FDM * FDM];
__device__ float g_gh  [(size_t)8 * 1024 * 1024];
__device__ float g_dh  [(size_t)8 * 1024 * FDM];
__device__ float g_ttt [(size_t)8 * SEQ * FDM];
__device__ float g_sum [(size_t)4096 * 2048];

// ---------------------- tf32 (pre-rounded fp32) operands --------------------
__device__ float g_hx_t [(size_t)4096 * 2048];
__device__ float g_wq_t [(size_t)6144 * 2048];
__device__ float g_wo_t [(size_t)2048 * 2048];
__device__ float g_fq_t [(size_t)8 * SEQ * FDM];
__device__ float g_fk_t [(size_t)8 * SEQ * FDM];
__device__ float g_fv_t [(size_t)8 * SEQ * FDM];
__device__ float g_w02_t[(size_t)8 * 1024 * FDM];
__device__ float g_w1_t [(size_t)8 * FDM * FDM];
__device__ float g_dgp_t[(size_t)8 * 1024 * 1024];
__device__ float g_vl_t [(size_t)8 * 1024 * FDM];
__device__ float g_ht_t [(size_t)8 * 1024 * FDM];
__device__ float g_hn_t [(size_t)8 * 1024 * FDM];
__device__ float g_sm_t [(size_t)4096 * 2048];

// ------------------- bf16 hi/lo (attention only) ----------------------------
__device__ __nv_bfloat16 g_aq_h[(size_t)4096*2048], g_aq_l[(size_t)4096*2048];
__device__ __nv_bfloat16 g_ak_h[(size_t)4096*2048], g_ak_l[(size_t)4096*2048];
__device__ __nv_bfloat16 g_av_h[(size_t)4096*2048], g_av_l[(size_t)4096*2048];

// ------------------------------ helpers -------------------------------------
__device__ __forceinline__ uint32_t smem_u32(const void* p) {
    uint32_t a;
    asm("{ .reg .u64 t; cvta.to.shared.u64 t, %1; cvt.u32.u64 %0, t; }" : "=r"(a) : "l"(p));
    return a;
}
__device__ __forceinline__ void cpa16(uint32_t s, const void* g) {
    asm volatile("cp.async.cg.shared.global [%0], [%1], 16;" :: "r"(s), "l"(g));
}
#define CP_COMMIT() asm volatile("cp.async.commit_group;" ::: "memory")
#define MMA16816(d, a, b0, b1) \
    asm volatile("mma.sync.aligned.m16n8k16.row.col.f32.bf16.bf16.f32 " \
        "{%0,%1,%2,%3}, {%4,%5,%6,%7}, {%8,%9}, {%0,%1,%2,%3};" \
        : "+f"((d)[0]), "+f"((d)[1]), "+f"((d)[2]), "+f"((d)[3]) \
        : "r"((a)[0]), "r"((a)[1]), "r"((a)[2]), "r"((a)[3]), "r"(b0), "r"(b1))
#define MMATF(d, a, b0, b1) \
    asm volatile("mma.sync.aligned.m16n8k8.row.col.f32.tf32.tf32.f32 " \
        "{%0,%1,%2,%3}, {%4,%5,%6,%7}, {%8,%9}, {%0,%1,%2,%3};" \
        : "+f"((d)[0]), "+f"((d)[1]), "+f"((d)[2]), "+f"((d)[3]) \
        : "r"((a)[0]), "r"((a)[1]), "r"((a)[2]), "r"((a)[3]), "r"(b0), "r"(b1))
__device__ __forceinline__ void ldmx4(uint32_t* r, uint32_t addr) {
    asm volatile("ldmatrix.sync.aligned.m8n8.x4.shared.b16 {%0,%1,%2,%3}, [%4];"
        : "=r"(r[0]), "=r"(r[1]), "=r"(r[2]), "=r"(r[3]) : "r"(addr));
}
__device__ __forceinline__ void ldmx4t(uint32_t* r, uint32_t addr) {
    asm volatile("ldmatrix.sync.aligned.m8n8.x4.trans.shared.b16 {%0,%1,%2,%3}, [%4];"
        : "=r"(r[0]), "=r"(r[1]), "=r"(r[2]), "=r"(r[3]) : "r"(addr));
}
__device__ __forceinline__ void split_w(float v, __nv_bfloat16* h, __nv_bfloat16* l, long i) {
    __nv_bfloat16 hv = __float2bfloat16_rn(v);
    h[i] = hv;
    l[i] = __float2bfloat16_rn(v - __bfloat162float(hv));
}
__device__ __forceinline__ float to_tf32(float v) {
    uint32_t u;
    asm("cvt.rna.tf32.f32 %0, %1;" : "=r"(u) : "f"(v));
    return __uint_as_float(u);
}
__device__ __forceinline__ uint32_t lds_u32(uint32_t addr) {
    uint32_t v;
    asm volatile("ld.shared.b32 %0, [%1];" : "=r"(v) : "r"(addr));
    return v;
}

// -------------------- TF32 mma.sync batched GEMM ----------------------------
// AT=0: A stored [M,K]; AT=1: A stored [K,M].  BT likewise for B.
// C[M,N] (+)= sum_k Aop[m,k]*Bop[n,k]; SPLIT also writes tf32-rounded copy Ct.
// Operands MUST be pre-rounded to tf32 (cvt.rna) by their producers.
template<int AT, int BT, bool ACC, bool SPLIT>
__global__ void __launch_bounds__(256, 2)
tf_gemm(const float* __restrict__ A, const float* __restrict__ B,
        float* __restrict__ C, float* __restrict__ Ct,
        int M, int N, int K, int lda, int ldb, long sA, long sB, long sC)
{
    constexpr int SA = AT ? 17408 : 18432;   // trans: 32*544 ; k-major: 128*144
    constexpr int SB = BT ? 17408 : 18432;
    constexpr int STAGE = SA + SB;
    extern __shared__ char smem[];
    uint32_t sb = smem_u32(smem);
    int tid = threadIdx.x, lane = tid & 31, wid = tid >> 5;
    int wm = wid >> 2, wn = wid & 3;
    long zb = blockIdx.z;
    const float* a = A + zb * sA;
    const float* b = B + zb * sB;
    int m0 = blockIdx.y << 7, n0 = blockIdx.x << 7;

    float acc[4][4][4];
    #pragma unroll
    for (int i = 0; i < 4; ++i)
        #pragma unroll
        for (int j = 0; j < 4; ++j)
            #pragma unroll
            for (int q = 0; q < 4; ++q) acc[i][j][q] = 0.f;

    auto issue = [&](int buf, int k0) {
        uint32_t st = sb + buf * STAGE;
        #pragma unroll
        for (int j = 0; j < 4; ++j) {
            int u = tid + j * 256;
            uint32_t so; long g;
            if (AT == 0) { int r = u >> 3, s = u & 7;  so = r * 144 + s * 16;
                           g = (long)(m0 + r) * lda + k0 + s * 4; }
            else         { int r = u >> 5, s = u & 31; so = r * 544 + s * 16;
                           g = (long)(k0 + r) * lda + m0 + s * 4; }
            cpa16(st + so, a + g);
            if (BT == 0) { int r = u >> 3, s = u & 7;  so = r * 144 + s * 16;
                           g = (long)(n0 + r) * ldb + k0 + s * 4; }
            else         { int r = u >> 5, s = u & 31; so = r * 544 + s * 16;
                           g = (long)(k0 + r) * ldb + n0 + s * 4; }
            cpa16(st + SA + so, b + g);
        }
        CP_COMMIT();
    };

    const int n = K >> 5;
    issue(0, 0);
    int buf = 0;
    for (int i = 0; i < n; ++i) {
        if (i + 1 < n) {
            issue(buf ^ 1, (i + 1) * 32);
            asm volatile("cp.async.wait_group 1;" ::: "memory");
        } else {
            asm volatile("cp.async.wait_group 0;" ::: "memory");
        }
        __syncthreads();
        uint32_t st = sb + buf * STAGE;
        uint32_t stB = st + SA;
        #pragma unroll
        for (int kk = 0; kk < 32; kk += 8) {
            uint32_t af[4][4];
            #pragma unroll
            for (int mt = 0; mt < 4; ++mt) {
                if (AT == 0) {
                    uint32_t ra = st + (wm * 64 + mt * 16 + (lane >> 2)) * 144
                                + (kk + (lane & 3)) * 4;
                    af[mt][0] = lds_u32(ra);
                    af[mt][1] = lds_u32(ra + 8 * 144);
                    af[mt][2] = lds_u32(ra + 16);
                    af[mt][3] = lds_u32(ra + 8 * 144 + 16);
                } else {
                    uint32_t ra = st + (kk + (lane & 3)) * 544
                                + (wm * 64 + mt * 16 + (lane >> 2)) * 4;
                    af[mt][0] = lds_u32(ra);
                    af[mt][1] = lds_u32(ra + 32);
                    af[mt][2] = lds_u32(ra + 4 * 544);
                    af[mt][3] = lds_u32(ra + 4 * 544 + 32);
                }
            }
            uint32_t bf_[4][2];
            #pragma unroll
            for (int nt = 0; nt < 4; ++nt) {
                if (BT == 0) {
                    uint32_t rb = stB + (wn * 32 + nt * 8 + (lane >> 2)) * 144
                                + (kk + (lane & 3)) * 4;
                    bf_[nt][0] = lds_u32(rb);
                    bf_[nt][1] = lds_u32(rb + 16);
                } else {
                    uint32_t rb = stB + (kk + (lane & 3)) * 544
                                + (wn * 32 + nt * 8 + (lane >> 2)) * 4;
                    bf_[nt][0] = lds_u32(rb);
                    bf_[nt][1] = lds_u32(rb + 4 * 544);
                }
            }
            #pragma unroll
            for (int nt = 0; nt < 4; ++nt)
                #pragma unroll
                for (int mt = 0; mt < 4; ++mt)
                    MMATF(acc[mt][nt], af[mt], bf_[nt][0], bf_[nt][1]);
        }
        __syncthreads();
        buf ^= 1;
    }
    float* c = C + zb * sC;
    float* ct = SPLIT ? Ct + zb * sC : nullptr;
    #pragma unroll
    for (int mt = 0; mt < 4; ++mt) {
        #pragma unroll
        for (int nt = 0; nt < 4; ++nt) {
            long r0 = m0 + wm * 64 + mt * 16 + (lane >> 2);
            int  cc = n0 + wn * 32 + nt * 8 + (lane & 3) * 2;
            long o0 = r0 * (long)N + cc;
            long o1 = (r0 + 8) * (long)N + cc;
            float v00 = acc[mt][nt][0], v01 = acc[mt][nt][1];
            float v10 = acc[mt][nt][2], v11 = acc[mt][nt][3];
            if (ACC) {
                float2 t0 = *(float2*)(c + o0), t1 = *(float2*)(c + o1);
                v00 += t0.x; v01 += t0.y; v10 += t1.x; v11 += t1.y;
            }
            *(float2*)(c + o0) = make_float2(v00, v01);
            *(float2*)(c + o1) = make_float2(v10, v11);
            if (SPLIT) {
                *(float2*)(ct + o0) = make_float2(to_tf32(v00), to_tf32(v01));
                *(float2*)(ct + o1) = make_float2(to_tf32(v10), to_tf32(v11));
            }
        }
    }
}

// ------------------------ conversion kernel ---------------------------------
__global__ void cvt_tf(const float* __restrict__ x, float* __restrict__ o, long n)
{
    long i = ((long)blockIdx.x * 256 + threadIdx.x) * 4;
    if (i >= n) return;
    float4 v = *(const float4*)(x + i);
    float4 w;
    w.x = to_tf32(v.x); w.y = to_tf32(v.y); w.z = to_tf32(v.z); w.w = to_tf32(v.w);
    *(float4*)(o + i) = w;
}

// ---------------- small SGEMM for the N=12 lr GEMM --------------------------
__global__ void lr_gemm(const float* __restrict__ A, const float* __restrict__ B,
                        float* __restrict__ C)
{
    __shared__ float bs[12][128];
    int row = blockIdx.x * 2 + (threadIdx.x >> 7);
    int tid = threadIdx.x & 127;
    float acc[12];
    #pragma unroll
    for (int c = 0; c < 12; ++c) acc[c] = 0.f;
    for (int k0 = 0; k0 < 2048; k0 += 128) {
        if (threadIdx.x < 128)
            #pragma unroll
            for (int c = 0; c < 12; ++c) bs[c][tid] = B[c * 2048 + k0 + tid];
        __syncthreads();
        float a = A[(long)row * 2048 + k0 + tid];
        #pragma unroll
        for (int c = 0; c < 12; ++c) acc[c] += a * bs[c][tid];
        __syncthreads();
    }
    __shared__ float red[2][12][4];
    #pragma unroll
    for (int c = 0; c < 12; ++c) {
        float v = acc[c];
        #pragma unroll
        for (int o = 16; o > 0; o >>= 1) v += __shfl_down_sync(0xffffffffu, v, o);
        if ((tid & 31) == 0) red[threadIdx.x >> 7][c][tid >> 5] = v;
    }
    __syncthreads();
    if (tid < 12) {
        int w = threadIdx.x >> 7;
        C[(long)row * 12 + tid] = red[w][tid][0] + red[w][tid][1] + red[w][tid][2] + red[w][tid][3];
    }
}

// ------------------------- block reduce (256 thr) ---------------------------
__device__ __forceinline__ float blockReduceSum(float v, float* sred)
{
    int lane = threadIdx.x & 31;
    #pragma unroll
    for (int o = 16; o > 0; o >>= 1) v += __shfl_down_sync(0xffffffffu, v, o);
    if (lane == 0) sred[threadIdx.x >> 5] = v;
    __syncthreads();
    if (threadIdx.x < 8) {
        float r = sred[threadIdx.x];
        #pragma unroll
        for (int o = 4; o > 0; o >>= 1) r += __shfl_down_sync(0xffu, r, o);
        if (threadIdx.x == 0) sred[0] = r;
    }
    __syncthreads();
    float out = sred[0];
    __syncthreads();
    return out;
}

// --------- prep: rmsnorm+rope + silu/L2 + lr ---------------------------------
__global__ void prep_kernel(const float* __restrict__ qkv, const float* __restrict__ lrpre,
                            const float* __restrict__ qnw, const float* __restrict__ knw,
                            const float* __restrict__ qksc, const float* __restrict__ qkof,
                            const float* __restrict__ lrb, float base_lr_inv,
                            __nv_bfloat16* __restrict__ aqh, __nv_bfloat16* __restrict__ aql,
                            __nv_bfloat16* __restrict__ akh, __nv_bfloat16* __restrict__ akl,
                            __nv_bfloat16* __restrict__ avh, __nv_bfloat16* __restrict__ avl,
                            float* __restrict__ fqt, float* __restrict__ fkt,
                            float* __restrict__ fvt, float* __restrict__ lrout)
{
    __shared__ float s_q[2048];
    __shared__ float s_k[2048];
    __shared__ float sred[8];
    int row = blockIdx.x;
    int b = row >> 11, t = row & 2047;
    int tid = threadIdx.x;
    const float* qr = qkv + (long)row * 6144;
    const float* kr = qr + 2048;
    const float* vr = qr + 4096;
    const float qscale = 0.088388347648318447f * 1.4426950408889634f;

    float qv[8], kv[8], fqv[8], fkv[8], fvv[8];
    float sq = 0.f, sk = 0.f;
    float p2q[4] = {0, 0, 0, 0}, p2k[4] = {0, 0, 0, 0};
    #pragma unroll
    for (int j = 0; j < 8; ++j) {
        int i = j * 256 + tid;
        float q = qr[i], k = kr[i], v = vr[i];
        qv[j] = q; kv[j] = k;
        sq += q * q; sk += k * k;
        float fqe = (q / (1.f + expf(-q))) * qksc[i * 2 + 0] + qkof[i * 2 + 0];
        float fke = (k / (1.f + expf(-k))) * qksc[i * 2 + 1] + qkof[i * 2 + 1];
        fqv[j] = fqe; fkv[j] = fke; fvv[j] = v / (1.f + expf(-v));
        p2q[j >> 1] += fqe * fqe;
        p2k[j >> 1] += fke * fke;
        split_w(v, avh, avl, (long)row * DIMD + i);
    }
    float SQ = blockReduceSum(sq, sred);
    float SK = blockReduceSum(sk, sred);
    float G2Q[4], G2K[4];
    #pragma unroll
    for (int g = 0; g < 4; ++g) G2Q[g] = blockReduceSum(p2q[g], sred);
    #pragma unroll
    for (int g = 0; g < 4; ++g) G2K[g] = blockReduceSum(p2k[g], sred);
    float rq = rsqrtf(SQ * (1.f / 2048.f) + 1e-6f);
    float rk = rsqrtf(SK * (1.f / 2048.f) + 1e-6f);
    #pragma unroll
    for (int j = 0; j < 8; ++j) {
        int i = j * 256 + tid;
        s_q[i] = qv[j] * rq * qnw[i];
        s_k[i] = kv[j] * rk * knw[i];
        int g = j >> 1;
        long fb = (((long)(b * 4 + g)) * SEQ + t) * FDM + (i & 511);
        fqt[fb] = to_tf32(fqv[j] / (sqrtf(G2Q[g]) + 1e-12f));
        fkt[fb] = to_tf32(fkv[j] / (sqrtf(G2K[g]) + 1e-12f));
        fvt[fb] = to_tf32(fvv[j]);
    }
    __syncthreads();
    #pragma unroll
    for (int j = 0; j < 8; ++j) {
        int i = j * 256 + tid;
        int pos = i & 127;
        int fi = pos & 63;
        float invf = expf(-(float)fi * (logf(500000.f) / 64.f));
        float sn, cs;
        sincosf((float)t * invf, &sn, &cs);
        float oq, ok_;
        if (pos < 64) {
            oq  = s_q[i] * cs - s_q[i + 64] * sn;
            ok_ = s_k[i] * cs - s_k[i + 64] * sn;
        } else {
            oq  = s_q[i] * cs + s_q[i - 64] * sn;
            ok_ = s_k[i] * cs + s_k[i - 64] * sn;
        }
        split_w(oq * qscale, aqh, aql, (long)row * DIMD + i);
        split_w(ok_, akh, akl, (long)row * DIMD + i);
    }
    if (tid < 12) {
        float x = lrpre[(long)row * 12 + tid] + lrb[tid] + base_lr_inv;
        lrout[(long)row * 12 + tid] = (x > 20.f) ? x : log1pf(expf(x));
    }
}

// -------------------- HMMA windowed flash attention (unchanged) --------------
#define ATS 272
#define PST 144
#define O_QH 0
#define O_QL 17408
#define O_KH 34816
#define O_KL 52224
#define O_VH 69632
#define O_VL 87040
#define O_S  104448
#define O_PH 121856
#define O_PL 131072
#define O_CR 140288
#define O_LR 140544
#define ATTN_SMEM 140800

__global__ void __launch_bounds__(256, 1)
attn_mma(const __nv_bfloat16* __restrict__ Qh, const __nv_bfloat16* __restrict__ Ql,
         const __nv_bfloat16* __restrict__ Kh, const __nv_bfloat16* __restrict__ Kl,
         const __nv_bfloat16* __restrict__ Vh, const __nv_bfloat16* __restrict__ Vl,
         float* __restrict__ O)
{
    extern __shared__ char smc[];
    uint32_t sb = smem_u32(smc);
    float* Sf = (float*)(smc + O_S);
    float* carr = (float*)(smc + O_CR);
    float* larr = (float*)(smc + O_LR);
    __nv_bfloat16* Pho = (__nv_bfloat16*)(smc + O_PH);
    __nv_bfloat16* Plo = (__nv_bfloat16*)(smc + O_PL);

    int tid = threadIdx.x, lane = tid & 31, wid = tid >> 5;
    int q0 = blockIdx.x << 6, h = blockIdx.y, b = blockIdx.z;
    int wr = (wid & 3) * 16;
    int wc = wid >> 2;
    uint32_t a_row = (lane & 7) + ((lane >> 3) & 1) * 8;
    uint32_t a_kb  = ((lane >> 4) & 1) * 16;
    uint32_t b_row = (lane & 7) + ((lane >> 4) & 1) * 8;
    uint32_t b_kb  = ((lane >> 3) & 1) * 16;
    uint32_t b_kr  = (lane & 7) + ((lane >> 3) & 1) * 8;
    uint32_t b_no  = ((lane >> 4) & 1) * 8;
    int tq = tid >> 2, td = tid & 3;

    #pragma unroll
    for (int j = 0; j < 4; ++j) {
        int u = tid + j * 256;
        int r = u >> 4, s = u & 15;
        long g = ((long)(b * SEQ + q0 + r)) * DIMD + h * 128 + s * 8;
        cpa16(sb + O_QH + r * ATS + s * 16, Qh + g);
        cpa16(sb + O_QL + r * ATS + s * 16, Ql + g);
    }
    CP_COMMIT();

    float oacc[8][4];
    #pragma unroll
    for (int i = 0; i < 8; ++i)
        #pragma unroll
        for (int q = 0; q < 4; ++q) oacc[i][q] = 0.f;
    float m = -INFINITY, lrow = 0.f;

    int kt_hi = q0 >> 6;
    int kt_lo = (q0 >= 1024) ? ((q0 - 1023) >> 6) : 0;
    for (int kt = kt_lo; kt <= kt_hi; ++kt) {
        int j0 = kt << 6;
        __syncthreads();
        #pragma unroll
        for (int j = 0; j < 4; ++j) {
            int u = tid + j * 256;
            int r = u >> 4, s = u & 15;
            long g = ((long)(b * SEQ + j0 + r)) * DIMD + h * 128 + s * 8;
            uint32_t so = r * ATS + s * 16;
            cpa16(sb + O_KH + so, Kh + g);
            cpa16(sb + O_KL + so, Kl + g);
            cpa16(sb + O_VH + so, Vh + g);
            cpa16(sb + O_VL + so, Vl + g);
        }
        CP_COMMIT();
        asm volatile("cp.async.wait_group 0;" ::: "memory");
        __syncthreads();

        float sacc[4][4];
        #pragma unroll
        for (int i = 0; i < 4; ++i)
            #pragma unroll
            for (int q = 0; q < 4; ++q) sacc[i][q] = 0.f;
        #pragma unroll
        for (int kk = 0; kk < 8; ++kk) {
            uint32_t ah4[4], al4[4];
            uint32_t ra = sb + O_QH + (wr + a_row) * ATS + kk * 32 + a_kb;
            ldmx4(ah4, ra);
            ldmx4(al4, ra + (O_QL - O_QH));
            uint32_t bh4[2][4], bl4[2][4];
            #pragma unroll
            for (int p = 0; p < 2; ++p) {
                uint32_t rb = sb + O_KH + (wc * 32 + p * 16 + b_row) * ATS + kk * 32 + b_kb;
                ldmx4(bh4[p], rb);
                ldmx4(bl4[p], rb + (O_KL - O_KH));
            }
            #pragma unroll
            for (int nt = 0; nt < 4; ++nt) {
                uint32_t b0h = bh4[nt >> 1][(nt & 1) * 2 + 0];
                uint32_t b1h = bh4[nt >> 1][(nt & 1) * 2 + 1];
                uint32_t b0l = bl4[nt >> 1][(nt & 1) * 2 + 0];
                uint32_t b1l = bl4[nt >> 1][(nt & 1) * 2 + 1];
                MMA16816(sacc[nt], ah4, b0h, b1h);
                MMA16816(sacc[nt], ah4, b0l, b1l);
                MMA16816(sacc[nt], al4, b0h, b1h);
            }
        }
        #pragma unroll
        for (int nt = 0; nt < 4; ++nt) {
            int col = wc * 32 + nt * 8 + (lane & 3) * 2;
            int r0 = wr + (lane >> 2);
            Sf[r0 * 68 + col] = sacc[nt][0];
            Sf[r0 * 68 + col + 1] = sacc[nt][1];
            Sf[(r0 + 8) * 68 + col] = sacc[nt][2];
            Sf[(r0 + 8) * 68 + col + 1] = sacc[nt][3];
        }
        __syncthreads();

        int ig = q0 + tq;
        float sv[16], tmax = -INFINITY;
        #pragma unroll
        for (int j = 0; j < 16; ++j) {
            int col = td * 16 + j;
            int jg = j0 + col;
            bool ok = (jg <= ig) && (ig - jg < 1024);
            float s = ok ? Sf[tq * 68 + col] : -INFINITY;
            sv[j] = s;
            tmax = fmaxf(tmax, s);
        }
        tmax = fmaxf(tmax, __shfl_xor_sync(0xffffffffu, tmax, 1));
        tmax = fmaxf(tmax, __shfl_xor_sync(0xffffffffu, tmax, 2));
        float mt = fmaxf(m, tmax);
        float mte = (mt > -INFINITY) ? mt : 0.f;
        float corr = exp2f(m - mte);
        float ls = 0.f;
        #pragma unroll
        for (int j = 0; j < 16; ++j) {
            int col = td * 16 + j;
            float p = exp2f(sv[j] - mte);
            ls += p;
            __nv_bfloat16 ph = __float2bfloat16_rn(p);
            Pho[tq * 72 + col] = ph;
            Plo[tq * 72 + col] = __float2bfloat16_rn(p - __bfloat162float(ph));
        }
        ls += __shfl_xor_sync(0xffffffffu, ls, 1);
        ls += __shfl_xor_sync(0xffffffffu, ls, 2);
        lrow = lrow * corr + ls;
        m = mt;
        if (td == 0) carr[tq] = corr;
        __syncthreads();

        {
            float c0 = carr[wr + (lane >> 2)];
            float c1 = carr[wr + 8 + (lane >> 2)];
            #pragma unroll
            for (int nt = 0; nt < 8; ++nt) {
                oacc[nt][0] *= c0; oacc[nt][1] *= c0;
                oacc[nt][2] *= c1; oacc[nt][3] *= c1;
            }
        }
        #pragma unroll
        for (int ktile = 0; ktile < 4; ++ktile) {
            uint32_t ph4[4], pl4[4];
            uint32_t ra = sb + O_PH + (wr + a_row) * PST + ktile * 32 + a_kb;
            ldmx4(ph4, ra);
            ldmx4(pl4, ra + (O_PL - O_PH));
            #pragma unroll
            for (int p2 = 0; p2 < 4; ++p2) {
                uint32_t vh4[4], vl4[4];
                uint32_t rb = sb + O_VH + (ktile * 16 + b_kr) * ATS + (wc * 64 + p2 * 16 + b_no) * 2;
                ldmx4t(vh4, rb);
                ldmx4t(vl4, rb + (O_VL - O_VH));
                #pragma unroll
                for (int sub = 0; sub < 2; ++sub) {
                    int nt = p2 * 2 + sub;
                    uint32_t b0h = vh4[sub * 2], b1h = vh4[sub * 2 + 1];
                    uint32_t b0l = vl4[sub * 2], b1l = vl4[sub * 2 + 1];
                    MMA16816(oacc[nt], ph4, b0h, b1h);
                    MMA16816(oacc[nt], ph4, b0l, b1l);
                    MMA16816(oacc[nt], pl4, b0h, b1h);
                }
            }
        }
    }
    if (td == 0) larr[tq] = lrow;
    __syncthreads();
    {
        int r0 = wr + (lane >> 2);
        float l0 = 1.f / larr[r0], l1 = 1.f / larr[r0 + 8];
        #pragma unroll
        for (int nt = 0; nt < 8; ++nt) {
            int col = wc * 64 + nt * 8 + (lane & 3) * 2;
            long o0 = ((long)(b * SEQ + q0 + r0)) * 2048 + h * 128 + col;
            long o1 = ((long)(b * SEQ + q0 + r0 + 8)) * 2048 + h * 128 + col;
            *(float2*)(O + o0) = make_float2(oacc[nt][0] * l0, oacc[nt][1] * l0);
            *(float2*)(O + o1) = make_float2(oacc[nt][2] * l1, oacc[nt][3] * l1);
        }
    }
}

// --------------------------- TTT helper kernels -----------------------------
__global__ void copyw(const float* __restrict__ w0, const float* __restrict__ w1,
                      const float* __restrict__ w2,
                      float* __restrict__ o02, float* __restrict__ o02t,
                      float* __restrict__ o1, float* __restrict__ o1t)
{
    long idx = (long)blockIdx.x * 256 + threadIdx.x;
    int col = idx & 511;
    int row = (idx >> 9) & 1023;
    int h = (idx >> 19) & 3;
    long src = (long)h * 262144 + (long)(row & 511) * 512 + col;
    float v = (row < 512) ? w0[src] : w2[src];
    o02[idx] = v;
    o02t[idx] = to_tf32(v);
    if (idx < (long)2 * 1024 * 1024) {
        float v1 = w1[idx & ((long)4 * 262144 - 1)];
        o1[idx] = v1;
        o1t[idx] = to_tf32(v1);
    }
}

__global__ void elem2(const float* __restrict__ fvt, const float* __restrict__ lr,
                      const float* __restrict__ gh, const float* __restrict__ dhin,
                      float* __restrict__ dgpt, float* __restrict__ vlt,
                      float* __restrict__ htt, int ck0)
{
    long idx = (long)blockIdx.x * 256 + threadIdx.x;
    int col = idx & 511;
    long tt = idx >> 9;
    int c = tt & 1023, bh = tt >> 10;
    int b = bh >> 2, h = bh & 3;
    long row = (long)b * SEQ + ck0 + c;
    float l0 = lr[row * 12 + h], l1 = lr[row * 12 + 4 + h], l2 = lr[row * 12 + 8 + h];
    long gi = (long)bh * 1048576 + (long)c * 1024 + col;
    float g = gh[gi], hp = gh[gi + 512], d = dhin[idx];
    float sig = 1.f / (1.f + expf(-g));
    float sg = g * sig;
    htt[idx] = to_tf32(sg * hp);
    float v = fvt[((long)bh * SEQ + ck0 + c) * FDM + col];
    dgpt[gi]       = to_tf32(d * hp * (sig * (1.f + g * (1.f - sig))) * l0);
    dgpt[gi + 512] = to_tf32(d * sg * l2);
    vlt[idx]       = to_tf32(v * l1);
}

__global__ void elem3(const float* __restrict__ gh, float* __restrict__ hnt)
{
    long idx = (long)blockIdx.x * 256 + threadIdx.x;
    int col = idx & 511;
    long tt = idx >> 9;
    int c = tt & 1023, bh = tt >> 10;
    long gi = (long)bh * 1048576 + (long)c * 1024 + col;
    float g = gh[gi];
    hnt[idx] = to_tf32((g / (1.f + expf(-g))) * gh[gi + 512]);
}

// -------------------- ttt rmsnorm + add attention result --------------------
__global__ void post_kernel(const float* __restrict__ ttt, const float* __restrict__ tw,
                            const float* __restrict__ sum, float* __restrict__ smt)
{
    __shared__ float sr[4];
    int fh = blockIdx.x, row = blockIdx.y;
    int b = row >> 11, t = row & 2047;
    int bh = b * 4 + fh;
    const float* src = ttt + ((long)bh * SEQ + t) * FDM;
    int tid = threadIdx.x;
    float v[4], ss = 0.f;
    #pragma unroll
    for (int j = 0; j < 4; ++j) { v[j] = src[tid + 128 * j]; ss += v[j] * v[j]; }
    #pragma unroll
    for (int o = 16; o > 0; o >>= 1) ss += __shfl_down_sync(0xffffffffu, ss, o);
    if ((tid & 31) == 0) sr[tid >> 5] = ss;
    __syncthreads();
    float tot = sr[0] + sr[1] + sr[2] + sr[3];
    float r = rsqrtf(tot * (1.f / 512.f) + 1e-6f);
    #pragma unroll
    for (int j = 0; j < 4; ++j) {
        int i = tid + 128 * j;
        long o = (long)row * 2048 + fh * 512 + i;
        smt[o] = to_tf32(sum[o] + v[j] * r * tw[i]);
    }
}

// --------------------------------- launch -----------------------------------
#define GSYM(p, s) cudaGetSymbolAddress((void**)&(p), s)

extern "C" void kernel_launch(void* const* d_in, const int* in_sizes, int n_in,
                              void* d_out, int out_size)
{
    const float* hidden = (const float*)d_in[0];
    const float* Wqkv   = (const float*)d_in[1];
    const float* Wo     = (const float*)d_in[2];
    const float* qnw    = (const float*)d_in[3];
    const float* knw    = (const float*)d_in[4];
    const float* w0     = (const float*)d_in[5];
    const float* w1     = (const float*)d_in[6];
    const float* w2     = (const float*)d_in[7];
    const float* lrw    = (const float*)d_in[8];
    const float* lrb    = (const float*)d_in[9];
    const float* qksc   = (const float*)d_in[10];
    const float* qkof   = (const float*)d_in[11];
    const float* tttw   = (const float*)d_in[12];
    float* out = (float*)d_out;

    float *qkv, *lrpre, *lr, *pw02, *pw1, *gh, *dh, *ttt, *sum;
    GSYM(qkv, g_qkv);   GSYM(lrpre, g_lrpre); GSYM(lr, g_lr);
    GSYM(pw02, g_w02);  GSYM(pw1, g_w1);
    GSYM(gh, g_gh);     GSYM(dh, g_dh);
    GSYM(ttt, g_ttt);   GSYM(sum, g_sum);

    float *hxt,*wqt,*wot,*fqt,*fkt,*fvt,*w02t,*w1t,*dgpt,*vlt,*htt,*hnt,*smt;
    GSYM(hxt, g_hx_t); GSYM(wqt, g_wq_t); GSYM(wot, g_wo_t);
    GSYM(fqt, g_fq_t); GSYM(fkt, g_fk_t); GSYM(fvt, g_fv_t);
    GSYM(w02t, g_w02_t); GSYM(w1t, g_w1_t);
    GSYM(dgpt, g_dgp_t); GSYM(vlt, g_vl_t); GSYM(htt, g_ht_t);
    GSYM(hnt, g_hn_t); GSYM(smt, g_sm_t);

    __nv_bfloat16 *aqh,*aql,*akh,*akl,*avh,*avl;
    GSYM(aqh, g_aq_h); GSYM(aql, g_aq_l); GSYM(akh, g_ak_h); GSYM(akl, g_ak_l);
    GSYM(avh, g_av_h); GSYM(avl, g_av_l);

    cudaFuncSetAttribute(tf_gemm<0,0,false,false>,
                         cudaFuncAttributeMaxDynamicSharedMemorySize, 73728);
    cudaFuncSetAttribute(tf_gemm<0,1,false,false>,
                         cudaFuncAttributeMaxDynamicSharedMemorySize, 71680);
    cudaFuncSetAttribute(tf_gemm<1,1,true,true>,
                         cudaFuncAttributeMaxDynamicSharedMemorySize, 69632);
    cudaFuncSetAttribute(attn_mma, cudaFuncAttributeMaxDynamicSharedMemorySize, ATTN_SMEM);

    #define G_NT(A,B,C,M,N,K,lda,ldb,sA,sB,sC,bat) \
        tf_gemm<0,0,false,false><<<dim3((N)/128,(M)/128,(bat)),256,73728>>>( \
            A,B,C,nullptr,M,N,K,lda,ldb,sA,sB,sC)
    #define G_NN(A,B,C,M,N,K,lda,ldb,sA,sB,sC,bat) \
        tf_gemm<0,1,false,false><<<dim3((N)/128,(M)/128,(bat)),256,71680>>>( \
            A,B,C,nullptr,M,N,K,lda,ldb,sA,sB,sC)
    #define G_TN_AS(A,B,C,Ct,M,N,K,lda,ldb,sA,sB,sC,bat) \
        tf_gemm<1,1,true,true><<<dim3((N)/128,(M)/128,(bat)),256,69632>>>( \
            A,B,C,Ct,M,N,K,lda,ldb,sA,sB,sC)

    cvt_tf<<<8192, 256>>>(hidden, hxt, (long)4096 * 2048);
    cvt_tf<<<12288, 256>>>(Wqkv, wqt, (long)6144 * 2048);
    cvt_tf<<<4096, 256>>>(Wo, wot, (long)2048 * 2048);

    G_NT(hxt, wqt, qkv, 4096, 6144, 2048, 2048, 2048, 0, 0, 0, 1);
    lr_gemm<<<2048, 256>>>(hidden, lrw, lrpre);

    float base = (float)(0.001 + log(-expm1(-0.001)));
    prep_kernel<<<4096, 256>>>(qkv, lrpre, qnw, knw, qksc, qkof, lrb, base,
                               aqh, aql, akh, akl, avh, avl,
                               fqt, fkt, fvt, lr);
    attn_mma<<<dim3(32, 16, 2), 256, ATTN_SMEM>>>(aqh, aql, akh, akl, avh, avl, sum);

    copyw<<<16384, 256>>>(w0, w1, w2, pw02, w02t, pw1, w1t);

    long sSeq = (long)SEQ * FDM;
    long sChk = (long)1024 * FDM;
    long sW   = (long)FDM * FDM;
    long sW02 = (long)1024 * FDM;
    long sGH  = (long)1024 * 1024;
    for (int ck = 0; ck < 2; ++ck) {
        int ck0 = ck * 1024;
        long co = (long)ck0 * FDM;
        G_NT(fkt + co, w02t, gh, 1024, 1024, 512, 512, 512, sSeq, sW02, sGH, 8);
        G_NN(fvt + co, w1t, dh, 1024, 512, 512, 512, 512, sSeq, sW, sChk, 8);
        elem2<<<16384, 256>>>(fvt, lr, gh, dh, dgpt, vlt, htt, ck0);
        G_TN_AS(dgpt, fkt + co, pw02, w02t, 1024, 512, 1024, 1024, 512, sGH, sSeq, sW02, 8);
        G_TN_AS(vlt, htt, pw1, w1t, 512, 512, 1024, 512, 512, sChk, sChk, sW, 8);
        G_NT(fqt + co, w02t, gh, 1024, 1024, 512, 512, 512, sSeq, sW02, sGH, 8);
        elem3<<<16384, 256>>>(gh, hnt);
        G_NT(hnt, w1t, ttt + co, 1024, 512, 512, 512, 512, sChk, sW, sSeq, 8);
    }

    post_kernel<<<dim3(4, 4096), 128>>>(ttt, tttw, sum, smt);
    G_NT(smt, wot, out, 4096, 2048, 2048, 2048, 2048, 0, 0, 0, 1);
    #undef G_NT
    #undef G_NN
    #undef G_TN_AS
}

// round 11
// speedup vs baseline: 6.7579x; 1.0632x over previous
#include <cuda_runtime.h>
#include <cuda_bf16.h>
#include <cstdint>
#include <math.h>

#define SEQ 2048
#define DIMD 2048
#define FDM 512

// ------------------------- fp32 scratch (device globals) --------------------
__device__ float g_qkv [(size_t)4096 * 6144];
__device__ float g_lrpre[(size_t)4096 * 12];
__device__ float g_lr  [(size_t)4096 * 12];
__device__ float g_w02 [(size_t)8 * 1024 * FDM];
__device__ float g_w1  [(size_t)8 * FDM * FDM];
__device__ float g_gh  [(size_t)8 * 1024 * 1024];
__device__ float g_dh  [(size_t)8 * 1024 * FDM];
__device__ float g_ttt [(size_t)8 * SEQ * FDM];
__device__ float g_sum [(size_t)4096 * 2048];

// ---------------------- tf32 (pre-rounded fp32) operands --------------------
__device__ float g_hx_t [(size_t)4096 * 2048];
__device__ float g_wq_t [(size_t)6144 * 2048];
__device__ float g_wo_t [(size_t)2048 * 2048];
__device__ float g_fq_t [(size_t)8 * SEQ * FDM];
__device__ float g_fk_t [(size_t)8 * SEQ * FDM];
__device__ float g_fv_t [(size_t)8 * SEQ * FDM];
__device__ float g_w02_t[(size_t)8 * 1024 * FDM];
__device__ float g_w1_t [(size_t)8 * FDM * FDM];
__device__ float g_dgp_t[(size_t)8 * 1024 * 1024];
__device__ float g_vl_t [(size_t)8 * 1024 * FDM];
__device__ float g_ht_t [(size_t)8 * 1024 * FDM];
__device__ float g_hn_t [(size_t)8 * 1024 * FDM];
__device__ float g_sm_t [(size_t)4096 * 2048];

// ------------------- bf16 hi/lo (attention only) ----------------------------
__device__ __nv_bfloat16 g_aq_h[(size_t)4096*2048], g_aq_l[(size_t)4096*2048];
__device__ __nv_bfloat16 g_ak_h[(size_t)4096*2048], g_ak_l[(size_t)4096*2048];
__device__ __nv_bfloat16 g_av_h[(size_t)4096*2048], g_av_l[(size_t)4096*2048];

// ------------------------------ helpers -------------------------------------
__device__ __forceinline__ uint32_t smem_u32(const void* p) {
    uint32_t a;
    asm("{ .reg .u64 t; cvta.to.shared.u64 t, %1; cvt.u32.u64 %0, t; }" : "=r"(a) : "l"(p));
    return a;
}
__device__ __forceinline__ void cpa16(uint32_t s, const void* g) {
    asm volatile("cp.async.cg.shared.global [%0], [%1], 16;" :: "r"(s), "l"(g));
}
#define CP_COMMIT() asm volatile("cp.async.commit_group;" ::: "memory")
#define MMA16816(d, a, b0, b1) \
    asm volatile("mma.sync.aligned.m16n8k16.row.col.f32.bf16.bf16.f32 " \
        "{%0,%1,%2,%3}, {%4,%5,%6,%7}, {%8,%9}, {%0,%1,%2,%3};" \
        : "+f"((d)[0]), "+f"((d)[1]), "+f"((d)[2]), "+f"((d)[3]) \
        : "r"((a)[0]), "r"((a)[1]), "r"((a)[2]), "r"((a)[3]), "r"(b0), "r"(b1))
#define MMATF(d, a, b0, b1) \
    asm volatile("mma.sync.aligned.m16n8k8.row.col.f32.tf32.tf32.f32 " \
        "{%0,%1,%2,%3}, {%4,%5,%6,%7}, {%8,%9}, {%0,%1,%2,%3};" \
        : "+f"((d)[0]), "+f"((d)[1]), "+f"((d)[2]), "+f"((d)[3]) \
        : "r"((a)[0]), "r"((a)[1]), "r"((a)[2]), "r"((a)[3]), "r"(b0), "r"(b1))
__device__ __forceinline__ void ldmx4(uint32_t* r, uint32_t addr) {
    asm volatile("ldmatrix.sync.aligned.m8n8.x4.shared.b16 {%0,%1,%2,%3}, [%4];"
        : "=r"(r[0]), "=r"(r[1]), "=r"(r[2]), "=r"(r[3]) : "r"(addr));
}
__device__ __forceinline__ void ldmx4t(uint32_t* r, uint32_t addr) {
    asm volatile("ldmatrix.sync.aligned.m8n8.x4.trans.shared.b16 {%0,%1,%2,%3}, [%4];"
        : "=r"(r[0]), "=r"(r[1]), "=r"(r[2]), "=r"(r[3]) : "r"(addr));
}
__device__ __forceinline__ void split_w(float v, __nv_bfloat16* h, __nv_bfloat16* l, long i) {
    __nv_bfloat16 hv = __float2bfloat16_rn(v);
    h[i] = hv;
    l[i] = __float2bfloat16_rn(v - __bfloat162float(hv));
}
__device__ __forceinline__ float to_tf32(float v) {
    uint32_t u;
    asm("cvt.rna.tf32.f32 %0, %1;" : "=r"(u) : "f"(v));
    return __uint_as_float(u);
}
__device__ __forceinline__ uint32_t lds_u32(uint32_t addr) {
    uint32_t v;
    asm volatile("ld.shared.b32 %0, [%1];" : "=r"(v) : "r"(addr));
    return v;
}

// -------------------- TF32 mma.sync batched GEMM ----------------------------
// AT=0: A stored [M,K]; AT=1: A stored [K,M].  BT likewise for B.
// C[M,N] (+)= sum_k Aop[m,k]*Bop[n,k]; SPLIT also writes tf32-rounded copy Ct.
// k-major operands (AT==0 / BT==0) use ldmatrix (b16 tile == 8x4 fp32 tile,
// exact m16n8k8 tf32 fragment mapping); trans sides use scalar LDS.
template<int AT, int BT, bool ACC, bool SPLIT>
__global__ void __launch_bounds__(256, 2)
tf_gemm(const float* __restrict__ A, const float* __restrict__ B,
        float* __restrict__ C, float* __restrict__ Ct,
        int M, int N, int K, int lda, int ldb, long sA, long sB, long sC)
{
    constexpr int SA = AT ? 17408 : 18432;   // trans: 32*544 ; k-major: 128*144
    constexpr int SB = BT ? 17408 : 18432;
    constexpr int STAGE = SA + SB;
    extern __shared__ char smem[];
    uint32_t sb = smem_u32(smem);
    int tid = threadIdx.x, lane = tid & 31, wid = tid >> 5;
    int wm = wid >> 2, wn = wid & 3;
    long zb = blockIdx.z;
    const float* a = A + zb * sA;
    const float* b = B + zb * sB;
    int m0 = blockIdx.y << 7, n0 = blockIdx.x << 7;

    float acc[4][4][4];
    #pragma unroll
    for (int i = 0; i < 4; ++i)
        #pragma unroll
        for (int j = 0; j < 4; ++j)
            #pragma unroll
            for (int q = 0; q < 4; ++q) acc[i][j][q] = 0.f;

    // ldmatrix per-lane byte offsets (k-major fp32 tiles, 144B row stride)
    int Lm = lane >> 3, Lr = lane & 7;
    uint32_t aoff = (uint32_t)(((Lm & 1) * 8 + Lr) * 144 + (Lm >> 1) * 16);
    uint32_t boff = (uint32_t)(((Lm >> 1) * 8 + Lr) * 144 + (Lm & 1) * 16);

    auto issue = [&](int buf, int k0) {
        uint32_t st = sb + buf * STAGE;
        #pragma unroll
        for (int j = 0; j < 4; ++j) {
            int u = tid + j * 256;
            uint32_t so; long g;
            if (AT == 0) { int r = u >> 3, s = u & 7;  so = r * 144 + s * 16;
                           g = (long)(m0 + r) * lda + k0 + s * 4; }
            else         { int r = u >> 5, s = u & 31; so = r * 544 + s * 16;
                           g = (long)(k0 + r) * lda + m0 + s * 4; }
            cpa16(st + so, a + g);
            if (BT == 0) { int r = u >> 3, s = u & 7;  so = r * 144 + s * 16;
                           g = (long)(n0 + r) * ldb + k0 + s * 4; }
            else         { int r = u >> 5, s = u & 31; so = r * 544 + s * 16;
                           g = (long)(k0 + r) * ldb + n0 + s * 4; }
            cpa16(st + SA + so, b + g);
        }
        CP_COMMIT();
    };

    const int n = K >> 5;
    issue(0, 0);
    int buf = 0;
    for (int i = 0; i < n; ++i) {
        if (i + 1 < n) {
            issue(buf ^ 1, (i + 1) * 32);
            asm volatile("cp.async.wait_group 1;" ::: "memory");
        } else {
            asm volatile("cp.async.wait_group 0;" ::: "memory");
        }
        __syncthreads();
        uint32_t st = sb + buf * STAGE;
        uint32_t stB = st + SA;
        #pragma unroll
        for (int kk = 0; kk < 32; kk += 8) {
            uint32_t af[4][4];
            #pragma unroll
            for (int mt = 0; mt < 4; ++mt) {
                if (AT == 0) {
                    ldmx4(af[mt], st + (wm * 64 + mt * 16) * 144 + kk * 4 + aoff);
                } else {
                    uint32_t ra = st + (kk + (lane & 3)) * 544
                                + (wm * 64 + mt * 16 + (lane >> 2)) * 4;
                    af[mt][0] = lds_u32(ra);
                    af[mt][1] = lds_u32(ra + 32);
                    af[mt][2] = lds_u32(ra + 4 * 544);
                    af[mt][3] = lds_u32(ra + 4 * 544 + 32);
                }
            }
            uint32_t bf_[4][2];
            if (BT == 0) {
                #pragma unroll
                for (int p = 0; p < 2; ++p) {
                    uint32_t r4[4];
                    ldmx4(r4, stB + (wn * 32 + p * 16) * 144 + kk * 4 + boff);
                    bf_[p * 2 + 0][0] = r4[0]; bf_[p * 2 + 0][1] = r4[1];
                    bf_[p * 2 + 1][0] = r4[2]; bf_[p * 2 + 1][1] = r4[3];
                }
            } else {
                #pragma unroll
                for (int nt = 0; nt < 4; ++nt) {
                    uint32_t rb = stB + (kk + (lane & 3)) * 544
                                + (wn * 32 + nt * 8 + (lane >> 2)) * 4;
                    bf_[nt][0] = lds_u32(rb);
                    bf_[nt][1] = lds_u32(rb + 4 * 544);
                }
            }
            #pragma unroll
            for (int nt = 0; nt < 4; ++nt)
                #pragma unroll
                for (int mt = 0; mt < 4; ++mt)
                    MMATF(acc[mt][nt], af[mt], bf_[nt][0], bf_[nt][1]);
        }
        __syncthreads();
        buf ^= 1;
    }
    float* c = C + zb * sC;
    float* ct = SPLIT ? Ct + zb * sC : nullptr;
    #pragma unroll
    for (int mt = 0; mt < 4; ++mt) {
        #pragma unroll
        for (int nt = 0; nt < 4; ++nt) {
            long r0 = m0 + wm * 64 + mt * 16 + (lane >> 2);
            int  cc = n0 + wn * 32 + nt * 8 + (lane & 3) * 2;
            long o0 = r0 * (long)N + cc;
            long o1 = (r0 + 8) * (long)N + cc;
            float v00 = acc[mt][nt][0], v01 = acc[mt][nt][1];
            float v10 = acc[mt][nt][2], v11 = acc[mt][nt][3];
            if (ACC) {
                float2 t0 = *(float2*)(c + o0), t1 = *(float2*)(c + o1);
                v00 += t0.x; v01 += t0.y; v10 += t1.x; v11 += t1.y;
            }
            *(float2*)(c + o0) = make_float2(v00, v01);
            *(float2*)(c + o1) = make_float2(v10, v11);
            if (SPLIT) {
                *(float2*)(ct + o0) = make_float2(to_tf32(v00), to_tf32(v01));
                *(float2*)(ct + o1) = make_float2(to_tf32(v10), to_tf32(v11));
            }
        }
    }
}

// ------------------------ conversion kernel ---------------------------------
__global__ void cvt_tf(const float* __restrict__ x, float* __restrict__ o, long n)
{
    long i = ((long)blockIdx.x * 256 + threadIdx.x) * 4;
    if (i >= n) return;
    float4 v = *(const float4*)(x + i);
    float4 w;
    w.x = to_tf32(v.x); w.y = to_tf32(v.y); w.z = to_tf32(v.z); w.w = to_tf32(v.w);
    *(float4*)(o + i) = w;
}

// ---------------- small SGEMM for the N=12 lr GEMM --------------------------
__global__ void lr_gemm(const float* __restrict__ A, const float* __restrict__ B,
                        float* __restrict__ C)
{
    __shared__ float bs[12][128];
    int row = blockIdx.x * 2 + (threadIdx.x >> 7);
    int tid = threadIdx.x & 127;
    float acc[12];
    #pragma unroll
    for (int c = 0; c < 12; ++c) acc[c] = 0.f;
    for (int k0 = 0; k0 < 2048; k0 += 128) {
        if (threadIdx.x < 128)
            #pragma unroll
            for (int c = 0; c < 12; ++c) bs[c][tid] = B[c * 2048 + k0 + tid];
        __syncthreads();
        float a = A[(long)row * 2048 + k0 + tid];
        #pragma unroll
        for (int c = 0; c < 12; ++c) acc[c] += a * bs[c][tid];
        __syncthreads();
    }
    __shared__ float red[2][12][4];
    #pragma unroll
    for (int c = 0; c < 12; ++c) {
        float v = acc[c];
        #pragma unroll
        for (int o = 16; o > 0; o >>= 1) v += __shfl_down_sync(0xffffffffu, v, o);
        if ((tid & 31) == 0) red[threadIdx.x >> 7][c][tid >> 5] = v;
    }
    __syncthreads();
    if (tid < 12) {
        int w = threadIdx.x >> 7;
        C[(long)row * 12 + tid] = red[w][tid][0] + red[w][tid][1] + red[w][tid][2] + red[w][tid][3];
    }
}

// ------------------------- block reduce (256 thr) ---------------------------
__device__ __forceinline__ float blockReduceSum(float v, float* sred)
{
    int lane = threadIdx.x & 31;
    #pragma unroll
    for (int o = 16; o > 0; o >>= 1) v += __shfl_down_sync(0xffffffffu, v, o);
    if (lane == 0) sred[threadIdx.x >> 5] = v;
    __syncthreads();
    if (threadIdx.x < 8) {
        float r = sred[threadIdx.x];
        #pragma unroll
        for (int o = 4; o > 0; o >>= 1) r += __shfl_down_sync(0xffu, r, o);
        if (threadIdx.x == 0) sred[0] = r;
    }
    __syncthreads();
    float out = sred[0];
    __syncthreads();
    return out;
}

// --------- prep: rmsnorm+rope + silu/L2 + lr ---------------------------------
__global__ void prep_kernel(const float* __restrict__ qkv, const float* __restrict__ lrpre,
                            const float* __restrict__ qnw, const float* __restrict__ knw,
                            const float* __restrict__ qksc, const float* __restrict__ qkof,
                            const float* __restrict__ lrb, float base_lr_inv,
                            __nv_bfloat16* __restrict__ aqh, __nv_bfloat16* __restrict__ aql,
                            __nv_bfloat16* __restrict__ akh, __nv_bfloat16* __restrict__ akl,
                            __nv_bfloat16* __restrict__ avh, __nv_bfloat16* __restrict__ avl,
                            float* __restrict__ fqt, float* __restrict__ fkt,
                            float* __restrict__ fvt, float* __restrict__ lrout)
{
    __shared__ float s_q[2048];
    __shared__ float s_k[2048];
    __shared__ float sred[8];
    int row = blockIdx.x;
    int b = row >> 11, t = row & 2047;
    int tid = threadIdx.x;
    const float* qr = qkv + (long)row * 6144;
    const float* kr = qr + 2048;
    const float* vr = qr + 4096;
    const float qscale = 0.088388347648318447f * 1.4426950408889634f;

    float qv[8], kv[8], fqv[8], fkv[8], fvv[8];
    float sq = 0.f, sk = 0.f;
    float p2q[4] = {0, 0, 0, 0}, p2k[4] = {0, 0, 0, 0};
    #pragma unroll
    for (int j = 0; j < 8; ++j) {
        int i = j * 256 + tid;
        float q = qr[i], k = kr[i], v = vr[i];
        qv[j] = q; kv[j] = k;
        sq += q * q; sk += k * k;
        float fqe = (q / (1.f + expf(-q))) * qksc[i * 2 + 0] + qkof[i * 2 + 0];
        float fke = (k / (1.f + expf(-k))) * qksc[i * 2 + 1] + qkof[i * 2 + 1];
        fqv[j] = fqe; fkv[j] = fke; fvv[j] = v / (1.f + expf(-v));
        p2q[j >> 1] += fqe * fqe;
        p2k[j >> 1] += fke * fke;
        split_w(v, avh, avl, (long)row * DIMD + i);
    }
    float SQ = blockReduceSum(sq, sred);
    float SK = blockReduceSum(sk, sred);
    float G2Q[4], G2K[4];
    #pragma unroll
    for (int g = 0; g < 4; ++g) G2Q[g] = blockReduceSum(p2q[g], sred);
    #pragma unroll
    for (int g = 0; g < 4; ++g) G2K[g] = blockReduceSum(p2k[g], sred);
    float rq = rsqrtf(SQ * (1.f / 2048.f) + 1e-6f);
    float rk = rsqrtf(SK * (1.f / 2048.f) + 1e-6f);
    #pragma unroll
    for (int j = 0; j < 8; ++j) {
        int i = j * 256 + tid;
        s_q[i] = qv[j] * rq * qnw[i];
        s_k[i] = kv[j] * rk * knw[i];
        int g = j >> 1;
        long fb = (((long)(b * 4 + g)) * SEQ + t) * FDM + (i & 511);
        fqt[fb] = to_tf32(fqv[j] / (sqrtf(G2Q[g]) + 1e-12f));
        fkt[fb] = to_tf32(fkv[j] / (sqrtf(G2K[g]) + 1e-12f));
        fvt[fb] = to_tf32(fvv[j]);
    }
    __syncthreads();
    #pragma unroll
    for (int j = 0; j < 8; ++j) {
        int i = j * 256 + tid;
        int pos = i & 127;
        int fi = pos & 63;
        float invf = expf(-(float)fi * (logf(500000.f) / 64.f));
        float sn, cs;
        sincosf((float)t * invf, &sn, &cs);
        float oq, ok_;
        if (pos < 64) {
            oq  = s_q[i] * cs - s_q[i + 64] * sn;
            ok_ = s_k[i] * cs - s_k[i + 64] * sn;
        } else {
            oq  = s_q[i] * cs + s_q[i - 64] * sn;
            ok_ = s_k[i] * cs + s_k[i - 64] * sn;
        }
        split_w(oq * qscale, aqh, aql, (long)row * DIMD + i);
        split_w(ok_, akh, akl, (long)row * DIMD + i);
    }
    if (tid < 12) {
        float x = lrpre[(long)row * 12 + tid] + lrb[tid] + base_lr_inv;
        lrout[(long)row * 12 + tid] = (x > 20.f) ? x : log1pf(expf(x));
    }
}

// -------------------- HMMA windowed flash attention (unchanged) --------------
#define ATS 272
#define PST 144
#define O_QH 0
#define O_QL 17408
#define O_KH 34816
#define O_KL 52224
#define O_VH 69632
#define O_VL 87040
#define O_S  104448
#define O_PH 121856
#define O_PL 131072
#define O_CR 140288
#define O_LR 140544
#define ATTN_SMEM 140800

__global__ void __launch_bounds__(256, 1)
attn_mma(const __nv_bfloat16* __restrict__ Qh, const __nv_bfloat16* __restrict__ Ql,
         const __nv_bfloat16* __restrict__ Kh, const __nv_bfloat16* __restrict__ Kl,
         const __nv_bfloat16* __restrict__ Vh, const __nv_bfloat16* __restrict__ Vl,
         float* __restrict__ O)
{
    extern __shared__ char smc[];
    uint32_t sb = smem_u32(smc);
    float* Sf = (float*)(smc + O_S);
    float* carr = (float*)(smc + O_CR);
    float* larr = (float*)(smc + O_LR);
    __nv_bfloat16* Pho = (__nv_bfloat16*)(smc + O_PH);
    __nv_bfloat16* Plo = (__nv_bfloat16*)(smc + O_PL);

    int tid = threadIdx.x, lane = tid & 31, wid = tid >> 5;
    int q0 = blockIdx.x << 6, h = blockIdx.y, b = blockIdx.z;
    int wr = (wid & 3) * 16;
    int wc = wid >> 2;
    uint32_t a_row = (lane & 7) + ((lane >> 3) & 1) * 8;
    uint32_t a_kb  = ((lane >> 4) & 1) * 16;
    uint32_t b_row = (lane & 7) + ((lane >> 4) & 1) * 8;
    uint32_t b_kb  = ((lane >> 3) & 1) * 16;
    uint32_t b_kr  = (lane & 7) + ((lane >> 3) & 1) * 8;
    uint32_t b_no  = ((lane >> 4) & 1) * 8;
    int tq = tid >> 2, td = tid & 3;

    #pragma unroll
    for (int j = 0; j < 4; ++j) {
        int u = tid + j * 256;
        int r = u >> 4, s = u & 15;
        long g = ((long)(b * SEQ + q0 + r)) * DIMD + h * 128 + s * 8;
        cpa16(sb + O_QH + r * ATS + s * 16, Qh + g);
        cpa16(sb + O_QL + r * ATS + s * 16, Ql + g);
    }
    CP_COMMIT();

    float oacc[8][4];
    #pragma unroll
    for (int i = 0; i < 8; ++i)
        #pragma unroll
        for (int q = 0; q < 4; ++q) oacc[i][q] = 0.f;
    float m = -INFINITY, lrow = 0.f;

    int kt_hi = q0 >> 6;
    int kt_lo = (q0 >= 1024) ? ((q0 - 1023) >> 6) : 0;
    for (int kt = kt_lo; kt <= kt_hi; ++kt) {
        int j0 = kt << 6;
        __syncthreads();
        #pragma unroll
        for (int j = 0; j < 4; ++j) {
            int u = tid + j * 256;
            int r = u >> 4, s = u & 15;
            long g = ((long)(b * SEQ + j0 + r)) * DIMD + h * 128 + s * 8;
            uint32_t so = r * ATS + s * 16;
            cpa16(sb + O_KH + so, Kh + g);
            cpa16(sb + O_KL + so, Kl + g);
            cpa16(sb + O_VH + so, Vh + g);
            cpa16(sb + O_VL + so, Vl + g);
        }
        CP_COMMIT();
        asm volatile("cp.async.wait_group 0;" ::: "memory");
        __syncthreads();

        float sacc[4][4];
        #pragma unroll
        for (int i = 0; i < 4; ++i)
            #pragma unroll
            for (int q = 0; q < 4; ++q) sacc[i][q] = 0.f;
        #pragma unroll
        for (int kk = 0; kk < 8; ++kk) {
            uint32_t ah4[4], al4[4];
            uint32_t ra = sb + O_QH + (wr + a_row) * ATS + kk * 32 + a_kb;
            ldmx4(ah4, ra);
            ldmx4(al4, ra + (O_QL - O_QH));
            uint32_t bh4[2][4], bl4[2][4];
            #pragma unroll
            for (int p = 0; p < 2; ++p) {
                uint32_t rb = sb + O_KH + (wc * 32 + p * 16 + b_row) * ATS + kk * 32 + b_kb;
                ldmx4(bh4[p], rb);
                ldmx4(bl4[p], rb + (O_KL - O_KH));
            }
            #pragma unroll
            for (int nt = 0; nt < 4; ++nt) {
                uint32_t b0h = bh4[nt >> 1][(nt & 1) * 2 + 0];
                uint32_t b1h = bh4[nt >> 1][(nt & 1) * 2 + 1];
                uint32_t b0l = bl4[nt >> 1][(nt & 1) * 2 + 0];
                uint32_t b1l = bl4[nt >> 1][(nt & 1) * 2 + 1];
                MMA16816(sacc[nt], ah4, b0h, b1h);
                MMA16816(sacc[nt], ah4, b0l, b1l);
                MMA16816(sacc[nt], al4, b0h, b1h);
            }
        }
        #pragma unroll
        for (int nt = 0; nt < 4; ++nt) {
            int col = wc * 32 + nt * 8 + (lane & 3) * 2;
            int r0 = wr + (lane >> 2);
            Sf[r0 * 68 + col] = sacc[nt][0];
            Sf[r0 * 68 + col + 1] = sacc[nt][1];
            Sf[(r0 + 8) * 68 + col] = sacc[nt][2];
            Sf[(r0 + 8) * 68 + col + 1] = sacc[nt][3];
        }
        __syncthreads();

        int ig = q0 + tq;
        float sv[16], tmax = -INFINITY;
        #pragma unroll
        for (int j = 0; j < 16; ++j) {
            int col = td * 16 + j;
            int jg = j0 + col;
            bool ok = (jg <= ig) && (ig - jg < 1024);
            float s = ok ? Sf[tq * 68 + col] : -INFINITY;
            sv[j] = s;
            tmax = fmaxf(tmax, s);
        }
        tmax = fmaxf(tmax, __shfl_xor_sync(0xffffffffu, tmax, 1));
        tmax = fmaxf(tmax, __shfl_xor_sync(0xffffffffu, tmax, 2));
        float mt = fmaxf(m, tmax);
        float mte = (mt > -INFINITY) ? mt : 0.f;
        float corr = exp2f(m - mte);
        float ls = 0.f;
        #pragma unroll
        for (int j = 0; j < 16; ++j) {
            int col = td * 16 + j;
            float p = exp2f(sv[j] - mte);
            ls += p;
            __nv_bfloat16 ph = __float2bfloat16_rn(p);
            Pho[tq * 72 + col] = ph;
            Plo[tq * 72 + col] = __float2bfloat16_rn(p - __bfloat162float(ph));
        }
        ls += __shfl_xor_sync(0xffffffffu, ls, 1);
        ls += __shfl_xor_sync(0xffffffffu, ls, 2);
        lrow = lrow * corr + ls;
        m = mt;
        if (td == 0) carr[tq] = corr;
        __syncthreads();

        {
            float c0 = carr[wr + (lane >> 2)];
            float c1 = carr[wr + 8 + (lane >> 2)];
            #pragma unroll
            for (int nt = 0; nt < 8; ++nt) {
                oacc[nt][0] *= c0; oacc[nt][1] *= c0;
                oacc[nt][2] *= c1; oacc[nt][3] *= c1;
            }
        }
        #pragma unroll
        for (int ktile = 0; ktile < 4; ++ktile) {
            uint32_t ph4[4], pl4[4];
            uint32_t ra = sb + O_PH + (wr + a_row) * PST + ktile * 32 + a_kb;
            ldmx4(ph4, ra);
            ldmx4(pl4, ra + (O_PL - O_PH));
            #pragma unroll
            for (int p2 = 0; p2 < 4; ++p2) {
                uint32_t vh4[4], vl4[4];
                uint32_t rb = sb + O_VH + (ktile * 16 + b_kr) * ATS + (wc * 64 + p2 * 16 + b_no) * 2;
                ldmx4t(vh4, rb);
                ldmx4t(vl4, rb + (O_VL - O_VH));
                #pragma unroll
                for (int sub = 0; sub < 2; ++sub) {
                    int nt = p2 * 2 + sub;
                    uint32_t b0h = vh4[sub * 2], b1h = vh4[sub * 2 + 1];
                    uint32_t b0l = vl4[sub * 2], b1l = vl4[sub * 2 + 1];
                    MMA16816(oacc[nt], ph4, b0h, b1h);
                    MMA16816(oacc[nt], ph4, b0l, b1l);
                    MMA16816(oacc[nt], pl4, b0h, b1h);
                }
            }
        }
    }
    if (td == 0) larr[tq] = lrow;
    __syncthreads();
    {
        int r0 = wr + (lane >> 2);
        float l0 = 1.f / larr[r0], l1 = 1.f / larr[r0 + 8];
        #pragma unroll
        for (int nt = 0; nt < 8; ++nt) {
            int col = wc * 64 + nt * 8 + (lane & 3) * 2;
            long o0 = ((long)(b * SEQ + q0 + r0)) * 2048 + h * 128 + col;
            long o1 = ((long)(b * SEQ + q0 + r0 + 8)) * 2048 + h * 128 + col;
            *(float2*)(O + o0) = make_float2(oacc[nt][0] * l0, oacc[nt][1] * l0);
            *(float2*)(O + o1) = make_float2(oacc[nt][2] * l1, oacc[nt][3] * l1);
        }
    }
}

// --------------------------- TTT helper kernels -----------------------------
__global__ void copyw(const float* __restrict__ w0, const float* __restrict__ w1,
                      const float* __restrict__ w2,
                      float* __restrict__ o02, float* __restrict__ o02t,
                      float* __restrict__ o1, float* __restrict__ o1t)
{
    long idx = (long)blockIdx.x * 256 + threadIdx.x;
    int col = idx & 511;
    int row = (idx >> 9) & 1023;
    int h = (idx >> 19) & 3;
    long src = (long)h * 262144 + (long)(row & 511) * 512 + col;
    float v = (row < 512) ? w0[src] : w2[src];
    o02[idx] = v;
    o02t[idx] = to_tf32(v);
    if (idx < (long)2 * 1024 * 1024) {
        float v1 = w1[idx & ((long)4 * 262144 - 1)];
        o1[idx] = v1;
        o1t[idx] = to_tf32(v1);
    }
}

__global__ void elem2(const float* __restrict__ fvt, const float* __restrict__ lr,
                      const float* __restrict__ gh, const float* __restrict__ dhin,
                      float* __restrict__ dgpt, float* __restrict__ vlt,
                      float* __restrict__ htt, int ck0)
{
    long idx = (long)blockIdx.x * 256 + threadIdx.x;
    int col = idx & 511;
    long tt = idx >> 9;
    int c = tt & 1023, bh = tt >> 10;
    int b = bh >> 2, h = bh & 3;
    long row = (long)b * SEQ + ck0 + c;
    float l0 = lr[row * 12 + h], l1 = lr[row * 12 + 4 + h], l2 = lr[row * 12 + 8 + h];
    long gi = (long)bh * 1048576 + (long)c * 1024 + col;
    float g = gh[gi], hp = gh[gi + 512], d = dhin[idx];
    float sig = 1.f / (1.f + expf(-g));
    float sg = g * sig;
    htt[idx] = to_tf32(sg * hp);
    float v = fvt[((long)bh * SEQ + ck0 + c) * FDM + col];
    dgpt[gi]       = to_tf32(d * hp * (sig * (1.f + g * (1.f - sig))) * l0);
    dgpt[gi + 512] = to_tf32(d * sg * l2);
    vlt[idx]       = to_tf32(v * l1);
}

__global__ void elem3(const float* __restrict__ gh, float* __restrict__ hnt)
{
    long idx = (long)blockIdx.x * 256 + threadIdx.x;
    int col = idx & 511;
    long tt = idx >> 9;
    int c = tt & 1023, bh = tt >> 10;
    long gi = (long)bh * 1048576 + (long)c * 1024 + col;
    float g = gh[gi];
    hnt[idx] = to_tf32((g / (1.f + expf(-g))) * gh[gi + 512]);
}

// -------------------- ttt rmsnorm + add attention result --------------------
__global__ void post_kernel(const float* __restrict__ ttt, const float* __restrict__ tw,
                            const float* __restrict__ sum, float* __restrict__ smt)
{
    __shared__ float sr[4];
    int fh = blockIdx.x, row = blockIdx.y;
    int b = row >> 11, t = row & 2047;
    int bh = b * 4 + fh;
    const float* src = ttt + ((long)bh * SEQ + t) * FDM;
    int tid = threadIdx.x;
    float v[4], ss = 0.f;
    #pragma unroll
    for (int j = 0; j < 4; ++j) { v[j] = src[tid + 128 * j]; ss += v[j] * v[j]; }
    #pragma unroll
    for (int o = 16; o > 0; o >>= 1) ss += __shfl_down_sync(0xffffffffu, ss, o);
    if ((tid & 31) == 0) sr[tid >> 5] = ss;
    __syncthreads();
    float tot = sr[0] + sr[1] + sr[2] + sr[3];
    float r = rsqrtf(tot * (1.f / 512.f) + 1e-6f);
    #pragma unroll
    for (int j = 0; j < 4; ++j) {
        int i = tid + 128 * j;
        long o = (long)row * 2048 + fh * 512 + i;
        smt[o] = to_tf32(sum[o] + v[j] * r * tw[i]);
    }
}

// --------------------------------- launch -----------------------------------
#define GSYM(p, s) cudaGetSymbolAddress((void**)&(p), s)

extern "C" void kernel_launch(void* const* d_in, const int* in_sizes, int n_in,
                              void* d_out, int out_size)
{
    const float* hidden = (const float*)d_in[0];
    const float* Wqkv   = (const float*)d_in[1];
    const float* Wo     = (const float*)d_in[2];
    const float* qnw    = (const float*)d_in[3];
    const float* knw    = (const float*)d_in[4];
    const float* w0     = (const float*)d_in[5];
    const float* w1     = (const float*)d_in[6];
    const float* w2     = (const float*)d_in[7];
    const float* lrw    = (const float*)d_in[8];
    const float* lrb    = (const float*)d_in[9];
    const float* qksc   = (const float*)d_in[10];
    const float* qkof   = (const float*)d_in[11];
    const float* tttw   = (const float*)d_in[12];
    float* out = (float*)d_out;

    float *qkv, *lrpre, *lr, *pw02, *pw1, *gh, *dh, *ttt, *sum;
    GSYM(qkv, g_qkv);   GSYM(lrpre, g_lrpre); GSYM(lr, g_lr);
    GSYM(pw02, g_w02);  GSYM(pw1, g_w1);
    GSYM(gh, g_gh);     GSYM(dh, g_dh);
    GSYM(ttt, g_ttt);   GSYM(sum, g_sum);

    float *hxt,*wqt,*wot,*fqt,*fkt,*fvt,*w02t,*w1t,*dgpt,*vlt,*htt,*hnt,*smt;
    GSYM(hxt, g_hx_t); GSYM(wqt, g_wq_t); GSYM(wot, g_wo_t);
    GSYM(fqt, g_fq_t); GSYM(fkt, g_fk_t); GSYM(fvt, g_fv_t);
    GSYM(w02t, g_w02_t); GSYM(w1t, g_w1_t);
    GSYM(dgpt, g_dgp_t); GSYM(vlt, g_vl_t); GSYM(htt, g_ht_t);
    GSYM(hnt, g_hn_t); GSYM(smt, g_sm_t);

    __nv_bfloat16 *aqh,*aql,*akh,*akl,*avh,*avl;
    GSYM(aqh, g_aq_h); GSYM(aql, g_aq_l); GSYM(akh, g_ak_h); GSYM(akl, g_ak_l);
    GSYM(avh, g_av_h); GSYM(avl, g_av_l);

    cudaFuncSetAttribute(tf_gemm<0,0,false,false>,
                         cudaFuncAttributeMaxDynamicSharedMemorySize, 73728);
    cudaFuncSetAttribute(tf_gemm<0,1,false,false>,
                         cudaFuncAttributeMaxDynamicSharedMemorySize, 71680);
    cudaFuncSetAttribute(tf_gemm<1,1,true,true>,
                         cudaFuncAttributeMaxDynamicSharedMemorySize, 69632);
    cudaFuncSetAttribute(attn_mma, cudaFuncAttributeMaxDynamicSharedMemorySize, ATTN_SMEM);

    #define G_NT(A,B,C,M,N,K,lda,ldb,sA,sB,sC,bat) \
        tf_gemm<0,0,false,false><<<dim3((N)/128,(M)/128,(bat)),256,73728>>>( \
            A,B,C,nullptr,M,N,K,lda,ldb,sA,sB,sC)
    #define G_NN(A,B,C,M,N,K,lda,ldb,sA,sB,sC,bat) \
        tf_gemm<0,1,false,false><<<dim3((N)/128,(M)/128,(bat)),256,71680>>>( \
            A,B,C,nullptr,M,N,K,lda,ldb,sA,sB,sC)
    #define G_TN_AS(A,B,C,Ct,M,N,K,lda,ldb,sA,sB,sC,bat) \
        tf_gemm<1,1,true,true><<<dim3((N)/128,(M)/128,(bat)),256,69632>>>( \
            A,B,C,Ct,M,N,K,lda,ldb,sA,sB,sC)

    cvt_tf<<<8192, 256>>>(hidden, hxt, (long)4096 * 2048);
    cvt_tf<<<12288, 256>>>(Wqkv, wqt, (long)6144 * 2048);
    cvt_tf<<<4096, 256>>>(Wo, wot, (long)2048 * 2048);

    G_NT(hxt, wqt, qkv, 4096, 6144, 2048, 2048, 2048, 0, 0, 0, 1);
    lr_gemm<<<2048, 256>>>(hidden, lrw, lrpre);

    float base = (float)(0.001 + log(-expm1(-0.001)));
    prep_kernel<<<4096, 256>>>(qkv, lrpre, qnw, knw, qksc, qkof, lrb, base,
                               aqh, aql, akh, akl, avh, avl,
                               fqt, fkt, fvt, lr);
    attn_mma<<<dim3(32, 16, 2), 256, ATTN_SMEM>>>(aqh, aql, akh, akl, avh, avl, sum);

    copyw<<<16384, 256>>>(w0, w1, w2, pw02, w02t, pw1, w1t);

    long sSeq = (long)SEQ * FDM;
    long sChk = (long)1024 * FDM;
    long sW   = (long)FDM * FDM;
    long sW02 = (long)1024 * FDM;
    long sGH  = (long)1024 * 1024;
    for (int ck = 0; ck < 2; ++ck) {
        int ck0 = ck * 1024;
        long co = (long)ck0 * FDM;
        G_NT(fkt + co, w02t, gh, 1024, 1024, 512, 512, 512, sSeq, sW02, sGH, 8);
        G_NN(fvt + co, w1t, dh, 1024, 512, 512, 512, 512, sSeq, sW, sChk, 8);
        elem2<<<16384, 256>>>(fvt, lr, gh, dh, dgpt, vlt, htt, ck0);
        G_TN_AS(dgpt, fkt + co, pw02, w02t, 1024, 512, 1024, 1024, 512, sGH, sSeq, sW02, 8);
        G_TN_AS(vlt, htt, pw1, w1t, 512, 512, 1024, 512, 512, sChk, sChk, sW, 8);
        G_NT(fqt + co, w02t, gh, 1024, 1024, 512, 512, 512, sSeq, sW02, sGH, 8);
        elem3<<<16384, 256>>>(gh, hnt);
        G_NT(hnt, w1t, ttt + co, 1024, 512, 512, 512, 512, sChk, sW, sSeq, 8);
    }

    post_kernel<<<dim3(4, 4096), 128>>>(ttt, tttw, sum, smt);
    G_NT(smt, wot, out, 4096, 2048, 2048, 2048, 2048, 0, 0, 0, 1);
    #undef G_NT
    #undef G_NN
    #undef G_TN_AS
}

// round 12
// speedup vs baseline: 7.0474x; 1.0428x over previous
#include <cuda_runtime.h>
#include <cuda_bf16.h>
#include <cstdint>
#include <math.h>

#define SEQ 2048
#define DIMD 2048
#define FDM 512

// ------------------------- fp32 scratch (device globals) --------------------
__device__ float g_qkv [(size_t)4096 * 6144];
__device__ float g_lrpre[(size_t)4096 * 12];
__device__ float g_lr  [(size_t)4096 * 12];
__device__ float g_w02 [(size_t)8 * 1024 * FDM];
__device__ float g_w1  [(size_t)8 * FDM * FDM];
__device__ float g_gh  [(size_t)8 * 1024 * 1024];
__device__ float g_dh  [(size_t)8 * 1024 * FDM];
__device__ float g_ttt [(size_t)8 * SEQ * FDM];
__device__ float g_sum [(size_t)4096 * 2048];

// ---------------------- tf32 (pre-rounded fp32) operands --------------------
__device__ float g_hx_t [(size_t)4096 * 2048];
__device__ float g_wq_t [(size_t)6144 * 2048];
__device__ float g_wo_t [(size_t)2048 * 2048];
__device__ float g_fq_t [(size_t)8 * SEQ * FDM];
__device__ float g_fk_t [(size_t)8 * SEQ * FDM];
__device__ float g_fv_t [(size_t)8 * SEQ * FDM];
__device__ float g_w02_t[(size_t)8 * 1024 * FDM];
__device__ float g_w1_t [(size_t)8 * FDM * FDM];
__device__ float g_dgp_t[(size_t)8 * 1024 * 1024];
__device__ float g_vl_t [(size_t)8 * 1024 * FDM];
__device__ float g_ht_t [(size_t)8 * 1024 * FDM];
__device__ float g_hn_t [(size_t)8 * 1024 * FDM];
__device__ float g_sm_t [(size_t)4096 * 2048];

// ------------------- bf16 hi/lo (attention only) ----------------------------
__device__ __nv_bfloat16 g_aq_h[(size_t)4096*2048], g_aq_l[(size_t)4096*2048];
__device__ __nv_bfloat16 g_ak_h[(size_t)4096*2048], g_ak_l[(size_t)4096*2048];
__device__ __nv_bfloat16 g_av_h[(size_t)4096*2048], g_av_l[(size_t)4096*2048];

// ------------------------------ helpers -------------------------------------
__device__ __forceinline__ uint32_t smem_u32(const void* p) {
    uint32_t a;
    asm("{ .reg .u64 t; cvta.to.shared.u64 t, %1; cvt.u32.u64 %0, t; }" : "=r"(a) : "l"(p));
    return a;
}
__device__ __forceinline__ void cpa16(uint32_t s, const void* g) {
    asm volatile("cp.async.cg.shared.global [%0], [%1], 16;" :: "r"(s), "l"(g));
}
#define CP_COMMIT() asm volatile("cp.async.commit_group;" ::: "memory")
#define MMA16816(d, a, b0, b1) \
    asm volatile("mma.sync.aligned.m16n8k16.row.col.f32.bf16.bf16.f32 " \
        "{%0,%1,%2,%3}, {%4,%5,%6,%7}, {%8,%9}, {%0,%1,%2,%3};" \
        : "+f"((d)[0]), "+f"((d)[1]), "+f"((d)[2]), "+f"((d)[3]) \
        : "r"((a)[0]), "r"((a)[1]), "r"((a)[2]), "r"((a)[3]), "r"(b0), "r"(b1))
#define MMATF(d, a, b0, b1) \
    asm volatile("mma.sync.aligned.m16n8k8.row.col.f32.tf32.tf32.f32 " \
        "{%0,%1,%2,%3}, {%4,%5,%6,%7}, {%8,%9}, {%0,%1,%2,%3};" \
        : "+f"((d)[0]), "+f"((d)[1]), "+f"((d)[2]), "+f"((d)[3]) \
        : "r"((a)[0]), "r"((a)[1]), "r"((a)[2]), "r"((a)[3]), "r"(b0), "r"(b1))
__device__ __forceinline__ void ldmx4(uint32_t* r, uint32_t addr) {
    asm volatile("ldmatrix.sync.aligned.m8n8.x4.shared.b16 {%0,%1,%2,%3}, [%4];"
        : "=r"(r[0]), "=r"(r[1]), "=r"(r[2]), "=r"(r[3]) : "r"(addr));
}
__device__ __forceinline__ void ldmx4t(uint32_t* r, uint32_t addr) {
    asm volatile("ldmatrix.sync.aligned.m8n8.x4.trans.shared.b16 {%0,%1,%2,%3}, [%4];"
        : "=r"(r[0]), "=r"(r[1]), "=r"(r[2]), "=r"(r[3]) : "r"(addr));
}
__device__ __forceinline__ void split_w(float v, __nv_bfloat16* h, __nv_bfloat16* l, long i) {
    __nv_bfloat16 hv = __float2bfloat16_rn(v);
    h[i] = hv;
    l[i] = __float2bfloat16_rn(v - __bfloat162float(hv));
}
__device__ __forceinline__ float to_tf32(float v) {
    uint32_t u;
    asm("cvt.rna.tf32.f32 %0, %1;" : "=r"(u) : "f"(v));
    return __uint_as_float(u);
}
__device__ __forceinline__ uint32_t lds_u32(uint32_t addr) {
    uint32_t v;
    asm volatile("ld.shared.b32 %0, [%1];" : "=r"(v) : "r"(addr));
    return v;
}

// -------------------- TF32 mma.sync batched GEMM (3-stage) ------------------
struct GP {
    const float* A; const float* B;
    float* C; float* Ct;
    int M, N, K, lda, ldb;
    long sA, sB, sC;
    int gx, gy;
};

template<int AT, int BT, bool ACC, bool SPLIT>
__device__ __forceinline__ void gemm_body(const GP p, int bz)
{
    if ((int)blockIdx.x >= p.gx || (int)blockIdx.y >= p.gy) return;
    constexpr int SA = AT ? 17408 : 18432;   // trans: 32*544 ; k-major: 128*144
    constexpr int SB = BT ? 17408 : 18432;
    constexpr int STAGE = SA + SB;
    extern __shared__ char smem[];
    uint32_t sb = smem_u32(smem);
    int tid = threadIdx.x, lane = tid & 31, wid = tid >> 5;
    int wm = wid >> 2, wn = wid & 3;
    const float* a = p.A + (long)bz * p.sA;
    const float* b = p.B + (long)bz * p.sB;
    int m0 = blockIdx.y << 7, n0 = blockIdx.x << 7;
    int lda = p.lda, ldb = p.ldb;

    float acc[4][4][4];
    #pragma unroll
    for (int i = 0; i < 4; ++i)
        #pragma unroll
        for (int j = 0; j < 4; ++j)
            #pragma unroll
            for (int q = 0; q < 4; ++q) acc[i][j][q] = 0.f;

    int Lm = lane >> 3, Lr = lane & 7;
    uint32_t aoff = (uint32_t)(((Lm & 1) * 8 + Lr) * 144 + (Lm >> 1) * 16);
    uint32_t boff = (uint32_t)(((Lm >> 1) * 8 + Lr) * 144 + (Lm & 1) * 16);

    auto issue = [&](int buf, int k0) {
        uint32_t st = sb + buf * STAGE;
        #pragma unroll
        for (int j = 0; j < 4; ++j) {
            int u = tid + j * 256;
            uint32_t so; long g;
            if (AT == 0) { int r = u >> 3, s = u & 7;  so = r * 144 + s * 16;
                           g = (long)(m0 + r) * lda + k0 + s * 4; }
            else         { int r = u >> 5, s = u & 31; so = r * 544 + s * 16;
                           g = (long)(k0 + r) * lda + m0 + s * 4; }
            cpa16(st + so, a + g);
            if (BT == 0) { int r = u >> 3, s = u & 7;  so = r * 144 + s * 16;
                           g = (long)(n0 + r) * ldb + k0 + s * 4; }
            else         { int r = u >> 5, s = u & 31; so = r * 544 + s * 16;
                           g = (long)(k0 + r) * ldb + n0 + s * 4; }
            cpa16(st + SA + so, b + g);
        }
        CP_COMMIT();
    };

    const int n = p.K >> 5;
    issue(0, 0);
    if (n > 1) issue(1, 32);
    int buf = 0;
    for (int i = 0; i < n; ++i) {
        if (i + 1 < n) asm volatile("cp.async.wait_group 1;" ::: "memory");
        else           asm volatile("cp.async.wait_group 0;" ::: "memory");
        __syncthreads();
        uint32_t st = sb + buf * STAGE;
        uint32_t stB = st + SA;
        #pragma unroll
        for (int kk = 0; kk < 32; kk += 8) {
            uint32_t af[4][4];
            #pragma unroll
            for (int mt = 0; mt < 4; ++mt) {
                if (AT == 0) {
                    ldmx4(af[mt], st + (wm * 64 + mt * 16) * 144 + kk * 4 + aoff);
                } else {
                    uint32_t ra = st + (kk + (lane & 3)) * 544
                                + (wm * 64 + mt * 16 + (lane >> 2)) * 4;
                    af[mt][0] = lds_u32(ra);
                    af[mt][1] = lds_u32(ra + 32);
                    af[mt][2] = lds_u32(ra + 4 * 544);
                    af[mt][3] = lds_u32(ra + 4 * 544 + 32);
                }
            }
            uint32_t bf_[4][2];
            if (BT == 0) {
                #pragma unroll
                for (int pp = 0; pp < 2; ++pp) {
                    uint32_t r4[4];
                    ldmx4(r4, stB + (wn * 32 + pp * 16) * 144 + kk * 4 + boff);
                    bf_[pp * 2 + 0][0] = r4[0]; bf_[pp * 2 + 0][1] = r4[1];
                    bf_[pp * 2 + 1][0] = r4[2]; bf_[pp * 2 + 1][1] = r4[3];
                }
            } else {
                #pragma unroll
                for (int nt = 0; nt < 4; ++nt) {
                    uint32_t rb = stB + (kk + (lane & 3)) * 544
                                + (wn * 32 + nt * 8 + (lane >> 2)) * 4;
                    bf_[nt][0] = lds_u32(rb);
                    bf_[nt][1] = lds_u32(rb + 4 * 544);
                }
            }
            #pragma unroll
            for (int nt = 0; nt < 4; ++nt)
                #pragma unroll
                for (int mt = 0; mt < 4; ++mt)
                    MMATF(acc[mt][nt], af[mt], bf_[nt][0], bf_[nt][1]);
        }
        if (i + 2 < n) issue((i + 2) % 3, (i + 2) * 32);
        buf = (buf == 2) ? 0 : buf + 1;
    }
    float* c = p.C + (long)bz * p.sC;
    float* ct = SPLIT ? p.Ct + (long)bz * p.sC : nullptr;
    int N = p.N;
    #pragma unroll
    for (int mt = 0; mt < 4; ++mt) {
        #pragma unroll
        for (int nt = 0; nt < 4; ++nt) {
            long r0 = m0 + wm * 64 + mt * 16 + (lane >> 2);
            int  cc = n0 + wn * 32 + nt * 8 + (lane & 3) * 2;
            long o0 = r0 * (long)N + cc;
            long o1 = (r0 + 8) * (long)N + cc;
            float v00 = acc[mt][nt][0], v01 = acc[mt][nt][1];
            float v10 = acc[mt][nt][2], v11 = acc[mt][nt][3];
            if (ACC) {
                float2 t0 = *(float2*)(c + o0), t1 = *(float2*)(c + o1);
                v00 += t0.x; v01 += t0.y; v10 += t1.x; v11 += t1.y;
            }
            *(float2*)(c + o0) = make_float2(v00, v01);
            *(float2*)(c + o1) = make_float2(v10, v11);
            if (SPLIT) {
                *(float2*)(ct + o0) = make_float2(to_tf32(v00), to_tf32(v01));
                *(float2*)(ct + o1) = make_float2(to_tf32(v10), to_tf32(v11));
            }
        }
    }
}

__global__ void __launch_bounds__(256, 2) tf_nt(GP p) {
    gemm_body<0, 0, false, false>(p, blockIdx.z);
}
__global__ void __launch_bounds__(256, 2) tf_pack_fwd(GP p1, GP p2, int z1) {
    if ((int)blockIdx.z < z1) gemm_body<0, 0, false, false>(p1, blockIdx.z);
    else                      gemm_body<0, 1, false, false>(p2, blockIdx.z - z1);
}
__global__ void __launch_bounds__(256, 2) tf_pack_upd(GP p1, GP p2, int z1) {
    if ((int)blockIdx.z < z1) gemm_body<1, 1, true, true>(p1, blockIdx.z);
    else                      gemm_body<1, 1, true, true>(p2, blockIdx.z - z1);
}

// ------------------------ conversion kernel ---------------------------------
__global__ void cvt_tf(const float* __restrict__ x, float* __restrict__ o, long n)
{
    long i = ((long)blockIdx.x * 256 + threadIdx.x) * 4;
    if (i >= n) return;
    float4 v = *(const float4*)(x + i);
    float4 w;
    w.x = to_tf32(v.x); w.y = to_tf32(v.y); w.z = to_tf32(v.z); w.w = to_tf32(v.w);
    *(float4*)(o + i) = w;
}

// ---------------- small SGEMM for the N=12 lr GEMM --------------------------
__global__ void lr_gemm(const float* __restrict__ A, const float* __restrict__ B,
                        float* __restrict__ C)
{
    __shared__ float bs[12][128];
    int row = blockIdx.x * 2 + (threadIdx.x >> 7);
    int tid = threadIdx.x & 127;
    float acc[12];
    #pragma unroll
    for (int c = 0; c < 12; ++c) acc[c] = 0.f;
    for (int k0 = 0; k0 < 2048; k0 += 128) {
        if (threadIdx.x < 128)
            #pragma unroll
            for (int c = 0; c < 12; ++c) bs[c][tid] = B[c * 2048 + k0 + tid];
        __syncthreads();
        float a = A[(long)row * 2048 + k0 + tid];
        #pragma unroll
        for (int c = 0; c < 12; ++c) acc[c] += a * bs[c][tid];
        __syncthreads();
    }
    __shared__ float red[2][12][4];
    #pragma unroll
    for (int c = 0; c < 12; ++c) {
        float v = acc[c];
        #pragma unroll
        for (int o = 16; o > 0; o >>= 1) v += __shfl_down_sync(0xffffffffu, v, o);
        if ((tid & 31) == 0) red[threadIdx.x >> 7][c][tid >> 5] = v;
    }
    __syncthreads();
    if (tid < 12) {
        int w = threadIdx.x >> 7;
        C[(long)row * 12 + tid] = red[w][tid][0] + red[w][tid][1] + red[w][tid][2] + red[w][tid][3];
    }
}

// ------------------------- block reduce (256 thr) ---------------------------
__device__ __forceinline__ float blockReduceSum(float v, float* sred)
{
    int lane = threadIdx.x & 31;
    #pragma unroll
    for (int o = 16; o > 0; o >>= 1) v += __shfl_down_sync(0xffffffffu, v, o);
    if (lane == 0) sred[threadIdx.x >> 5] = v;
    __syncthreads();
    if (threadIdx.x < 8) {
        float r = sred[threadIdx.x];
        #pragma unroll
        for (int o = 4; o > 0; o >>= 1) r += __shfl_down_sync(0xffu, r, o);
        if (threadIdx.x == 0) sred[0] = r;
    }
    __syncthreads();
    float out = sred[0];
    __syncthreads();
    return out;
}

// --------- prep: rmsnorm+rope + silu/L2 + lr ---------------------------------
__global__ void prep_kernel(const float* __restrict__ qkv, const float* __restrict__ lrpre,
                            const float* __restrict__ qnw, const float* __restrict__ knw,
                            const float* __restrict__ qksc, const float* __restrict__ qkof,
                            const float* __restrict__ lrb, float base_lr_inv,
                            __nv_bfloat16* __restrict__ aqh, __nv_bfloat16* __restrict__ aql,
                            __nv_bfloat16* __restrict__ akh, __nv_bfloat16* __restrict__ akl,
                            __nv_bfloat16* __restrict__ avh, __nv_bfloat16* __restrict__ avl,
                            float* __restrict__ fqt, float* __restrict__ fkt,
                            float* __restrict__ fvt, float* __restrict__ lrout)
{
    __shared__ float s_q[2048];
    __shared__ float s_k[2048];
    __shared__ float sred[8];
    int row = blockIdx.x;
    int b = row >> 11, t = row & 2047;
    int tid = threadIdx.x;
    const float* qr = qkv + (long)row * 6144;
    const float* kr = qr + 2048;
    const float* vr = qr + 4096;
    const float qscale = 0.088388347648318447f * 1.4426950408889634f;

    float qv[8], kv[8], fqv[8], fkv[8], fvv[8];
    float sq = 0.f, sk = 0.f;
    float p2q[4] = {0, 0, 0, 0}, p2k[4] = {0, 0, 0, 0};
    #pragma unroll
    for (int j = 0; j < 8; ++j) {
        int i = j * 256 + tid;
        float q = qr[i], k = kr[i], v = vr[i];
        qv[j] = q; kv[j] = k;
        sq += q * q; sk += k * k;
        float fqe = (q / (1.f + expf(-q))) * qksc[i * 2 + 0] + qkof[i * 2 + 0];
        float fke = (k / (1.f + expf(-k))) * qksc[i * 2 + 1] + qkof[i * 2 + 1];
        fqv[j] = fqe; fkv[j] = fke; fvv[j] = v / (1.f + expf(-v));
        p2q[j >> 1] += fqe * fqe;
        p2k[j >> 1] += fke * fke;
        split_w(v, avh, avl, (long)row * DIMD + i);
    }
    float SQ = blockReduceSum(sq, sred);
    float SK = blockReduceSum(sk, sred);
    float G2Q[4], G2K[4];
    #pragma unroll
    for (int g = 0; g < 4; ++g) G2Q[g] = blockReduceSum(p2q[g], sred);
    #pragma unroll
    for (int g = 0; g < 4; ++g) G2K[g] = blockReduceSum(p2k[g], sred);
    float rq = rsqrtf(SQ * (1.f / 2048.f) + 1e-6f);
    float rk = rsqrtf(SK * (1.f / 2048.f) + 1e-6f);
    #pragma unroll
    for (int j = 0; j < 8; ++j) {
        int i = j * 256 + tid;
        s_q[i] = qv[j] * rq * qnw[i];
        s_k[i] = kv[j] * rk * knw[i];
        int g = j >> 1;
        long fb = (((long)(b * 4 + g)) * SEQ + t) * FDM + (i & 511);
        fqt[fb] = to_tf32(fqv[j] / (sqrtf(G2Q[g]) + 1e-12f));
        fkt[fb] = to_tf32(fkv[j] / (sqrtf(G2K[g]) + 1e-12f));
        fvt[fb] = to_tf32(fvv[j]);
    }
    __syncthreads();
    #pragma unroll
    for (int j = 0; j < 8; ++j) {
        int i = j * 256 + tid;
        int pos = i & 127;
        int fi = pos & 63;
        float invf = expf(-(float)fi * (logf(500000.f) / 64.f));
        float sn, cs;
        sincosf((float)t * invf, &sn, &cs);
        float oq, ok_;
        if (pos < 64) {
            oq  = s_q[i] * cs - s_q[i + 64] * sn;
            ok_ = s_k[i] * cs - s_k[i + 64] * sn;
        } else {
            oq  = s_q[i] * cs + s_q[i - 64] * sn;
            ok_ = s_k[i] * cs + s_k[i - 64] * sn;
        }
        split_w(oq * qscale, aqh, aql, (long)row * DIMD + i);
        split_w(ok_, akh, akl, (long)row * DIMD + i);
    }
    if (tid < 12) {
        float x = lrpre[(long)row * 12 + tid] + lrb[tid] + base_lr_inv;
        lrout[(long)row * 12 + tid] = (x > 20.f) ? x : log1pf(expf(x));
    }
}

// -------------------- HMMA windowed flash attention (unchanged) --------------
#define ATS 272
#define PST 144
#define O_QH 0
#define O_QL 17408
#define O_KH 34816
#define O_KL 52224
#define O_VH 69632
#define O_VL 87040
#define O_S  104448
#define O_PH 121856
#define O_PL 131072
#define O_CR 140288
#define O_LR 140544
#define ATTN_SMEM 140800

__global__ void __launch_bounds__(256, 1)
attn_mma(const __nv_bfloat16* __restrict__ Qh, const __nv_bfloat16* __restrict__ Ql,
         const __nv_bfloat16* __restrict__ Kh, const __nv_bfloat16* __restrict__ Kl,
         const __nv_bfloat16* __restrict__ Vh, const __nv_bfloat16* __restrict__ Vl,
         float* __restrict__ O)
{
    extern __shared__ char smc[];
    uint32_t sb = smem_u32(smc);
    float* Sf = (float*)(smc + O_S);
    float* carr = (float*)(smc + O_CR);
    float* larr = (float*)(smc + O_LR);
    __nv_bfloat16* Pho = (__nv_bfloat16*)(smc + O_PH);
    __nv_bfloat16* Plo = (__nv_bfloat16*)(smc + O_PL);

    int tid = threadIdx.x, lane = tid & 31, wid = tid >> 5;
    int q0 = blockIdx.x << 6, h = blockIdx.y, b = blockIdx.z;
    int wr = (wid & 3) * 16;
    int wc = wid >> 2;
    uint32_t a_row = (lane & 7) + ((lane >> 3) & 1) * 8;
    uint32_t a_kb  = ((lane >> 4) & 1) * 16;
    uint32_t b_row = (lane & 7) + ((lane >> 4) & 1) * 8;
    uint32_t b_kb  = ((lane >> 3) & 1) * 16;
    uint32_t b_kr  = (lane & 7) + ((lane >> 3) & 1) * 8;
    uint32_t b_no  = ((lane >> 4) & 1) * 8;
    int tq = tid >> 2, td = tid & 3;

    #pragma unroll
    for (int j = 0; j < 4; ++j) {
        int u = tid + j * 256;
        int r = u >> 4, s = u & 15;
        long g = ((long)(b * SEQ + q0 + r)) * DIMD + h * 128 + s * 8;
        cpa16(sb + O_QH + r * ATS + s * 16, Qh + g);
        cpa16(sb + O_QL + r * ATS + s * 16, Ql + g);
    }
    CP_COMMIT();

    float oacc[8][4];
    #pragma unroll
    for (int i = 0; i < 8; ++i)
        #pragma unroll
        for (int q = 0; q < 4; ++q) oacc[i][q] = 0.f;
    float m = -INFINITY, lrow = 0.f;

    int kt_hi = q0 >> 6;
    int kt_lo = (q0 >= 1024) ? ((q0 - 1023) >> 6) : 0;
    for (int kt = kt_lo; kt <= kt_hi; ++kt) {
        int j0 = kt << 6;
        __syncthreads();
        #pragma unroll
        for (int j = 0; j < 4; ++j) {
            int u = tid + j * 256;
            int r = u >> 4, s = u & 15;
            long g = ((long)(b * SEQ + j0 + r)) * DIMD + h * 128 + s * 8;
            uint32_t so = r * ATS + s * 16;
            cpa16(sb + O_KH + so, Kh + g);
            cpa16(sb + O_KL + so, Kl + g);
            cpa16(sb + O_VH + so, Vh + g);
            cpa16(sb + O_VL + so, Vl + g);
        }
        CP_COMMIT();
        asm volatile("cp.async.wait_group 0;" ::: "memory");
        __syncthreads();

        float sacc[4][4];
        #pragma unroll
        for (int i = 0; i < 4; ++i)
            #pragma unroll
            for (int q = 0; q < 4; ++q) sacc[i][q] = 0.f;
        #pragma unroll
        for (int kk = 0; kk < 8; ++kk) {
            uint32_t ah4[4], al4[4];
            uint32_t ra = sb + O_QH + (wr + a_row) * ATS + kk * 32 + a_kb;
            ldmx4(ah4, ra);
            ldmx4(al4, ra + (O_QL - O_QH));
            uint32_t bh4[2][4], bl4[2][4];
            #pragma unroll
            for (int p = 0; p < 2; ++p) {
                uint32_t rb = sb + O_KH + (wc * 32 + p * 16 + b_row) * ATS + kk * 32 + b_kb;
                ldmx4(bh4[p], rb);
                ldmx4(bl4[p], rb + (O_KL - O_KH));
            }
            #pragma unroll
            for (int nt = 0; nt < 4; ++nt) {
                uint32_t b0h = bh4[nt >> 1][(nt & 1) * 2 + 0];
                uint32_t b1h = bh4[nt >> 1][(nt & 1) * 2 + 1];
                uint32_t b0l = bl4[nt >> 1][(nt & 1) * 2 + 0];
                uint32_t b1l = bl4[nt >> 1][(nt & 1) * 2 + 1];
                MMA16816(sacc[nt], ah4, b0h, b1h);
                MMA16816(sacc[nt], ah4, b0l, b1l);
                MMA16816(sacc[nt], al4, b0h, b1h);
            }
        }
        #pragma unroll
        for (int nt = 0; nt < 4; ++nt) {
            int col = wc * 32 + nt * 8 + (lane & 3) * 2;
            int r0 = wr + (lane >> 2);
            Sf[r0 * 68 + col] = sacc[nt][0];
            Sf[r0 * 68 + col + 1] = sacc[nt][1];
            Sf[(r0 + 8) * 68 + col] = sacc[nt][2];
            Sf[(r0 + 8) * 68 + col + 1] = sacc[nt][3];
        }
        __syncthreads();

        int ig = q0 + tq;
        float sv[16], tmax = -INFINITY;
        #pragma unroll
        for (int j = 0; j < 16; ++j) {
            int col = td * 16 + j;
            int jg = j0 + col;
            bool ok = (jg <= ig) && (ig - jg < 1024);
            float s = ok ? Sf[tq * 68 + col] : -INFINITY;
            sv[j] = s;
            tmax = fmaxf(tmax, s);
        }
        tmax = fmaxf(tmax, __shfl_xor_sync(0xffffffffu, tmax, 1));
        tmax = fmaxf(tmax, __shfl_xor_sync(0xffffffffu, tmax, 2));
        float mt = fmaxf(m, tmax);
        float mte = (mt > -INFINITY) ? mt : 0.f;
        float corr = exp2f(m - mte);
        float ls = 0.f;
        #pragma unroll
        for (int j = 0; j < 16; ++j) {
            int col = td * 16 + j;
            float p = exp2f(sv[j] - mte);
            ls += p;
            __nv_bfloat16 ph = __float2bfloat16_rn(p);
            Pho[tq * 72 + col] = ph;
            Plo[tq * 72 + col] = __float2bfloat16_rn(p - __bfloat162float(ph));
        }
        ls += __shfl_xor_sync(0xffffffffu, ls, 1);
        ls += __shfl_xor_sync(0xffffffffu, ls, 2);
        lrow = lrow * corr + ls;
        m = mt;
        if (td == 0) carr[tq] = corr;
        __syncthreads();

        {
            float c0 = carr[wr + (lane >> 2)];
            float c1 = carr[wr + 8 + (lane >> 2)];
            #pragma unroll
            for (int nt = 0; nt < 8; ++nt) {
                oacc[nt][0] *= c0; oacc[nt][1] *= c0;
                oacc[nt][2] *= c1; oacc[nt][3] *= c1;
            }
        }
        #pragma unroll
        for (int ktile = 0; ktile < 4; ++ktile) {
            uint32_t ph4[4], pl4[4];
            uint32_t ra = sb + O_PH + (wr + a_row) * PST + ktile * 32 + a_kb;
            ldmx4(ph4, ra);
            ldmx4(pl4, ra + (O_PL - O_PH));
            #pragma unroll
            for (int p2 = 0; p2 < 4; ++p2) {
                uint32_t vh4[4], vl4[4];
                uint32_t rb = sb + O_VH + (ktile * 16 + b_kr) * ATS + (wc * 64 + p2 * 16 + b_no) * 2;
                ldmx4t(vh4, rb);
                ldmx4t(vl4, rb + (O_VL - O_VH));
                #pragma unroll
                for (int sub = 0; sub < 2; ++sub) {
                    int nt = p2 * 2 + sub;
                    uint32_t b0h = vh4[sub * 2], b1h = vh4[sub * 2 + 1];
                    uint32_t b0l = vl4[sub * 2], b1l = vl4[sub * 2 + 1];
                    MMA16816(oacc[nt], ph4, b0h, b1h);
                    MMA16816(oacc[nt], ph4, b0l, b1l);
                    MMA16816(oacc[nt], pl4, b0h, b1h);
                }
            }
        }
    }
    if (td == 0) larr[tq] = lrow;
    __syncthreads();
    {
        int r0 = wr + (lane >> 2);
        float l0 = 1.f / larr[r0], l1 = 1.f / larr[r0 + 8];
        #pragma unroll
        for (int nt = 0; nt < 8; ++nt) {
            int col = wc * 64 + nt * 8 + (lane & 3) * 2;
            long o0 = ((long)(b * SEQ + q0 + r0)) * 2048 + h * 128 + col;
            long o1 = ((long)(b * SEQ + q0 + r0 + 8)) * 2048 + h * 128 + col;
            *(float2*)(O + o0) = make_float2(oacc[nt][0] * l0, oacc[nt][1] * l0);
            *(float2*)(O + o1) = make_float2(oacc[nt][2] * l1, oacc[nt][3] * l1);
        }
    }
}

// --------------------------- TTT helper kernels -----------------------------
__global__ void copyw(const float* __restrict__ w0, const float* __restrict__ w1,
                      const float* __restrict__ w2,
                      float* __restrict__ o02, float* __restrict__ o02t,
                      float* __restrict__ o1, float* __restrict__ o1t)
{
    long idx = (long)blockIdx.x * 256 + threadIdx.x;
    int col = idx & 511;
    int row = (idx >> 9) & 1023;
    int h = (idx >> 19) & 3;
    long src = (long)h * 262144 + (long)(row & 511) * 512 + col;
    float v = (row < 512) ? w0[src] : w2[src];
    o02[idx] = v;
    o02t[idx] = to_tf32(v);
    if (idx < (long)2 * 1024 * 1024) {
        float v1 = w1[idx & ((long)4 * 262144 - 1)];
        o1[idx] = v1;
        o1t[idx] = to_tf32(v1);
    }
}

__global__ void elem2(const float* __restrict__ fvt, const float* __restrict__ lr,
                      const float* __restrict__ gh, const float* __restrict__ dhin,
                      float* __restrict__ dgpt, float* __restrict__ vlt,
                      float* __restrict__ htt, int ck0)
{
    long idx = (long)blockIdx.x * 256 + threadIdx.x;
    int col = idx & 511;
    long tt = idx >> 9;
    int c = tt & 1023, bh = tt >> 10;
    int b = bh >> 2, h = bh & 3;
    long row = (long)b * SEQ + ck0 + c;
    float l0 = lr[row * 12 + h], l1 = lr[row * 12 + 4 + h], l2 = lr[row * 12 + 8 + h];
    long gi = (long)bh * 1048576 + (long)c * 1024 + col;
    float g = gh[gi], hp = gh[gi + 512], d = dhin[idx];
    float sig = 1.f / (1.f + expf(-g));
    float sg = g * sig;
    htt[idx] = to_tf32(sg * hp);
    float v = fvt[((long)bh * SEQ + ck0 + c) * FDM + col];
    dgpt[gi]       = to_tf32(d * hp * (sig * (1.f + g * (1.f - sig))) * l0);
    dgpt[gi + 512] = to_tf32(d * sg * l2);
    vlt[idx]       = to_tf32(v * l1);
}

__global__ void elem3(const float* __restrict__ gh, float* __restrict__ hnt)
{
    long idx = (long)blockIdx.x * 256 + threadIdx.x;
    int col = idx & 511;
    long tt = idx >> 9;
    int c = tt & 1023, bh = tt >> 10;
    long gi = (long)bh * 1048576 + (long)c * 1024 + col;
    float g = gh[gi];
    hnt[idx] = to_tf32((g / (1.f + expf(-g))) * gh[gi + 512]);
}

// -------------------- ttt rmsnorm + add attention result --------------------
__global__ void post_kernel(const float* __restrict__ ttt, const float* __restrict__ tw,
                            const float* __restrict__ sum, float* __restrict__ smt)
{
    __shared__ float sr[4];
    int fh = blockIdx.x, row = blockIdx.y;
    int b = row >> 11, t = row & 2047;
    int bh = b * 4 + fh;
    const float* src = ttt + ((long)bh * SEQ + t) * FDM;
    int tid = threadIdx.x;
    float v[4], ss = 0.f;
    #pragma unroll
    for (int j = 0; j < 4; ++j) { v[j] = src[tid + 128 * j]; ss += v[j] * v[j]; }
    #pragma unroll
    for (int o = 16; o > 0; o >>= 1) ss += __shfl_down_sync(0xffffffffu, ss, o);
    if ((tid & 31) == 0) sr[tid >> 5] = ss;
    __syncthreads();
    float tot = sr[0] + sr[1] + sr[2] + sr[3];
    float r = rsqrtf(tot * (1.f / 512.f) + 1e-6f);
    #pragma unroll
    for (int j = 0; j < 4; ++j) {
        int i = tid + 128 * j;
        long o = (long)row * 2048 + fh * 512 + i;
        smt[o] = to_tf32(sum[o] + v[j] * r * tw[i]);
    }
}

// --------------------------------- launch -----------------------------------
#define GSYM(p, s) cudaGetSymbolAddress((void**)&(p), s)

extern "C" void kernel_launch(void* const* d_in, const int* in_sizes, int n_in,
                              void* d_out, int out_size)
{
    const float* hidden = (const float*)d_in[0];
    const float* Wqkv   = (const float*)d_in[1];
    const float* Wo     = (const float*)d_in[2];
    const float* qnw    = (const float*)d_in[3];
    const float* knw    = (const float*)d_in[4];
    const float* w0     = (const float*)d_in[5];
    const float* w1     = (const float*)d_in[6];
    const float* w2     = (const float*)d_in[7];
    const float* lrw    = (const float*)d_in[8];
    const float* lrb    = (const float*)d_in[9];
    const float* qksc   = (const float*)d_in[10];
    const float* qkof   = (const float*)d_in[11];
    const float* tttw   = (const float*)d_in[12];
    float* out = (float*)d_out;

    float *qkv, *lrpre, *lr, *pw02, *pw1, *gh, *dh, *ttt, *sum;
    GSYM(qkv, g_qkv);   GSYM(lrpre, g_lrpre); GSYM(lr, g_lr);
    GSYM(pw02, g_w02);  GSYM(pw1, g_w1);
    GSYM(gh, g_gh);     GSYM(dh, g_dh);
    GSYM(ttt, g_ttt);   GSYM(sum, g_sum);

    float *hxt,*wqt,*wot,*fqt,*fkt,*fvt,*w02t,*w1t,*dgpt,*vlt,*htt,*hnt,*smt;
    GSYM(hxt, g_hx_t); GSYM(wqt, g_wq_t); GSYM(wot, g_wo_t);
    GSYM(fqt, g_fq_t); GSYM(fkt, g_fk_t); GSYM(fvt, g_fv_t);
    GSYM(w02t, g_w02_t); GSYM(w1t, g_w1_t);
    GSYM(dgpt, g_dgp_t); GSYM(vlt, g_vl_t); GSYM(htt, g_ht_t);
    GSYM(hnt, g_hn_t); GSYM(smt, g_sm_t);

    __nv_bfloat16 *aqh,*aql,*akh,*akl,*avh,*avl;
    GSYM(aqh, g_aq_h); GSYM(aql, g_aq_l); GSYM(akh, g_ak_h); GSYM(akl, g_ak_l);
    GSYM(avh, g_av_h); GSYM(avl, g_av_l);

    cudaFuncSetAttribute(tf_nt, cudaFuncAttributeMaxDynamicSharedMemorySize, 110592);
    cudaFuncSetAttribute(tf_pack_fwd, cudaFuncAttributeMaxDynamicSharedMemorySize, 110592);
    cudaFuncSetAttribute(tf_pack_upd, cudaFuncAttributeMaxDynamicSharedMemorySize, 104448);
    cudaFuncSetAttribute(attn_mma, cudaFuncAttributeMaxDynamicSharedMemorySize, ATTN_SMEM);

    cvt_tf<<<8192, 256>>>(hidden, hxt, (long)4096 * 2048);
    cvt_tf<<<12288, 256>>>(Wqkv, wqt, (long)6144 * 2048);
    cvt_tf<<<4096, 256>>>(Wo, wot, (long)2048 * 2048);

    {
        GP p{hxt, wqt, qkv, nullptr, 4096, 6144, 2048, 2048, 2048, 0, 0, 0, 48, 32};
        tf_nt<<<dim3(48, 32, 1), 256, 110592>>>(p);
    }
    lr_gemm<<<2048, 256>>>(hidden, lrw, lrpre);

    float base = (float)(0.001 + log(-expm1(-0.001)));
    prep_kernel<<<4096, 256>>>(qkv, lrpre, qnw, knw, qksc, qkof, lrb, base,
                               aqh, aql, akh, akl, avh, avl,
                               fqt, fkt, fvt, lr);
    attn_mma<<<dim3(32, 16, 2), 256, ATTN_SMEM>>>(aqh, aql, akh, akl, avh, avl, sum);

    copyw<<<16384, 256>>>(w0, w1, w2, pw02, w02t, pw1, w1t);

    long sSeq = (long)SEQ * FDM;
    long sChk = (long)1024 * FDM;
    long sW   = (long)FDM * FDM;
    long sW02 = (long)1024 * FDM;
    long sGH  = (long)1024 * 1024;
    for (int ck = 0; ck < 2; ++ck) {
        int ck0 = ck * 1024;
        long co = (long)ck0 * FDM;
        // forward: gh = K @ W02^T (NT)  ||  dh = V @ W1 (NN), packed
        {
            GP p1{fkt + co, w02t, gh, nullptr, 1024, 1024, 512, 512, 512, sSeq, sW02, sGH, 8, 8};
            GP p2{fvt + co, w1t, dh, nullptr, 1024, 512, 512, 512, 512, sSeq, sW, sChk, 4, 8};
            tf_pack_fwd<<<dim3(8, 8, 16), 256, 110592>>>(p1, p2, 8);
        }
        elem2<<<16384, 256>>>(fvt, lr, gh, dh, dgpt, vlt, htt, ck0);
        // updates: W02 += dgp^T @ K  ||  W1 += vl^T @ ht, packed (TN, acc, split)
        {
            GP p1{dgpt, fkt + co, pw02, w02t, 1024, 512, 1024, 1024, 512, sGH, sSeq, sW02, 4, 8};
            GP p2{vlt, htt, pw1, w1t, 512, 512, 1024, 512, 512, sChk, sChk, sW, 4, 4};
            tf_pack_upd<<<dim3(4, 8, 16), 256, 104448>>>(p1, p2, 8);
        }
        // query pass
        {
            GP p{fqt + co, w02t, gh, nullptr, 1024, 1024, 512, 512, 512, sSeq, sW02, sGH, 8, 8};
            tf_nt<<<dim3(8, 8, 8), 256, 110592>>>(p);
        }
        elem3<<<16384, 256>>>(gh, hnt);
        {
            GP p{hnt, w1t, ttt + co, nullptr, 1024, 512, 512, 512, 512, sChk, sW, sSeq, 4, 8};
            tf_nt<<<dim3(4, 8, 8), 256, 110592>>>(p);
        }
    }

    post_kernel<<<dim3(4, 4096), 128>>>(ttt, tttw, sum, smt);
    {
        GP p{smt, wot, out, nullptr, 4096, 2048, 2048, 2048, 2048, 0, 0, 0, 16, 32};
        tf_nt<<<dim3(16, 32, 1), 256, 110592>>>(p);
    }
}

// round 13
// speedup vs baseline: 7.5022x; 1.0645x over previous
#include <cuda_runtime.h>
#include <cuda_bf16.h>
#include <cstdint>
#include <math.h>

#define SEQ 2048
#define DIMD 2048
#define FDM 512

// ------------------------- fp32 scratch (device globals) --------------------
__device__ float g_qkv [(size_t)4096 * 6144];
__device__ float g_lrpre[(size_t)4096 * 12];
__device__ float g_lr  [(size_t)4096 * 12];
__device__ float g_w02 [(size_t)8 * 1024 * FDM];
__device__ float g_w1  [(size_t)8 * FDM * FDM];
__device__ float g_gh  [(size_t)8 * 1024 * 1024];
__device__ float g_dh  [(size_t)8 * 1024 * FDM];
__device__ float g_ttt [(size_t)8 * SEQ * FDM];
__device__ float g_sum [(size_t)4096 * 2048];

// ---------------------- tf32 (pre-rounded fp32) operands --------------------
__device__ float g_hx_t [(size_t)4096 * 2048];
__device__ float g_wq_t [(size_t)6144 * 2048];
__device__ float g_wo_t [(size_t)2048 * 2048];
__device__ float g_fq_t [(size_t)8 * SEQ * FDM];
__device__ float g_fk_t [(size_t)8 * SEQ * FDM];
__device__ float g_fv_t [(size_t)8 * SEQ * FDM];
__device__ float g_w02_t[(size_t)8 * 1024 * FDM];
__device__ float g_w1_t [(size_t)8 * FDM * FDM];
__device__ float g_dgp_t[(size_t)8 * 1024 * 1024];
__device__ float g_vl_t [(size_t)8 * 1024 * FDM];
__device__ float g_ht_t [(size_t)8 * 1024 * FDM];
__device__ float g_hn_t [(size_t)8 * 1024 * FDM];
__device__ float g_sm_t [(size_t)4096 * 2048];

// ------------------- bf16 hi/lo (attention only) ----------------------------
__device__ __nv_bfloat16 g_aq_h[(size_t)4096*2048], g_aq_l[(size_t)4096*2048];
__device__ __nv_bfloat16 g_ak_h[(size_t)4096*2048], g_ak_l[(size_t)4096*2048];
__device__ __nv_bfloat16 g_av_h[(size_t)4096*2048], g_av_l[(size_t)4096*2048];

// ------------------------------ helpers -------------------------------------
__device__ __forceinline__ uint32_t smem_u32(const void* p) {
    uint32_t a;
    asm("{ .reg .u64 t; cvta.to.shared.u64 t, %1; cvt.u32.u64 %0, t; }" : "=r"(a) : "l"(p));
    return a;
}
__device__ __forceinline__ void cpa16(uint32_t s, const void* g) {
    asm volatile("cp.async.cg.shared.global [%0], [%1], 16;" :: "r"(s), "l"(g));
}
#define CP_COMMIT() asm volatile("cp.async.commit_group;" ::: "memory")
#define MMA16816(d, a, b0, b1) \
    asm volatile("mma.sync.aligned.m16n8k16.row.col.f32.bf16.bf16.f32 " \
        "{%0,%1,%2,%3}, {%4,%5,%6,%7}, {%8,%9}, {%0,%1,%2,%3};" \
        : "+f"((d)[0]), "+f"((d)[1]), "+f"((d)[2]), "+f"((d)[3]) \
        : "r"((a)[0]), "r"((a)[1]), "r"((a)[2]), "r"((a)[3]), "r"(b0), "r"(b1))
#define MMATF(d, a, b0, b1) \
    asm volatile("mma.sync.aligned.m16n8k8.row.col.f32.tf32.tf32.f32 " \
        "{%0,%1,%2,%3}, {%4,%5,%6,%7}, {%8,%9}, {%0,%1,%2,%3};" \
        : "+f"((d)[0]), "+f"((d)[1]), "+f"((d)[2]), "+f"((d)[3]) \
        : "r"((a)[0]), "r"((a)[1]), "r"((a)[2]), "r"((a)[3]), "r"(b0), "r"(b1))
__device__ __forceinline__ void ldmx4(uint32_t* r, uint32_t addr) {
    asm volatile("ldmatrix.sync.aligned.m8n8.x4.shared.b16 {%0,%1,%2,%3}, [%4];"
        : "=r"(r[0]), "=r"(r[1]), "=r"(r[2]), "=r"(r[3]) : "r"(addr));
}
__device__ __forceinline__ void ldmx4t(uint32_t* r, uint32_t addr) {
    asm volatile("ldmatrix.sync.aligned.m8n8.x4.trans.shared.b16 {%0,%1,%2,%3}, [%4];"
        : "=r"(r[0]), "=r"(r[1]), "=r"(r[2]), "=r"(r[3]) : "r"(addr));
}
__device__ __forceinline__ void split_w(float v, __nv_bfloat16* h, __nv_bfloat16* l, long i) {
    __nv_bfloat16 hv = __float2bfloat16_rn(v);
    h[i] = hv;
    l[i] = __float2bfloat16_rn(v - __bfloat162float(hv));
}
__device__ __forceinline__ float to_tf32(float v) {
    uint32_t u;
    asm("cvt.rna.tf32.f32 %0, %1;" : "=r"(u) : "f"(v));
    return __uint_as_float(u);
}
__device__ __forceinline__ uint32_t lds_u32(uint32_t addr) {
    uint32_t v;
    asm volatile("ld.shared.b32 %0, [%1];" : "=r"(v) : "r"(addr));
    return v;
}
__device__ __forceinline__ uint32_t pack_bf2(float a, float b) {
    __nv_bfloat162 t;
    t.x = __float2bfloat16_rn(a);
    t.y = __float2bfloat16_rn(b);
    return *(uint32_t*)&t;
}

// -------------------- TF32 mma.sync batched GEMM (3-stage) ------------------
struct GP {
    const float* A; const float* B;
    float* C; float* Ct;
    int M, N, K, lda, ldb;
    long sA, sB, sC;
    int gx, gy;
};

template<int AT, int BT, bool ACC, bool SPLIT>
__device__ __forceinline__ void gemm_body(const GP p, int bz)
{
    if ((int)blockIdx.x >= p.gx || (int)blockIdx.y >= p.gy) return;
    constexpr int SA = AT ? 17408 : 18432;
    constexpr int SB = BT ? 17408 : 18432;
    constexpr int STAGE = SA + SB;
    extern __shared__ char smem[];
    uint32_t sb = smem_u32(smem);
    int tid = threadIdx.x, lane = tid & 31, wid = tid >> 5;
    int wm = wid >> 2, wn = wid & 3;
    const float* a = p.A + (long)bz * p.sA;
    const float* b = p.B + (long)bz * p.sB;
    int m0 = blockIdx.y << 7, n0 = blockIdx.x << 7;
    int lda = p.lda, ldb = p.ldb;

    float acc[4][4][4];
    #pragma unroll
    for (int i = 0; i < 4; ++i)
        #pragma unroll
        for (int j = 0; j < 4; ++j)
            #pragma unroll
            for (int q = 0; q < 4; ++q) acc[i][j][q] = 0.f;

    int Lm = lane >> 3, Lr = lane & 7;
    uint32_t aoff = (uint32_t)(((Lm & 1) * 8 + Lr) * 144 + (Lm >> 1) * 16);
    uint32_t boff = (uint32_t)(((Lm >> 1) * 8 + Lr) * 144 + (Lm & 1) * 16);

    auto issue = [&](int buf, int k0) {
        uint32_t st = sb + buf * STAGE;
        #pragma unroll
        for (int j = 0; j < 4; ++j) {
            int u = tid + j * 256;
            uint32_t so; long g;
            if (AT == 0) { int r = u >> 3, s = u & 7;  so = r * 144 + s * 16;
                           g = (long)(m0 + r) * lda + k0 + s * 4; }
            else         { int r = u >> 5, s = u & 31; so = r * 544 + s * 16;
                           g = (long)(k0 + r) * lda + m0 + s * 4; }
            cpa16(st + so, a + g);
            if (BT == 0) { int r = u >> 3, s = u & 7;  so = r * 144 + s * 16;
                           g = (long)(n0 + r) * ldb + k0 + s * 4; }
            else         { int r = u >> 5, s = u & 31; so = r * 544 + s * 16;
                           g = (long)(k0 + r) * ldb + n0 + s * 4; }
            cpa16(st + SA + so, b + g);
        }
        CP_COMMIT();
    };

    const int n = p.K >> 5;
    issue(0, 0);
    if (n > 1) issue(1, 32);
    int buf = 0;
    for (int i = 0; i < n; ++i) {
        if (i + 1 < n) asm volatile("cp.async.wait_group 1;" ::: "memory");
        else           asm volatile("cp.async.wait_group 0;" ::: "memory");
        __syncthreads();
        uint32_t st = sb + buf * STAGE;
        uint32_t stB = st + SA;
        #pragma unroll
        for (int kk = 0; kk < 32; kk += 8) {
            uint32_t af[4][4];
            #pragma unroll
            for (int mt = 0; mt < 4; ++mt) {
                if (AT == 0) {
                    ldmx4(af[mt], st + (wm * 64 + mt * 16) * 144 + kk * 4 + aoff);
                } else {
                    uint32_t ra = st + (kk + (lane & 3)) * 544
                                + (wm * 64 + mt * 16 + (lane >> 2)) * 4;
                    af[mt][0] = lds_u32(ra);
                    af[mt][1] = lds_u32(ra + 32);
                    af[mt][2] = lds_u32(ra + 4 * 544);
                    af[mt][3] = lds_u32(ra + 4 * 544 + 32);
                }
            }
            uint32_t bf_[4][2];
            if (BT == 0) {
                #pragma unroll
                for (int pp = 0; pp < 2; ++pp) {
                    uint32_t r4[4];
                    ldmx4(r4, stB + (wn * 32 + pp * 16) * 144 + kk * 4 + boff);
                    bf_[pp * 2 + 0][0] = r4[0]; bf_[pp * 2 + 0][1] = r4[1];
                    bf_[pp * 2 + 1][0] = r4[2]; bf_[pp * 2 + 1][1] = r4[3];
                }
            } else {
                #pragma unroll
                for (int nt = 0; nt < 4; ++nt) {
                    uint32_t rb = stB + (kk + (lane & 3)) * 544
                                + (wn * 32 + nt * 8 + (lane >> 2)) * 4;
                    bf_[nt][0] = lds_u32(rb);
                    bf_[nt][1] = lds_u32(rb + 4 * 544);
                }
            }
            #pragma unroll
            for (int nt = 0; nt < 4; ++nt)
                #pragma unroll
                for (int mt = 0; mt < 4; ++mt)
                    MMATF(acc[mt][nt], af[mt], bf_[nt][0], bf_[nt][1]);
        }
        if (i + 2 < n) issue((i + 2) % 3, (i + 2) * 32);
        buf = (buf == 2) ? 0 : buf + 1;
    }
    float* c = p.C + (long)bz * p.sC;
    float* ct = SPLIT ? p.Ct + (long)bz * p.sC : nullptr;
    int N = p.N;
    #pragma unroll
    for (int mt = 0; mt < 4; ++mt) {
        #pragma unroll
        for (int nt = 0; nt < 4; ++nt) {
            long r0 = m0 + wm * 64 + mt * 16 + (lane >> 2);
            int  cc = n0 + wn * 32 + nt * 8 + (lane & 3) * 2;
            long o0 = r0 * (long)N + cc;
            long o1 = (r0 + 8) * (long)N + cc;
            float v00 = acc[mt][nt][0], v01 = acc[mt][nt][1];
            float v10 = acc[mt][nt][2], v11 = acc[mt][nt][3];
            if (ACC) {
                float2 t0 = *(float2*)(c + o0), t1 = *(float2*)(c + o1);
                v00 += t0.x; v01 += t0.y; v10 += t1.x; v11 += t1.y;
            }
            *(float2*)(c + o0) = make_float2(v00, v01);
            *(float2*)(c + o1) = make_float2(v10, v11);
            if (SPLIT) {
                *(float2*)(ct + o0) = make_float2(to_tf32(v00), to_tf32(v01));
                *(float2*)(ct + o1) = make_float2(to_tf32(v10), to_tf32(v11));
            }
        }
    }
}

__global__ void __launch_bounds__(256, 2) tf_nt(GP p) {
    gemm_body<0, 0, false, false>(p, blockIdx.z);
}
__global__ void __launch_bounds__(256, 2) tf_pack_fwd(GP p1, GP p2, int z1) {
    if ((int)blockIdx.z < z1) gemm_body<0, 0, false, false>(p1, blockIdx.z);
    else                      gemm_body<0, 1, false, false>(p2, blockIdx.z - z1);
}
__global__ void __launch_bounds__(256, 2) tf_pack_upd(GP p1, GP p2, int z1) {
    if ((int)blockIdx.z < z1) gemm_body<1, 1, true, true>(p1, blockIdx.z);
    else                      gemm_body<1, 1, true, true>(p2, blockIdx.z - z1);
}
__global__ void __launch_bounds__(256, 2) tf_pack3(GP p1, GP p2, GP p3, int z1, int z2) {
    int z = blockIdx.z;
    if (z < z1)            gemm_body<0, 0, false, false>(p1, z);
    else if (z < z1 + z2)  gemm_body<0, 0, false, false>(p2, z - z1);
    else                   gemm_body<0, 1, false, false>(p3, z - z1 - z2);
}

// ------------------------ conversion kernel ---------------------------------
__global__ void cvt_tf(const float* __restrict__ x, float* __restrict__ o, long n)
{
    long i = ((long)blockIdx.x * 256 + threadIdx.x) * 4;
    if (i >= n) return;
    float4 v = *(const float4*)(x + i);
    float4 w;
    w.x = to_tf32(v.x); w.y = to_tf32(v.y); w.z = to_tf32(v.z); w.w = to_tf32(v.w);
    *(float4*)(o + i) = w;
}

// ---------------- small SGEMM for the N=12 lr GEMM --------------------------
__global__ void lr_gemm(const float* __restrict__ A, const float* __restrict__ B,
                        float* __restrict__ C)
{
    __shared__ float bs[12][128];
    int row = blockIdx.x * 2 + (threadIdx.x >> 7);
    int tid = threadIdx.x & 127;
    float acc[12];
    #pragma unroll
    for (int c = 0; c < 12; ++c) acc[c] = 0.f;
    for (int k0 = 0; k0 < 2048; k0 += 128) {
        if (threadIdx.x < 128)
            #pragma unroll
            for (int c = 0; c < 12; ++c) bs[c][tid] = B[c * 2048 + k0 + tid];
        __syncthreads();
        float a = A[(long)row * 2048 + k0 + tid];
        #pragma unroll
        for (int c = 0; c < 12; ++c) acc[c] += a * bs[c][tid];
        __syncthreads();
    }
    __shared__ float red[2][12][4];
    #pragma unroll
    for (int c = 0; c < 12; ++c) {
        float v = acc[c];
        #pragma unroll
        for (int o = 16; o > 0; o >>= 1) v += __shfl_down_sync(0xffffffffu, v, o);
        if ((tid & 31) == 0) red[threadIdx.x >> 7][c][tid >> 5] = v;
    }
    __syncthreads();
    if (tid < 12) {
        int w = threadIdx.x >> 7;
        C[(long)row * 12 + tid] = red[w][tid][0] + red[w][tid][1] + red[w][tid][2] + red[w][tid][3];
    }
}

// ------------------------- block reduce (256 thr) ---------------------------
__device__ __forceinline__ float blockReduceSum(float v, float* sred)
{
    int lane = threadIdx.x & 31;
    #pragma unroll
    for (int o = 16; o > 0; o >>= 1) v += __shfl_down_sync(0xffffffffu, v, o);
    if (lane == 0) sred[threadIdx.x >> 5] = v;
    __syncthreads();
    if (threadIdx.x < 8) {
        float r = sred[threadIdx.x];
        #pragma unroll
        for (int o = 4; o > 0; o >>= 1) r += __shfl_down_sync(0xffu, r, o);
        if (threadIdx.x == 0) sred[0] = r;
    }
    __syncthreads();
    float out = sred[0];
    __syncthreads();
    return out;
}

// --------- prep: rmsnorm+rope + silu/L2 + lr ---------------------------------
__global__ void prep_kernel(const float* __restrict__ qkv, const float* __restrict__ lrpre,
                            const float* __restrict__ qnw, const float* __restrict__ knw,
                            const float* __restrict__ qksc, const float* __restrict__ qkof,
                            const float* __restrict__ lrb, float base_lr_inv,
                            __nv_bfloat16* __restrict__ aqh, __nv_bfloat16* __restrict__ aql,
                            __nv_bfloat16* __restrict__ akh, __nv_bfloat16* __restrict__ akl,
                            __nv_bfloat16* __restrict__ avh, __nv_bfloat16* __restrict__ avl,
                            float* __restrict__ fqt, float* __restrict__ fkt,
                            float* __restrict__ fvt, float* __restrict__ lrout)
{
    __shared__ float s_q[2048];
    __shared__ float s_k[2048];
    __shared__ float sred[8];
    int row = blockIdx.x;
    int b = row >> 11, t = row & 2047;
    int tid = threadIdx.x;
    const float* qr = qkv + (long)row * 6144;
    const float* kr = qr + 2048;
    const float* vr = qr + 4096;
    const float qscale = 0.088388347648318447f * 1.4426950408889634f;

    float qv[8], kv[8], fqv[8], fkv[8], fvv[8];
    float sq = 0.f, sk = 0.f;
    float p2q[4] = {0, 0, 0, 0}, p2k[4] = {0, 0, 0, 0};
    #pragma unroll
    for (int j = 0; j < 8; ++j) {
        int i = j * 256 + tid;
        float q = qr[i], k = kr[i], v = vr[i];
        qv[j] = q; kv[j] = k;
        sq += q * q; sk += k * k;
        float fqe = (q / (1.f + expf(-q))) * qksc[i * 2 + 0] + qkof[i * 2 + 0];
        float fke = (k / (1.f + expf(-k))) * qksc[i * 2 + 1] + qkof[i * 2 + 1];
        fqv[j] = fqe; fkv[j] = fke; fvv[j] = v / (1.f + expf(-v));
        p2q[j >> 1] += fqe * fqe;
        p2k[j >> 1] += fke * fke;
        split_w(v, avh, avl, (long)row * DIMD + i);
    }
    float SQ = blockReduceSum(sq, sred);
    float SK = blockReduceSum(sk, sred);
    float G2Q[4], G2K[4];
    #pragma unroll
    for (int g = 0; g < 4; ++g) G2Q[g] = blockReduceSum(p2q[g], sred);
    #pragma unroll
    for (int g = 0; g < 4; ++g) G2K[g] = blockReduceSum(p2k[g], sred);
    float rq = rsqrtf(SQ * (1.f / 2048.f) + 1e-6f);
    float rk = rsqrtf(SK * (1.f / 2048.f) + 1e-6f);
    #pragma unroll
    for (int j = 0; j < 8; ++j) {
        int i = j * 256 + tid;
        s_q[i] = qv[j] * rq * qnw[i];
        s_k[i] = kv[j] * rk * knw[i];
        int g = j >> 1;
        long fb = (((long)(b * 4 + g)) * SEQ + t) * FDM + (i & 511);
        fqt[fb] = to_tf32(fqv[j] / (sqrtf(G2Q[g]) + 1e-12f));
        fkt[fb] = to_tf32(fkv[j] / (sqrtf(G2K[g]) + 1e-12f));
        fvt[fb] = to_tf32(fvv[j]);
    }
    __syncthreads();
    #pragma unroll
    for (int j = 0; j < 8; ++j) {
        int i = j * 256 + tid;
        int pos = i & 127;
        int fi = pos & 63;
        float invf = expf(-(float)fi * (logf(500000.f) / 64.f));
        float sn, cs;
        sincosf((float)t * invf, &sn, &cs);
        float oq, ok_;
        if (pos < 64) {
            oq  = s_q[i] * cs - s_q[i + 64] * sn;
            ok_ = s_k[i] * cs - s_k[i + 64] * sn;
        } else {
            oq  = s_q[i] * cs + s_q[i - 64] * sn;
            ok_ = s_k[i] * cs + s_k[i - 64] * sn;
        }
        split_w(oq * qscale, aqh, aql, (long)row * DIMD + i);
        split_w(ok_, akh, akl, (long)row * DIMD + i);
    }
    if (tid < 12) {
        float x = lrpre[(long)row * 12 + tid] + lrb[tid] + base_lr_inv;
        lrout[(long)row * 12 + tid] = (x > 20.f) ? x : log1pf(expf(x));
    }
}

// ------------- HMMA flash attention, register softmax (4 warps) --------------
#define ATS 272
#define O_QH 0
#define O_QL 17408
#define O_KH 34816
#define O_KL 52224
#define O_VH 69632
#define O_VL 87040
#define ATTN_SMEM 104448

__global__ void __launch_bounds__(128, 2)
attn_mma(const __nv_bfloat16* __restrict__ Qh, const __nv_bfloat16* __restrict__ Ql,
         const __nv_bfloat16* __restrict__ Kh, const __nv_bfloat16* __restrict__ Kl,
         const __nv_bfloat16* __restrict__ Vh, const __nv_bfloat16* __restrict__ Vl,
         float* __restrict__ O)
{
    extern __shared__ char smc[];
    uint32_t sb = smem_u32(smc);
    int tid = threadIdx.x, lane = tid & 31, wid = tid >> 5;
    int q0 = blockIdx.x << 6, h = blockIdx.y, b = blockIdx.z;
    int wr = wid * 16;
    uint32_t a_row = (lane & 7) + ((lane >> 3) & 1) * 8;
    uint32_t a_kb  = ((lane >> 4) & 1) * 16;
    uint32_t b_row = (lane & 7) + ((lane >> 4) & 1) * 8;
    uint32_t b_kb  = ((lane >> 3) & 1) * 16;
    uint32_t b_kr  = (lane & 7) + ((lane >> 3) & 1) * 8;
    uint32_t b_no  = ((lane >> 4) & 1) * 8;

    // resident Q hi/lo
    #pragma unroll
    for (int j = 0; j < 8; ++j) {
        int u = tid + j * 128;
        int r = u >> 4, s = u & 15;
        long g = ((long)(b * SEQ + q0 + r)) * DIMD + h * 128 + s * 8;
        cpa16(sb + O_QH + r * ATS + s * 16, Qh + g);
        cpa16(sb + O_QL + r * ATS + s * 16, Ql + g);
    }
    CP_COMMIT();

    float oacc[16][4];
    #pragma unroll
    for (int i = 0; i < 16; ++i)
        #pragma unroll
        for (int q = 0; q < 4; ++q) oacc[i][q] = 0.f;
    float m_lo = -INFINITY, m_hi = -INFINITY, l_lo = 0.f, l_hi = 0.f;

    int r_lo = q0 + wr + (lane >> 2);
    int r_hi = r_lo + 8;

    int kt_hi2 = q0 >> 6;
    int kt_lo2 = (q0 >= 1024) ? ((q0 - 1023) >> 6) : 0;
    for (int kt = kt_lo2; kt <= kt_hi2; ++kt) {
        int j0 = kt << 6;
        __syncthreads();
        #pragma unroll
        for (int j = 0; j < 8; ++j) {
            int u = tid + j * 128;
            int r = u >> 4, s = u & 15;
            long g = ((long)(b * SEQ + j0 + r)) * DIMD + h * 128 + s * 8;
            uint32_t so = r * ATS + s * 16;
            cpa16(sb + O_KH + so, Kh + g);
            cpa16(sb + O_KL + so, Kl + g);
            cpa16(sb + O_VH + so, Vh + g);
            cpa16(sb + O_VL + so, Vl + g);
        }
        CP_COMMIT();
        asm volatile("cp.async.wait_group 0;" ::: "memory");
        __syncthreads();

        // ---- S = Q K^T : warp computes rows [wr, wr+16) x cols [0,64) ----
        float sacc[8][4];
        #pragma unroll
        for (int i = 0; i < 8; ++i)
            #pragma unroll
            for (int q = 0; q < 4; ++q) sacc[i][q] = 0.f;
        #pragma unroll
        for (int kk = 0; kk < 8; ++kk) {
            uint32_t ah4[4], al4[4];
            uint32_t ra = sb + O_QH + (wr + a_row) * ATS + kk * 32 + a_kb;
            ldmx4(ah4, ra);
            ldmx4(al4, ra + (O_QL - O_QH));
            uint32_t bh4[4][4], bl4[4][4];
            #pragma unroll
            for (int p = 0; p < 4; ++p) {
                uint32_t rb = sb + O_KH + (p * 16 + b_row) * ATS + kk * 32 + b_kb;
                ldmx4(bh4[p], rb);
                ldmx4(bl4[p], rb + (O_KL - O_KH));
            }
            #pragma unroll
            for (int nt = 0; nt < 8; ++nt) {
                uint32_t b0h = bh4[nt >> 1][(nt & 1) * 2 + 0];
                uint32_t b1h = bh4[nt >> 1][(nt & 1) * 2 + 1];
                uint32_t b0l = bl4[nt >> 1][(nt & 1) * 2 + 0];
                uint32_t b1l = bl4[nt >> 1][(nt & 1) * 2 + 1];
                MMA16816(sacc[nt], ah4, b0h, b1h);
                MMA16816(sacc[nt], ah4, b0l, b1l);
                MMA16816(sacc[nt], al4, b0h, b1h);
            }
        }
        // ---- mask + register softmax ----
        float tmax_lo = -INFINITY, tmax_hi = -INFINITY;
        #pragma unroll
        for (int nt = 0; nt < 8; ++nt) {
            #pragma unroll
            for (int e = 0; e < 2; ++e) {
                int col = j0 + nt * 8 + (lane & 3) * 2 + e;
                bool ok0 = (col <= r_lo) && (r_lo - col < 1024);
                bool ok1 = (col <= r_hi) && (r_hi - col < 1024);
                sacc[nt][e]     = ok0 ? sacc[nt][e]     : -INFINITY;
                sacc[nt][2 + e] = ok1 ? sacc[nt][2 + e] : -INFINITY;
                tmax_lo = fmaxf(tmax_lo, sacc[nt][e]);
                tmax_hi = fmaxf(tmax_hi, sacc[nt][2 + e]);
            }
        }
        tmax_lo = fmaxf(tmax_lo, __shfl_xor_sync(0xffffffffu, tmax_lo, 1));
        tmax_lo = fmaxf(tmax_lo, __shfl_xor_sync(0xffffffffu, tmax_lo, 2));
        tmax_hi = fmaxf(tmax_hi, __shfl_xor_sync(0xffffffffu, tmax_hi, 1));
        tmax_hi = fmaxf(tmax_hi, __shfl_xor_sync(0xffffffffu, tmax_hi, 2));
        float mt_lo = fmaxf(m_lo, tmax_lo);
        float mt_hi = fmaxf(m_hi, tmax_hi);
        float mte_lo = (mt_lo > -INFINITY) ? mt_lo : 0.f;
        float mte_hi = (mt_hi > -INFINITY) ? mt_hi : 0.f;
        float corr_lo = exp2f(m_lo - mte_lo);
        float corr_hi = exp2f(m_hi - mte_hi);

        uint32_t ph[4][4], pl[4][4];
        float ls_lo = 0.f, ls_hi = 0.f;
        #pragma unroll
        for (int k2 = 0; k2 < 4; ++k2) {
            #pragma unroll
            for (int half = 0; half < 2; ++half) {
                int nt = k2 * 2 + half;
                float p00 = exp2f(sacc[nt][0] - mte_lo);
                float p01 = exp2f(sacc[nt][1] - mte_lo);
                float p10 = exp2f(sacc[nt][2] - mte_hi);
                float p11 = exp2f(sacc[nt][3] - mte_hi);
                ls_lo += p00 + p01;
                ls_hi += p10 + p11;
                uint32_t h0 = pack_bf2(p00, p01);
                uint32_t h1 = pack_bf2(p10, p11);
                __nv_bfloat162 hb0 = *(__nv_bfloat162*)&h0;
                __nv_bfloat162 hb1 = *(__nv_bfloat162*)&h1;
                uint32_t l0 = pack_bf2(p00 - __bfloat162float(hb0.x),
                                       p01 - __bfloat162float(hb0.y));
                uint32_t l1 = pack_bf2(p10 - __bfloat162float(hb1.x),
                                       p11 - __bfloat162float(hb1.y));
                ph[k2][half * 2 + 0] = h0; ph[k2][half * 2 + 1] = h1;
                pl[k2][half * 2 + 0] = l0; pl[k2][half * 2 + 1] = l1;
            }
            // reorder to a0..a3: a0=(r,kc),a1=(r+8,kc),a2=(r,kc+8),a3=(r+8,kc+8)
            // half0 wrote slots {0,1}=(r,kc),(r+8,kc); half1 wrote {2,3}=(r,kc+8),(r+8,kc+8)
            // -> already matches a0..a3 layout. (slots: [0]=a0,[1]=a1,[2]=a2,[3]=a3)
        }
        ls_lo += __shfl_xor_sync(0xffffffffu, ls_lo, 1);
        ls_lo += __shfl_xor_sync(0xffffffffu, ls_lo, 2);
        ls_hi += __shfl_xor_sync(0xffffffffu, ls_hi, 1);
        ls_hi += __shfl_xor_sync(0xffffffffu, ls_hi, 2);
        l_lo = l_lo * corr_lo + ls_lo;
        l_hi = l_hi * corr_hi + ls_hi;
        m_lo = mt_lo; m_hi = mt_hi;

        #pragma unroll
        for (int nt = 0; nt < 16; ++nt) {
            oacc[nt][0] *= corr_lo; oacc[nt][1] *= corr_lo;
            oacc[nt][2] *= corr_hi; oacc[nt][3] *= corr_hi;
        }
        // ---- O += P V : warp rows [wr, wr+16) x d-cols [0,128) ----
        #pragma unroll
        for (int k2 = 0; k2 < 4; ++k2) {
            #pragma unroll
            for (int p2 = 0; p2 < 8; ++p2) {
                uint32_t vh4[4], vl4[4];
                uint32_t rb = sb + O_VH + (k2 * 16 + b_kr) * ATS + (p2 * 16 + b_no) * 2;
                ldmx4t(vh4, rb);
                ldmx4t(vl4, rb + (O_VL - O_VH));
                #pragma unroll
                for (int sub = 0; sub < 2; ++sub) {
                    int nt = p2 * 2 + sub;
                    uint32_t b0h = vh4[sub * 2], b1h = vh4[sub * 2 + 1];
                    uint32_t b0l = vl4[sub * 2], b1l = vl4[sub * 2 + 1];
                    MMA16816(oacc[nt], ph[k2], b0h, b1h);
                    MMA16816(oacc[nt], ph[k2], b0l, b1l);
                    MMA16816(oacc[nt], pl[k2], b0h, b1h);
                }
            }
        }
    }
    float rl0 = 1.f / l_lo, rl1 = 1.f / l_hi;
    #pragma unroll
    for (int nt = 0; nt < 16; ++nt) {
        int col = nt * 8 + (lane & 3) * 2;
        long o0 = ((long)(b * SEQ + r_lo)) * 2048 + h * 128 + col;
        long o1 = ((long)(b * SEQ + r_hi)) * 2048 + h * 128 + col;
        *(float2*)(O + o0) = make_float2(oacc[nt][0] * rl0, oacc[nt][1] * rl0);
        *(float2*)(O + o1) = make_float2(oacc[nt][2] * rl1, oacc[nt][3] * rl1);
    }
}

// --------------------------- TTT helper kernels -----------------------------
__global__ void copyw(const float* __restrict__ w0, const float* __restrict__ w1,
                      const float* __restrict__ w2,
                      float* __restrict__ o02, float* __restrict__ o02t,
                      float* __restrict__ o1, float* __restrict__ o1t)
{
    long idx = (long)blockIdx.x * 256 + threadIdx.x;
    int col = idx & 511;
    int row = (idx >> 9) & 1023;
    int h = (idx >> 19) & 3;
    long src = (long)h * 262144 + (long)(row & 511) * 512 + col;
    float v = (row < 512) ? w0[src] : w2[src];
    o02[idx] = v;
    o02t[idx] = to_tf32(v);
    if (idx < (long)2 * 1024 * 1024) {
        float v1 = w1[idx & ((long)4 * 262144 - 1)];
        o1[idx] = v1;
        o1t[idx] = to_tf32(v1);
    }
}

__global__ void elem2(const float* __restrict__ fvt, const float* __restrict__ lr,
                      const float* __restrict__ gh, const float* __restrict__ dhin,
                      float* __restrict__ dgpt, float* __restrict__ vlt,
                      float* __restrict__ htt, int ck0)
{
    long idx = (long)blockIdx.x * 256 + threadIdx.x;
    int col = idx & 511;
    long tt = idx >> 9;
    int c = tt & 1023, bh = tt >> 10;
    int b = bh >> 2, h = bh & 3;
    long row = (long)b * SEQ + ck0 + c;
    float l0 = lr[row * 12 + h], l1 = lr[row * 12 + 4 + h], l2 = lr[row * 12 + 8 + h];
    long gi = (long)bh * 1048576 + (long)c * 1024 + col;
    float g = gh[gi], hp = gh[gi + 512], d = dhin[idx];
    float sig = 1.f / (1.f + expf(-g));
    float sg = g * sig;
    htt[idx] = to_tf32(sg * hp);
    float v = fvt[((long)bh * SEQ + ck0 + c) * FDM + col];
    dgpt[gi]       = to_tf32(d * hp * (sig * (1.f + g * (1.f - sig))) * l0);
    dgpt[gi + 512] = to_tf32(d * sg * l2);
    vlt[idx]       = to_tf32(v * l1);
}

__global__ void elem3(const float* __restrict__ gh, float* __restrict__ hnt)
{
    long idx = (long)blockIdx.x * 256 + threadIdx.x;
    int col = idx & 511;
    long tt = idx >> 9;
    int c = tt & 1023, bh = tt >> 10;
    long gi = (long)bh * 1048576 + (long)c * 1024 + col;
    float g = gh[gi];
    hnt[idx] = to_tf32((g / (1.f + expf(-g))) * gh[gi + 512]);
}

// -------------------- ttt rmsnorm + add attention result --------------------
__global__ void post_kernel(const float* __restrict__ ttt, const float* __restrict__ tw,
                            const float* __restrict__ sum, float* __restrict__ smt)
{
    __shared__ float sr[4];
    int fh = blockIdx.x, row = blockIdx.y;
    int b = row >> 11, t = row & 2047;
    int bh = b * 4 + fh;
    const float* src = ttt + ((long)bh * SEQ + t) * FDM;
    int tid = threadIdx.x;
    float v[4], ss = 0.f;
    #pragma unroll
    for (int j = 0; j < 4; ++j) { v[j] = src[tid + 128 * j]; ss += v[j] * v[j]; }
    #pragma unroll
    for (int o = 16; o > 0; o >>= 1) ss += __shfl_down_sync(0xffffffffu, ss, o);
    if ((tid & 31) == 0) sr[tid >> 5] = ss;
    __syncthreads();
    float tot = sr[0] + sr[1] + sr[2] + sr[3];
    float r = rsqrtf(tot * (1.f / 512.f) + 1e-6f);
    #pragma unroll
    for (int j = 0; j < 4; ++j) {
        int i = tid + 128 * j;
        long o = (long)row * 2048 + fh * 512 + i;
        smt[o] = to_tf32(sum[o] + v[j] * r * tw[i]);
    }
}

// --------------------------------- launch -----------------------------------
#define GSYM(p, s) cudaGetSymbolAddress((void**)&(p), s)

extern "C" void kernel_launch(void* const* d_in, const int* in_sizes, int n_in,
                              void* d_out, int out_size)
{
    const float* hidden = (const float*)d_in[0];
    const float* Wqkv   = (const float*)d_in[1];
    const float* Wo     = (const float*)d_in[2];
    const float* qnw    = (const float*)d_in[3];
    const float* knw    = (const float*)d_in[4];
    const float* w0     = (const float*)d_in[5];
    const float* w1     = (const float*)d_in[6];
    const float* w2     = (const float*)d_in[7];
    const float* lrw    = (const float*)d_in[8];
    const float* lrb    = (const float*)d_in[9];
    const float* qksc   = (const float*)d_in[10];
    const float* qkof   = (const float*)d_in[11];
    const float* tttw   = (const float*)d_in[12];
    float* out = (float*)d_out;

    float *qkv, *lrpre, *lr, *pw02, *pw1, *gh, *dh, *ttt, *sum;
    GSYM(qkv, g_qkv);   GSYM(lrpre, g_lrpre); GSYM(lr, g_lr);
    GSYM(pw02, g_w02);  GSYM(pw1, g_w1);
    GSYM(gh, g_gh);     GSYM(dh, g_dh);
    GSYM(ttt, g_ttt);   GSYM(sum, g_sum);

    float *hxt,*wqt,*wot,*fqt,*fkt,*fvt,*w02t,*w1t,*dgpt,*vlt,*htt,*hnt,*smt;
    GSYM(hxt, g_hx_t); GSYM(wqt, g_wq_t); GSYM(wot, g_wo_t);
    GSYM(fqt, g_fq_t); GSYM(fkt, g_fk_t); GSYM(fvt, g_fv_t);
    GSYM(w02t, g_w02_t); GSYM(w1t, g_w1_t);
    GSYM(dgpt, g_dgp_t); GSYM(vlt, g_vl_t); GSYM(htt, g_ht_t);
    GSYM(hnt, g_hn_t); GSYM(smt, g_sm_t);

    __nv_bfloat16 *aqh,*aql,*akh,*akl,*avh,*avl;
    GSYM(aqh, g_aq_h); GSYM(aql, g_aq_l); GSYM(akh, g_ak_h); GSYM(akl, g_ak_l);
    GSYM(avh, g_av_h); GSYM(avl, g_av_l);

    cudaFuncSetAttribute(tf_nt, cudaFuncAttributeMaxDynamicSharedMemorySize, 110592);
    cudaFuncSetAttribute(tf_pack_fwd, cudaFuncAttributeMaxDynamicSharedMemorySize, 110592);
    cudaFuncSetAttribute(tf_pack_upd, cudaFuncAttributeMaxDynamicSharedMemorySize, 104448);
    cudaFuncSetAttribute(tf_pack3, cudaFuncAttributeMaxDynamicSharedMemorySize, 110592);
    cudaFuncSetAttribute(attn_mma, cudaFuncAttributeMaxDynamicSharedMemorySize, ATTN_SMEM);

    cvt_tf<<<8192, 256>>>(hidden, hxt, (long)4096 * 2048);
    cvt_tf<<<12288, 256>>>(Wqkv, wqt, (long)6144 * 2048);
    cvt_tf<<<4096, 256>>>(Wo, wot, (long)2048 * 2048);

    {
        GP p{hxt, wqt, qkv, nullptr, 4096, 6144, 2048, 2048, 2048, 0, 0, 0, 48, 32};
        tf_nt<<<dim3(48, 32, 1), 256, 110592>>>(p);
    }
    lr_gemm<<<2048, 256>>>(hidden, lrw, lrpre);

    float base = (float)(0.001 + log(-expm1(-0.001)));
    prep_kernel<<<4096, 256>>>(qkv, lrpre, qnw, knw, qksc, qkof, lrb, base,
                               aqh, aql, akh, akl, avh, avl,
                               fqt, fkt, fvt, lr);
    attn_mma<<<dim3(32, 16, 2), 128, ATTN_SMEM>>>(aqh, aql, akh, akl, avh, avl, sum);

    copyw<<<16384, 256>>>(w0, w1, w2, pw02, w02t, pw1, w1t);

    long sSeq = (long)SEQ * FDM;
    long sChk = (long)1024 * FDM;
    long sW   = (long)FDM * FDM;
    long sW02 = (long)1024 * FDM;
    long sGH  = (long)1024 * 1024;

    // ---- chunk 0 ----
    {
        GP p1{fkt, w02t, gh, nullptr, 1024, 1024, 512, 512, 512, sSeq, sW02, sGH, 8, 8};
        GP p2{fvt, w1t, dh, nullptr, 1024, 512, 512, 512, 512, sSeq, sW, sChk, 4, 8};
        tf_pack_fwd<<<dim3(8, 8, 16), 256, 110592>>>(p1, p2, 8);
    }
    elem2<<<16384, 256>>>(fvt, lr, gh, dh, dgpt, vlt, htt, 0);
    {
        GP p1{dgpt, fkt, pw02, w02t, 1024, 512, 1024, 1024, 512, sGH, sSeq, sW02, 4, 8};
        GP p2{vlt, htt, pw1, w1t, 512, 512, 1024, 512, 512, sChk, sChk, sW, 4, 4};
        tf_pack_upd<<<dim3(4, 8, 16), 256, 104448>>>(p1, p2, 8);
    }
    {
        GP p{fqt, w02t, gh, nullptr, 1024, 1024, 512, 512, 512, sSeq, sW02, sGH, 8, 8};
        tf_nt<<<dim3(8, 8, 8), 256, 110592>>>(p);
    }
    elem3<<<16384, 256>>>(gh, hnt);

    long co1 = (long)1024 * FDM;
    // ---- final(ck0) || fwd(ck1) packed ----
    {
        GP p1{hnt, w1t, ttt, nullptr, 1024, 512, 512, 512, 512, sChk, sW, sSeq, 4, 8};
        GP p2{fkt + co1, w02t, gh, nullptr, 1024, 1024, 512, 512, 512, sSeq, sW02, sGH, 8, 8};
        GP p3{fvt + co1, w1t, dh, nullptr, 1024, 512, 512, 512, 512, sSeq, sW, sChk, 4, 8};
        tf_pack3<<<dim3(8, 8, 24), 256, 110592>>>(p1, p2, p3, 8, 8);
    }
    // ---- chunk 1 ----
    elem2<<<16384, 256>>>(fvt, lr, gh, dh, dgpt, vlt, htt, 1024);
    {
        GP p1{dgpt, fkt + co1, pw02, w02t, 1024, 512, 1024, 1024, 512, sGH, sSeq, sW02, 4, 8};
        GP p2{vlt, htt, pw1, w1t, 512, 512, 1024, 512, 512, sChk, sChk, sW, 4, 4};
        tf_pack_upd<<<dim3(4, 8, 16), 256, 104448>>>(p1, p2, 8);
    }
    {
        GP p{fqt + co1, w02t, gh, nullptr, 1024, 1024, 512, 512, 512, sSeq, sW02, sGH, 8, 8};
        tf_nt<<<dim3(8, 8, 8), 256, 110592>>>(p);
    }
    elem3<<<16384, 256>>>(gh, hnt);
    {
        GP p{hnt, w1t, ttt + co1, nullptr, 1024, 512, 512, 512, 512, sChk, sW, sSeq, 4, 8};
        tf_nt<<<dim3(4, 8, 8), 256, 110592>>>(p);
    }

    post_kernel<<<dim3(4, 4096), 128>>>(ttt, tttw, sum, smt);
    {
        GP p{smt, wot, out, nullptr, 4096, 2048, 2048, 2048, 2048, 0, 0, 0, 16, 32};
        tf_nt<<<dim3(16, 32, 1), 256, 110592>>>(p);
    }
}